// round 2
// baseline (speedup 1.0000x reference)
#include <cuda_runtime.h>
#include <math.h>

// Problem constants
#define BB 4
#define TT 4096
#define CC 2048
#define DD 128
#define MTOT (BB*TT)   // 16384

// Scratch for q, k, v projections: [B*T, 128] fp32 each (8 MB each)
__device__ float g_q[MTOT*DD];
__device__ float g_k[MTOT*DD];
__device__ float g_v[MTOT*DD];

// ---------------------------------------------------------------------------
// Kernel 1: fused QKV projection.  out[M,128] = x[M,2048] @ W[2048,128]
// blockIdx.y in {0,1,2} selects (Wq->g_q, Wk->g_k, Wv->g_v)
// BM=128, BN=128, BK=16, 256 threads, 8x8 register microtile
// ---------------------------------------------------------------------------
#define PBM 128
#define PBK 16
#define APAD (PBM+4)   // 132
#define BPAD (DD+4)    // 132

__global__ __launch_bounds__(256) void proj_kernel(
    const float* __restrict__ x,
    const float* __restrict__ Wq,
    const float* __restrict__ Wk,
    const float* __restrict__ Wv)
{
    __shared__ float As[PBK][APAD];   // k-major, m contiguous
    __shared__ float Bs[PBK][BPAD];

    const float* W;
    float* out;
    if (blockIdx.y == 0)      { W = Wq; out = g_q; }
    else if (blockIdx.y == 1) { W = Wk; out = g_k; }
    else                      { W = Wv; out = g_v; }

    const int m0 = blockIdx.x * PBM;
    const int t  = threadIdx.x;
    const int tm = (t >> 4) * 8;   // 0..120
    const int tn = (t & 15) * 8;   // 0..120

    float acc[8][8];
    #pragma unroll
    for (int i = 0; i < 8; i++)
        #pragma unroll
        for (int j = 0; j < 8; j++) acc[i][j] = 0.f;

    for (int k0 = 0; k0 < CC; k0 += PBK) {
        // Load A tile: 128 rows x 16 k  (512 float4 loads, 2 per thread)
        #pragma unroll
        for (int it = 0; it < 2; it++) {
            int idx = t + it * 256;          // 0..511
            int r   = idx >> 2;              // 0..127
            int kk  = (idx & 3) * 4;         // 0,4,8,12
            float4 v = *reinterpret_cast<const float4*>(
                &x[(size_t)(m0 + r) * CC + k0 + kk]);
            As[kk + 0][r] = v.x;
            As[kk + 1][r] = v.y;
            As[kk + 2][r] = v.z;
            As[kk + 3][r] = v.w;
        }
        // Load B tile: 16 rows x 128 cols
        #pragma unroll
        for (int it = 0; it < 2; it++) {
            int idx = t + it * 256;          // 0..511
            int kk  = idx >> 5;              // 0..15
            int n   = (idx & 31) * 4;        // 0..124
            float4 v = *reinterpret_cast<const float4*>(
                &W[(size_t)(k0 + kk) * DD + n]);
            *reinterpret_cast<float4*>(&Bs[kk][n]) = v;
        }
        __syncthreads();

        #pragma unroll
        for (int kk = 0; kk < PBK; kk++) {
            float4 a0 = *reinterpret_cast<const float4*>(&As[kk][tm]);
            float4 a1 = *reinterpret_cast<const float4*>(&As[kk][tm + 4]);
            float4 b0 = *reinterpret_cast<const float4*>(&Bs[kk][tn]);
            float4 b1 = *reinterpret_cast<const float4*>(&Bs[kk][tn + 4]);
            float a[8] = {a0.x, a0.y, a0.z, a0.w, a1.x, a1.y, a1.z, a1.w};
            float b[8] = {b0.x, b0.y, b0.z, b0.w, b1.x, b1.y, b1.z, b1.w};
            #pragma unroll
            for (int i = 0; i < 8; i++)
                #pragma unroll
                for (int j = 0; j < 8; j++)
                    acc[i][j] += a[i] * b[j];
        }
        __syncthreads();
    }

    // Epilogue
    #pragma unroll
    for (int i = 0; i < 8; i++) {
        float4 o0 = make_float4(acc[i][0], acc[i][1], acc[i][2], acc[i][3]);
        float4 o1 = make_float4(acc[i][4], acc[i][5], acc[i][6], acc[i][7]);
        float* p = &out[(size_t)(m0 + tm + i) * DD + tn];
        *reinterpret_cast<float4*>(p)     = o0;
        *reinterpret_cast<float4*>(p + 4) = o1;
    }
}

// ---------------------------------------------------------------------------
// Kernel 2: causal flash attention, fp32.
// Grid: (T/BQ, B).  One CTA handles BQ=64 queries; streams BKV=64 key tiles.
// 256 threads. Dynamic smem: Q/K/V tiles (padded) + S tile + row stats.
// ---------------------------------------------------------------------------
#define BQ 64
#define BKV 64
#define QPAD 132
#define SPAD 68
#define ATT_SMEM_FLOATS (3*BQ*QPAD + BQ*SPAD + 3*BQ)
#define ATT_SMEM_BYTES (ATT_SMEM_FLOATS * 4)

__global__ __launch_bounds__(256) void attn_kernel(float* __restrict__ outp)
{
    extern __shared__ float sm[];
    float* Qs     = sm;                    // [BQ][QPAD]
    float* Ks     = Qs + BQ * QPAD;        // [BKV][QPAD]
    float* Vs     = Ks + BKV * QPAD;       // [BKV][QPAD]
    float* Ss     = Vs + BKV * QPAD;       // [BQ][SPAD]
    float* row_m  = Ss + BQ * SPAD;        // [BQ]
    float* row_l  = row_m + BQ;            // [BQ]
    float* row_al = row_l + BQ;            // [BQ]

    const int b  = blockIdx.y;
    const int qt = (gridDim.x - 1) - blockIdx.x;   // big (causal-long) tiles launch first
    const int m0 = qt * BQ;
    const int t  = threadIdx.x;
    const float scale = 0.08838834764831845f;      // 1/sqrt(128)

    const float* qbase = g_q + ((size_t)b * TT + m0) * DD;

    // Load Q tile (pre-scaled)
    #pragma unroll
    for (int it = 0; it < 8; it++) {
        int idx = t + it * 256;           // 0..2047 float4 units
        int r   = idx >> 5;               // 0..63
        int c   = (idx & 31) * 4;         // 0..124
        float4 v = *reinterpret_cast<const float4*>(&qbase[(size_t)r * DD + c]);
        v.x *= scale; v.y *= scale; v.z *= scale; v.w *= scale;
        *reinterpret_cast<float4*>(&Qs[r * QPAD + c]) = v;
    }
    if (t < BQ) { row_m[t] = -INFINITY; row_l[t] = 0.f; }

    // acc mapping: thread owns 4 query rows x 8 output cols
    const int rb = (t >> 4) * 4;   // 0..60
    const int cb = (t & 15) * 8;   // 0..120
    float acc[4][8];
    #pragma unroll
    for (int i = 0; i < 4; i++)
        #pragma unroll
        for (int j = 0; j < 8; j++) acc[i][j] = 0.f;

    __syncthreads();

    for (int kt = 0; kt <= qt; kt++) {
        const float* kbase = g_k + ((size_t)b * TT + kt * BKV) * DD;
        const float* vbase = g_v + ((size_t)b * TT + kt * BKV) * DD;
        #pragma unroll
        for (int it = 0; it < 8; it++) {
            int idx = t + it * 256;
            int r   = idx >> 5;
            int c   = (idx & 31) * 4;
            *reinterpret_cast<float4*>(&Ks[r * QPAD + c]) =
                *reinterpret_cast<const float4*>(&kbase[(size_t)r * DD + c]);
            *reinterpret_cast<float4*>(&Vs[r * QPAD + c]) =
                *reinterpret_cast<const float4*>(&vbase[(size_t)r * DD + c]);
        }
        __syncthreads();

        // S = Qs @ Ks^T : thread computes 4x4 microtile
        const int kg = (t & 15) * 4;   // 0..60  (4 key cols)
        float s[4][4];
        #pragma unroll
        for (int i = 0; i < 4; i++)
            #pragma unroll
            for (int j = 0; j < 4; j++) s[i][j] = 0.f;

        for (int d = 0; d < DD; d += 4) {
            float4 a0 = *reinterpret_cast<const float4*>(&Qs[(rb + 0) * QPAD + d]);
            float4 a1 = *reinterpret_cast<const float4*>(&Qs[(rb + 1) * QPAD + d]);
            float4 a2 = *reinterpret_cast<const float4*>(&Qs[(rb + 2) * QPAD + d]);
            float4 a3 = *reinterpret_cast<const float4*>(&Qs[(rb + 3) * QPAD + d]);
            float4 b0 = *reinterpret_cast<const float4*>(&Ks[(kg + 0) * QPAD + d]);
            float4 b1 = *reinterpret_cast<const float4*>(&Ks[(kg + 1) * QPAD + d]);
            float4 b2 = *reinterpret_cast<const float4*>(&Ks[(kg + 2) * QPAD + d]);
            float4 b3 = *reinterpret_cast<const float4*>(&Ks[(kg + 3) * QPAD + d]);
            float av[4][4] = {{a0.x,a0.y,a0.z,a0.w},{a1.x,a1.y,a1.z,a1.w},
                              {a2.x,a2.y,a2.z,a2.w},{a3.x,a3.y,a3.z,a3.w}};
            float bv[4][4] = {{b0.x,b0.y,b0.z,b0.w},{b1.x,b1.y,b1.z,b1.w},
                              {b2.x,b2.y,b2.z,b2.w},{b3.x,b3.y,b3.z,b3.w}};
            #pragma unroll
            for (int i = 0; i < 4; i++)
                #pragma unroll
                for (int j = 0; j < 4; j++)
                    s[i][j] += av[i][0]*bv[j][0] + av[i][1]*bv[j][1]
                             + av[i][2]*bv[j][2] + av[i][3]*bv[j][3];
        }

        const bool diag = (kt == qt);
        #pragma unroll
        for (int i = 0; i < 4; i++)
            #pragma unroll
            for (int j = 0; j < 4; j++) {
                float v = s[i][j];
                if (diag && (kg + j) > (rb + i)) v = -1e30f;
                Ss[(rb + i) * SPAD + (kg + j)] = v;
            }
        __syncthreads();

        // Online softmax stats: one thread per query row
        if (t < BQ) {
            int r = t;
            float mold = row_m[r];
            float mx = mold;
            #pragma unroll 8
            for (int k = 0; k < BKV; k++) mx = fmaxf(mx, Ss[r * SPAD + k]);
            float alpha = __expf(mold - mx);   // 0 on first tile (mold = -inf)
            float sum = 0.f;
            #pragma unroll 8
            for (int k = 0; k < BKV; k++) {
                float p = __expf(Ss[r * SPAD + k] - mx);
                Ss[r * SPAD + k] = p;
                sum += p;
            }
            row_m[r]  = mx;
            row_l[r]  = row_l[r] * alpha + sum;
            row_al[r] = alpha;
        }
        __syncthreads();

        // acc = acc*alpha + P @ V
        float al[4];
        #pragma unroll
        for (int i = 0; i < 4; i++) al[i] = row_al[rb + i];
        #pragma unroll
        for (int i = 0; i < 4; i++)
            #pragma unroll
            for (int j = 0; j < 8; j++) acc[i][j] *= al[i];

        for (int k = 0; k < BKV; k++) {
            float p0 = Ss[(rb + 0) * SPAD + k];
            float p1 = Ss[(rb + 1) * SPAD + k];
            float p2 = Ss[(rb + 2) * SPAD + k];
            float p3 = Ss[(rb + 3) * SPAD + k];
            float4 v0 = *reinterpret_cast<const float4*>(&Vs[k * QPAD + cb]);
            float4 v1 = *reinterpret_cast<const float4*>(&Vs[k * QPAD + cb + 4]);
            float vv[8] = {v0.x, v0.y, v0.z, v0.w, v1.x, v1.y, v1.z, v1.w};
            #pragma unroll
            for (int j = 0; j < 8; j++) {
                acc[0][j] += p0 * vv[j];
                acc[1][j] += p1 * vv[j];
                acc[2][j] += p2 * vv[j];
                acc[3][j] += p3 * vv[j];
            }
        }
        __syncthreads();
    }

    // Final normalize + store
    float invl[4];
    #pragma unroll
    for (int i = 0; i < 4; i++) invl[i] = 1.0f / row_l[rb + i];
    #pragma unroll
    for (int i = 0; i < 4; i++) {
        float4 o0 = make_float4(acc[i][0]*invl[i], acc[i][1]*invl[i],
                                acc[i][2]*invl[i], acc[i][3]*invl[i]);
        float4 o1 = make_float4(acc[i][4]*invl[i], acc[i][5]*invl[i],
                                acc[i][6]*invl[i], acc[i][7]*invl[i]);
        float* p = &outp[((size_t)b * TT + m0 + rb + i) * DD + cb];
        *reinterpret_cast<float4*>(p)     = o0;
        *reinterpret_cast<float4*>(p + 4) = o1;
    }
}

// ---------------------------------------------------------------------------
extern "C" void kernel_launch(void* const* d_in, const int* in_sizes, int n_in,
                              void* d_out, int out_size)
{
    const float* x  = (const float*)d_in[0];
    const float* Wq = (const float*)d_in[1];
    const float* Wk = (const float*)d_in[2];
    const float* Wv = (const float*)d_in[3];
    float* out = (float*)d_out;

    (void)in_sizes; (void)n_in; (void)out_size;

    // QKV projections: grid (16384/128, 3)
    proj_kernel<<<dim3(MTOT / PBM, 3), 256>>>(x, Wq, Wk, Wv);

    // Flash attention: grid (T/BQ, B), 119.5 KB dynamic smem
    cudaFuncSetAttribute(attn_kernel,
                         cudaFuncAttributeMaxDynamicSharedMemorySize,
                         ATT_SMEM_BYTES);
    attn_kernel<<<dim3(TT / BQ, BB), 256, ATT_SMEM_BYTES>>>(out);
}

// round 4
// speedup vs baseline: 1.5286x; 1.5286x over previous
#include <cuda_runtime.h>
#include <cuda_bf16.h>
#include <cstdint>
#include <math.h>

// Problem constants
#define BB 4
#define TT 4096
#define CC 2048
#define DD 128
#define MTOT (BB*TT)   // 16384

// ---------------------------------------------------------------------------
// Global scratch
// ---------------------------------------------------------------------------
__device__ float g_q[MTOT*DD];
__device__ float g_k[MTOT*DD];
__device__ float g_v[MTOT*DD];
// W^T split-bf16: [3][N=128][K=2048]
__device__ __nv_bfloat16 g_wt_hi[3][DD*CC];
__device__ __nv_bfloat16 g_wt_lo[3][DD*CC];

__device__ __forceinline__ uint32_t smem_u32(const void* p) {
    uint32_t a;
    asm("{ .reg .u64 t; cvta.to.shared.u64 t, %1; cvt.u32.u64 %0, t; }"
        : "=r"(a) : "l"(p));
    return a;
}
__device__ __forceinline__ void ldmatrix_x4(uint32_t& r0, uint32_t& r1,
                                            uint32_t& r2, uint32_t& r3,
                                            uint32_t addr) {
    asm volatile("ldmatrix.sync.aligned.m8n8.x4.shared.b16 {%0,%1,%2,%3}, [%4];"
                 : "=r"(r0), "=r"(r1), "=r"(r2), "=r"(r3) : "r"(addr));
}
__device__ __forceinline__ void mma16816(float* c, const uint32_t* a, const uint32_t* b) {
    asm volatile(
        "mma.sync.aligned.m16n8k16.row.col.f32.bf16.bf16.f32 "
        "{%0,%1,%2,%3}, {%4,%5,%6,%7}, {%8,%9}, {%0,%1,%2,%3};"
        : "+f"(c[0]), "+f"(c[1]), "+f"(c[2]), "+f"(c[3])
        : "r"(a[0]), "r"(a[1]), "r"(a[2]), "r"(a[3]), "r"(b[0]), "r"(b[1]));
}

// ---------------------------------------------------------------------------
// Kernel 0: split W (fp32 [K=2048, N=128]) into bf16 hi/lo transposed [N, K]
// ---------------------------------------------------------------------------
__global__ __launch_bounds__(128) void prep_w_kernel(
    const float* __restrict__ Wq,
    const float* __restrict__ Wk,
    const float* __restrict__ Wv)
{
    const int n = blockIdx.x;
    const int w = blockIdx.y;
    const float* W = (w == 0) ? Wq : (w == 1) ? Wk : Wv;
    __nv_bfloat16* hi = g_wt_hi[w];
    __nv_bfloat16* lo = g_wt_lo[w];
    const int k0 = threadIdx.x * 16;
    #pragma unroll
    for (int i = 0; i < 16; i++) {
        float v = W[(size_t)(k0 + i) * DD + n];
        __nv_bfloat16 h = __float2bfloat16(v);
        __nv_bfloat16 l = __float2bfloat16(v - __bfloat162float(h));
        hi[(size_t)n * CC + k0 + i] = h;
        lo[(size_t)n * CC + k0 + i] = l;
    }
}

// ---------------------------------------------------------------------------
// Kernel 1: projection via mma.sync m16n8k16 bf16 (split hi/lo, 3 terms).
// Grid (MTOT/128, 3); 256 threads (8 warps, 4x2). BK=32.
// ---------------------------------------------------------------------------
#define LDA 40   // bf16 elems per smem row (80 B, 16B-multiple for ldmatrix)

__global__ __launch_bounds__(256) void proj_mma_kernel(const float* __restrict__ x)
{
    __shared__ __nv_bfloat16 Ah[128 * LDA];
    __shared__ __nv_bfloat16 Al[128 * LDA];
    __shared__ __nv_bfloat16 Bh[128 * LDA];
    __shared__ __nv_bfloat16 Bl[128 * LDA];

    const int tid  = threadIdx.x;
    const int lane = tid & 31;
    const int wid  = tid >> 5;
    const int wm   = (wid >> 1) * 32;   // warp M offset: 0,32,64,96
    const int wn   = (wid & 1) * 64;    // warp N offset: 0,64
    const int m0   = blockIdx.x * 128;
    const int w    = blockIdx.y;

    const __nv_bfloat16* __restrict__ wt_h = g_wt_hi[w];
    const __nv_bfloat16* __restrict__ wt_l = g_wt_lo[w];
    float* out = (w == 0) ? g_q : (w == 1) ? g_k : g_v;

    const uint32_t ah_base = smem_u32(Ah);
    const uint32_t al_base = smem_u32(Al);
    const uint32_t bh_base = smem_u32(Bh);
    const uint32_t bl_base = smem_u32(Bl);

    float acc[2][8][4];
    #pragma unroll
    for (int i = 0; i < 2; i++)
        #pragma unroll
        for (int j = 0; j < 8; j++)
            #pragma unroll
            for (int c = 0; c < 4; c++) acc[i][j][c] = 0.f;

    // ldmatrix lane-address components
    const int lb = lane >> 3;   // block 0..3
    const int lr = lane & 7;    // row within block

    for (int kc = 0; kc < CC / 32; kc++) {
        const int k0 = kc * 32;

        // ---- A tile: x[128, 32] fp32 -> split bf16 hi/lo
        #pragma unroll
        for (int it = 0; it < 4; it++) {
            int idx = tid + it * 256;        // 0..1023 float4 units
            int r   = idx >> 3;              // 0..127
            int c4  = (idx & 7) * 4;         // 0..28
            float4 v = *reinterpret_cast<const float4*>(
                &x[(size_t)(m0 + r) * CC + k0 + c4]);
            __nv_bfloat16 h0 = __float2bfloat16(v.x);
            __nv_bfloat16 h1 = __float2bfloat16(v.y);
            __nv_bfloat16 h2 = __float2bfloat16(v.z);
            __nv_bfloat16 h3 = __float2bfloat16(v.w);
            __nv_bfloat16 l0 = __float2bfloat16(v.x - __bfloat162float(h0));
            __nv_bfloat16 l1 = __float2bfloat16(v.y - __bfloat162float(h1));
            __nv_bfloat16 l2 = __float2bfloat16(v.z - __bfloat162float(h2));
            __nv_bfloat16 l3 = __float2bfloat16(v.w - __bfloat162float(h3));
            uint32_t hp0 = ((uint32_t)__bfloat16_as_ushort(h1) << 16) | __bfloat16_as_ushort(h0);
            uint32_t hp1 = ((uint32_t)__bfloat16_as_ushort(h3) << 16) | __bfloat16_as_ushort(h2);
            uint32_t lp0 = ((uint32_t)__bfloat16_as_ushort(l1) << 16) | __bfloat16_as_ushort(l0);
            uint32_t lp1 = ((uint32_t)__bfloat16_as_ushort(l3) << 16) | __bfloat16_as_ushort(l2);
            *reinterpret_cast<uint2*>(&Ah[r * LDA + c4]) = make_uint2(hp0, hp1);
            *reinterpret_cast<uint2*>(&Al[r * LDA + c4]) = make_uint2(lp0, lp1);
        }
        // ---- B tile: W^T[128 n, 32 k] bf16 hi/lo
        #pragma unroll
        for (int it = 0; it < 2; it++) {
            int idx = tid + it * 256;        // 0..511 8-elem units
            int n   = idx >> 2;              // 0..127
            int k8  = (idx & 3) * 8;         // 0,8,16,24
            *reinterpret_cast<uint4*>(&Bh[n * LDA + k8]) =
                *reinterpret_cast<const uint4*>(&wt_h[(size_t)n * CC + k0 + k8]);
            *reinterpret_cast<uint4*>(&Bl[n * LDA + k8]) =
                *reinterpret_cast<const uint4*>(&wt_l[(size_t)n * CC + k0 + k8]);
        }
        __syncthreads();

        #pragma unroll
        for (int ks = 0; ks < 32; ks += 16) {
            // A fragments: a0 rows0-7/k0-7, a1 rows8-15/k0-7, a2 rows0-7/k8-15, a3 rows8-15/k8-15
            uint32_t ah[2][4], al[2][4];
            #pragma unroll
            for (int mf = 0; mf < 2; mf++) {
                uint32_t off = (uint32_t)((wm + mf * 16 + (lb & 1) * 8 + lr) * LDA
                                          + ks + (lb >> 1) * 8) * 2;
                ldmatrix_x4(ah[mf][0], ah[mf][1], ah[mf][2], ah[mf][3], ah_base + off);
                ldmatrix_x4(al[mf][0], al[mf][1], al[mf][2], al[mf][3], al_base + off);
            }
            // B fragments: block0 n0-7/k0-7 (b0 of nf even), block1 n0-7/k8-15 (b1),
            //              block2 n8-15/k0-7, block3 n8-15/k8-15
            uint32_t bh[8][2], bl[8][2];
            #pragma unroll
            for (int np = 0; np < 4; np++) {
                uint32_t off = (uint32_t)((wn + np * 16 + (lb >> 1) * 8 + lr) * LDA
                                          + ks + (lb & 1) * 8) * 2;
                uint32_t r0, r1, r2, r3;
                ldmatrix_x4(r0, r1, r2, r3, bh_base + off);
                bh[2*np][0] = r0; bh[2*np][1] = r1; bh[2*np+1][0] = r2; bh[2*np+1][1] = r3;
                ldmatrix_x4(r0, r1, r2, r3, bl_base + off);
                bl[2*np][0] = r0; bl[2*np][1] = r1; bl[2*np+1][0] = r2; bl[2*np+1][1] = r3;
            }
            #pragma unroll
            for (int mf = 0; mf < 2; mf++)
                #pragma unroll
                for (int nf = 0; nf < 8; nf++) {
                    mma16816(acc[mf][nf], ah[mf], bh[nf]);
                    mma16816(acc[mf][nf], al[mf], bh[nf]);
                    mma16816(acc[mf][nf], ah[mf], bl[nf]);
                }
        }
        __syncthreads();
    }

    // ---- epilogue: C fragment rows g / g+8, cols 2t,2t+1
    const int g  = lane >> 2;
    const int t4 = lane & 3;
    #pragma unroll
    for (int mf = 0; mf < 2; mf++)
        #pragma unroll
        for (int nf = 0; nf < 8; nf++) {
            int row0 = m0 + wm + mf * 16 + g;
            int col  = wn + nf * 8 + t4 * 2;
            *reinterpret_cast<float2*>(&out[(size_t)row0 * DD + col]) =
                make_float2(acc[mf][nf][0], acc[mf][nf][1]);
            *reinterpret_cast<float2*>(&out[(size_t)(row0 + 8) * DD + col]) =
                make_float2(acc[mf][nf][2], acc[mf][nf][3]);
        }
}

// ---------------------------------------------------------------------------
// Kernel 2: causal flash attention, fp32, register softmax + balanced sched.
// 128 CTAs; CTA c handles sorted work items c and 255-c (65 KV-tiles each).
// item j -> qt = 63 - (j>>2), b = j&3.
// ---------------------------------------------------------------------------
#define BQ 64
#define BKV 64
#define QPAD 132
#define SPAD 68
#define ATT_SMEM_FLOATS (3*BQ*QPAD + BQ*SPAD)
#define ATT_SMEM_BYTES (ATT_SMEM_FLOATS * 4)

__global__ __launch_bounds__(256) void attn_kernel(float* __restrict__ outp)
{
    extern __shared__ float sm[];
    float* Qs = sm;                    // [BQ][QPAD]
    float* Ks = Qs + BQ * QPAD;        // [BKV][QPAD]
    float* Vs = Ks + BKV * QPAD;       // [BKV][QPAD]
    float* Ss = Vs + BKV * QPAD;       // [BQ][SPAD]

    const int t  = threadIdx.x;
    const int rb = (t >> 4) * 4;       // 4 query rows
    const int kg = (t & 15) * 4;       // 4 key cols (S phase)
    const int cb = (t & 15) * 8;       // 8 out cols (PV phase)
    const float scale = 0.08838834764831845f;  // 1/sqrt(128)

    #pragma unroll
    for (int item_i = 0; item_i < 2; item_i++) {
        const int j  = (item_i == 0) ? blockIdx.x : (255 - (int)blockIdx.x);
        const int qt = 63 - (j >> 2);
        const int b  = j & 3;
        const int m0 = qt * BQ;

        const float* qbase = g_q + ((size_t)b * TT + m0) * DD;
        #pragma unroll
        for (int it = 0; it < 8; it++) {
            int idx = t + it * 256;
            int r   = idx >> 5;
            int c   = (idx & 31) * 4;
            float4 v = *reinterpret_cast<const float4*>(&qbase[(size_t)r * DD + c]);
            v.x *= scale; v.y *= scale; v.z *= scale; v.w *= scale;
            *reinterpret_cast<float4*>(&Qs[r * QPAD + c]) = v;
        }

        float m_run[4], l_run[4];
        float acc[4][8];
        #pragma unroll
        for (int i = 0; i < 4; i++) {
            m_run[i] = -INFINITY; l_run[i] = 0.f;
            #pragma unroll
            for (int jj = 0; jj < 8; jj++) acc[i][jj] = 0.f;
        }
        __syncthreads();

        for (int kt = 0; kt <= qt; kt++) {
            const float* kbase = g_k + ((size_t)b * TT + kt * BKV) * DD;
            const float* vbase = g_v + ((size_t)b * TT + kt * BKV) * DD;
            #pragma unroll
            for (int it = 0; it < 8; it++) {
                int idx = t + it * 256;
                int r   = idx >> 5;
                int c   = (idx & 31) * 4;
                *reinterpret_cast<float4*>(&Ks[r * QPAD + c]) =
                    *reinterpret_cast<const float4*>(&kbase[(size_t)r * DD + c]);
                *reinterpret_cast<float4*>(&Vs[r * QPAD + c]) =
                    *reinterpret_cast<const float4*>(&vbase[(size_t)r * DD + c]);
            }
            __syncthreads();

            // S = Qs @ Ks^T : 4x4 microtile
            float s[4][4];
            #pragma unroll
            for (int i = 0; i < 4; i++)
                #pragma unroll
                for (int jj = 0; jj < 4; jj++) s[i][jj] = 0.f;

            for (int d = 0; d < DD; d += 4) {
                float4 a0 = *reinterpret_cast<const float4*>(&Qs[(rb + 0) * QPAD + d]);
                float4 a1 = *reinterpret_cast<const float4*>(&Qs[(rb + 1) * QPAD + d]);
                float4 a2 = *reinterpret_cast<const float4*>(&Qs[(rb + 2) * QPAD + d]);
                float4 a3 = *reinterpret_cast<const float4*>(&Qs[(rb + 3) * QPAD + d]);
                float4 b0 = *reinterpret_cast<const float4*>(&Ks[(kg + 0) * QPAD + d]);
                float4 b1 = *reinterpret_cast<const float4*>(&Ks[(kg + 1) * QPAD + d]);
                float4 b2 = *reinterpret_cast<const float4*>(&Ks[(kg + 2) * QPAD + d]);
                float4 b3 = *reinterpret_cast<const float4*>(&Ks[(kg + 3) * QPAD + d]);
                float av[4][4] = {{a0.x,a0.y,a0.z,a0.w},{a1.x,a1.y,a1.z,a1.w},
                                  {a2.x,a2.y,a2.z,a2.w},{a3.x,a3.y,a3.z,a3.w}};
                float bv[4][4] = {{b0.x,b0.y,b0.z,b0.w},{b1.x,b1.y,b1.z,b1.w},
                                  {b2.x,b2.y,b2.z,b2.w},{b3.x,b3.y,b3.z,b3.w}};
                #pragma unroll
                for (int i = 0; i < 4; i++)
                    #pragma unroll
                    for (int jj = 0; jj < 4; jj++)
                        s[i][jj] += av[i][0]*bv[jj][0] + av[i][1]*bv[jj][1]
                                  + av[i][2]*bv[jj][2] + av[i][3]*bv[jj][3];
            }

            if (kt == qt) {   // diagonal causal mask
                #pragma unroll
                for (int i = 0; i < 4; i++)
                    #pragma unroll
                    for (int jj = 0; jj < 4; jj++)
                        if (kg + jj > rb + i) s[i][jj] = -1e30f;
            }

            // ---- register online softmax (16 lanes share a row group)
            #pragma unroll
            for (int i = 0; i < 4; i++) {
                float mx = fmaxf(fmaxf(s[i][0], s[i][1]), fmaxf(s[i][2], s[i][3]));
                mx = fmaxf(mx, __shfl_xor_sync(0xFFFFFFFFu, mx, 1, 16));
                mx = fmaxf(mx, __shfl_xor_sync(0xFFFFFFFFu, mx, 2, 16));
                mx = fmaxf(mx, __shfl_xor_sync(0xFFFFFFFFu, mx, 4, 16));
                mx = fmaxf(mx, __shfl_xor_sync(0xFFFFFFFFu, mx, 8, 16));
                float mnew = fmaxf(m_run[i], mx);
                float alpha = __expf(m_run[i] - mnew);
                float p0 = __expf(s[i][0] - mnew);
                float p1 = __expf(s[i][1] - mnew);
                float p2 = __expf(s[i][2] - mnew);
                float p3 = __expf(s[i][3] - mnew);
                float ps = p0 + p1 + p2 + p3;
                ps += __shfl_xor_sync(0xFFFFFFFFu, ps, 1, 16);
                ps += __shfl_xor_sync(0xFFFFFFFFu, ps, 2, 16);
                ps += __shfl_xor_sync(0xFFFFFFFFu, ps, 4, 16);
                ps += __shfl_xor_sync(0xFFFFFFFFu, ps, 8, 16);
                l_run[i] = l_run[i] * alpha + ps;
                m_run[i] = mnew;
                #pragma unroll
                for (int jj = 0; jj < 8; jj++) acc[i][jj] *= alpha;
                Ss[(rb + i) * SPAD + kg + 0] = p0;
                Ss[(rb + i) * SPAD + kg + 1] = p1;
                Ss[(rb + i) * SPAD + kg + 2] = p2;
                Ss[(rb + i) * SPAD + kg + 3] = p3;
            }
            __syncthreads();

            // acc += P @ V
            for (int k = 0; k < BKV; k++) {
                float p0 = Ss[(rb + 0) * SPAD + k];
                float p1 = Ss[(rb + 1) * SPAD + k];
                float p2 = Ss[(rb + 2) * SPAD + k];
                float p3 = Ss[(rb + 3) * SPAD + k];
                float4 v0 = *reinterpret_cast<const float4*>(&Vs[k * QPAD + cb]);
                float4 v1 = *reinterpret_cast<const float4*>(&Vs[k * QPAD + cb + 4]);
                float vv[8] = {v0.x, v0.y, v0.z, v0.w, v1.x, v1.y, v1.z, v1.w};
                #pragma unroll
                for (int jj = 0; jj < 8; jj++) {
                    acc[0][jj] += p0 * vv[jj];
                    acc[1][jj] += p1 * vv[jj];
                    acc[2][jj] += p2 * vv[jj];
                    acc[3][jj] += p3 * vv[jj];
                }
            }
            __syncthreads();
        }

        // store (normalized)
        #pragma unroll
        for (int i = 0; i < 4; i++) {
            float inv = 1.0f / l_run[i];
            float4 o0 = make_float4(acc[i][0]*inv, acc[i][1]*inv, acc[i][2]*inv, acc[i][3]*inv);
            float4 o1 = make_float4(acc[i][4]*inv, acc[i][5]*inv, acc[i][6]*inv, acc[i][7]*inv);
            float* p = &outp[((size_t)b * TT + m0 + rb + i) * DD + cb];
            *reinterpret_cast<float4*>(p)     = o0;
            *reinterpret_cast<float4*>(p + 4) = o1;
        }
    }
}

// ---------------------------------------------------------------------------
extern "C" void kernel_launch(void* const* d_in, const int* in_sizes, int n_in,
                              void* d_out, int out_size)
{
    const float* x  = (const float*)d_in[0];
    const float* Wq = (const float*)d_in[1];
    const float* Wk = (const float*)d_in[2];
    const float* Wv = (const float*)d_in[3];
    float* out = (float*)d_out;
    (void)in_sizes; (void)n_in; (void)out_size;

    prep_w_kernel<<<dim3(DD, 3), 128>>>(Wq, Wk, Wv);
    proj_mma_kernel<<<dim3(MTOT / 128, 3), 256>>>(x);

    cudaFuncSetAttribute(attn_kernel,
                         cudaFuncAttributeMaxDynamicSharedMemorySize,
                         ATT_SMEM_BYTES);
    attn_kernel<<<128, 256, ATT_SMEM_BYTES>>>(out);
}

// round 5
// speedup vs baseline: 3.3643x; 2.2008x over previous
#include <cuda_runtime.h>
#include <cuda_bf16.h>
#include <cstdint>
#include <math.h>

#define BB 4
#define TT 4096
#define CC 2048
#define DD 128
#define MTOT (BB*TT)   // 16384

// ---------------------------------------------------------------------------
// Global scratch: projections stored as split bf16 (hi/lo)
// q,k: [m][d];  v: transposed [d][m]
// ---------------------------------------------------------------------------
__device__ __nv_bfloat16 g_qh[MTOT*DD];
__device__ __nv_bfloat16 g_ql[MTOT*DD];
__device__ __nv_bfloat16 g_kh[MTOT*DD];
__device__ __nv_bfloat16 g_kl[MTOT*DD];
__device__ __nv_bfloat16 g_vth[DD*MTOT];
__device__ __nv_bfloat16 g_vtl[DD*MTOT];
// W^T split-bf16: [3][N=128][K=2048]
__device__ __nv_bfloat16 g_wt_hi[3][DD*CC];
__device__ __nv_bfloat16 g_wt_lo[3][DD*CC];

__device__ __forceinline__ uint32_t smem_u32(const void* p) {
    uint32_t a;
    asm("{ .reg .u64 t; cvta.to.shared.u64 t, %1; cvt.u32.u64 %0, t; }"
        : "=r"(a) : "l"(p));
    return a;
}
__device__ __forceinline__ void ldmatrix_x4(uint32_t& r0, uint32_t& r1,
                                            uint32_t& r2, uint32_t& r3,
                                            uint32_t addr) {
    asm volatile("ldmatrix.sync.aligned.m8n8.x4.shared.b16 {%0,%1,%2,%3}, [%4];"
                 : "=r"(r0), "=r"(r1), "=r"(r2), "=r"(r3) : "r"(addr));
}
__device__ __forceinline__ void mma16816(float* c, const uint32_t* a, const uint32_t* b) {
    asm volatile(
        "mma.sync.aligned.m16n8k16.row.col.f32.bf16.bf16.f32 "
        "{%0,%1,%2,%3}, {%4,%5,%6,%7}, {%8,%9}, {%0,%1,%2,%3};"
        : "+f"(c[0]), "+f"(c[1]), "+f"(c[2]), "+f"(c[3])
        : "r"(a[0]), "r"(a[1]), "r"(a[2]), "r"(a[3]), "r"(b[0]), "r"(b[1]));
}
__device__ __forceinline__ uint32_t packh2(__nv_bfloat16 a, __nv_bfloat16 b) {
    return ((uint32_t)__bfloat16_as_ushort(b) << 16) | __bfloat16_as_ushort(a);
}

// ---------------------------------------------------------------------------
// Kernel 0: split W (fp32 [K,128]) into bf16 hi/lo transposed [N,K]
// ---------------------------------------------------------------------------
__global__ __launch_bounds__(128) void prep_w_kernel(
    const float* __restrict__ Wq,
    const float* __restrict__ Wk,
    const float* __restrict__ Wv)
{
    const int n = blockIdx.x;
    const int w = blockIdx.y;
    const float* W = (w == 0) ? Wq : (w == 1) ? Wk : Wv;
    __nv_bfloat16* hi = g_wt_hi[w];
    __nv_bfloat16* lo = g_wt_lo[w];
    const int k0 = threadIdx.x * 16;
    #pragma unroll
    for (int i = 0; i < 16; i++) {
        float v = W[(size_t)(k0 + i) * DD + n];
        __nv_bfloat16 h = __float2bfloat16(v);
        __nv_bfloat16 l = __float2bfloat16(v - __bfloat162float(h));
        hi[(size_t)n * CC + k0 + i] = h;
        lo[(size_t)n * CC + k0 + i] = l;
    }
}

// ---------------------------------------------------------------------------
// Kernel 1: projection via mma.sync m16n8k16 bf16 (split hi/lo, 3 terms).
// Grid (MTOT/128, 3); 256 threads (8 warps, 4x2). BK=32.
// Epilogue stores split bf16: q scaled [m][d], k [m][d], v transposed [d][m].
// ---------------------------------------------------------------------------
#define LDA 40   // bf16 elems per smem row

__global__ __launch_bounds__(256) void proj_mma_kernel(const float* __restrict__ x)
{
    __shared__ __nv_bfloat16 Ah[128 * LDA];
    __shared__ __nv_bfloat16 Al[128 * LDA];
    __shared__ __nv_bfloat16 Bh[128 * LDA];
    __shared__ __nv_bfloat16 Bl[128 * LDA];

    const int tid  = threadIdx.x;
    const int lane = tid & 31;
    const int wid  = tid >> 5;
    const int wm   = (wid >> 1) * 32;
    const int wn   = (wid & 1) * 64;
    const int m0   = blockIdx.x * 128;
    const int w    = blockIdx.y;

    const __nv_bfloat16* __restrict__ wt_h = g_wt_hi[w];
    const __nv_bfloat16* __restrict__ wt_l = g_wt_lo[w];

    const uint32_t ah_base = smem_u32(Ah);
    const uint32_t al_base = smem_u32(Al);
    const uint32_t bh_base = smem_u32(Bh);
    const uint32_t bl_base = smem_u32(Bl);

    float acc[2][8][4];
    #pragma unroll
    for (int i = 0; i < 2; i++)
        #pragma unroll
        for (int j = 0; j < 8; j++)
            #pragma unroll
            for (int c = 0; c < 4; c++) acc[i][j][c] = 0.f;

    const int lb = lane >> 3;
    const int lr = lane & 7;

    for (int kc = 0; kc < CC / 32; kc++) {
        const int k0 = kc * 32;
        #pragma unroll
        for (int it = 0; it < 4; it++) {
            int idx = tid + it * 256;
            int r   = idx >> 3;
            int c4  = (idx & 7) * 4;
            float4 v = *reinterpret_cast<const float4*>(
                &x[(size_t)(m0 + r) * CC + k0 + c4]);
            __nv_bfloat16 h0 = __float2bfloat16(v.x);
            __nv_bfloat16 h1 = __float2bfloat16(v.y);
            __nv_bfloat16 h2 = __float2bfloat16(v.z);
            __nv_bfloat16 h3 = __float2bfloat16(v.w);
            __nv_bfloat16 l0 = __float2bfloat16(v.x - __bfloat162float(h0));
            __nv_bfloat16 l1 = __float2bfloat16(v.y - __bfloat162float(h1));
            __nv_bfloat16 l2 = __float2bfloat16(v.z - __bfloat162float(h2));
            __nv_bfloat16 l3 = __float2bfloat16(v.w - __bfloat162float(h3));
            *reinterpret_cast<uint2*>(&Ah[r * LDA + c4]) =
                make_uint2(packh2(h0, h1), packh2(h2, h3));
            *reinterpret_cast<uint2*>(&Al[r * LDA + c4]) =
                make_uint2(packh2(l0, l1), packh2(l2, l3));
        }
        #pragma unroll
        for (int it = 0; it < 2; it++) {
            int idx = tid + it * 256;
            int n   = idx >> 2;
            int k8  = (idx & 3) * 8;
            *reinterpret_cast<uint4*>(&Bh[n * LDA + k8]) =
                *reinterpret_cast<const uint4*>(&wt_h[(size_t)n * CC + k0 + k8]);
            *reinterpret_cast<uint4*>(&Bl[n * LDA + k8]) =
                *reinterpret_cast<const uint4*>(&wt_l[(size_t)n * CC + k0 + k8]);
        }
        __syncthreads();

        #pragma unroll
        for (int ks = 0; ks < 32; ks += 16) {
            uint32_t ah[2][4], al[2][4];
            #pragma unroll
            for (int mf = 0; mf < 2; mf++) {
                uint32_t off = (uint32_t)((wm + mf * 16 + (lb & 1) * 8 + lr) * LDA
                                          + ks + (lb >> 1) * 8) * 2;
                ldmatrix_x4(ah[mf][0], ah[mf][1], ah[mf][2], ah[mf][3], ah_base + off);
                ldmatrix_x4(al[mf][0], al[mf][1], al[mf][2], al[mf][3], al_base + off);
            }
            uint32_t bh[8][2], bl[8][2];
            #pragma unroll
            for (int np = 0; np < 4; np++) {
                uint32_t off = (uint32_t)((wn + np * 16 + (lb >> 1) * 8 + lr) * LDA
                                          + ks + (lb & 1) * 8) * 2;
                uint32_t r0, r1, r2, r3;
                ldmatrix_x4(r0, r1, r2, r3, bh_base + off);
                bh[2*np][0] = r0; bh[2*np][1] = r1; bh[2*np+1][0] = r2; bh[2*np+1][1] = r3;
                ldmatrix_x4(r0, r1, r2, r3, bl_base + off);
                bl[2*np][0] = r0; bl[2*np][1] = r1; bl[2*np+1][0] = r2; bl[2*np+1][1] = r3;
            }
            #pragma unroll
            for (int mf = 0; mf < 2; mf++)
                #pragma unroll
                for (int nf = 0; nf < 8; nf++) {
                    mma16816(acc[mf][nf], ah[mf], bh[nf]);
                    mma16816(acc[mf][nf], al[mf], bh[nf]);
                    mma16816(acc[mf][nf], ah[mf], bl[nf]);
                }
        }
        __syncthreads();
    }

    // ---- epilogue: split outputs to bf16 hi/lo
    const int g  = lane >> 2;
    const int t4 = lane & 3;
    const float qscale = 0.08838834764831845f;  // 1/sqrt(128)
    #pragma unroll
    for (int mf = 0; mf < 2; mf++)
        #pragma unroll
        for (int nf = 0; nf < 8; nf++) {
            int row0 = m0 + wm + mf * 16 + g;
            int col  = wn + nf * 8 + t4 * 2;
            float c0 = acc[mf][nf][0], c1 = acc[mf][nf][1];
            float c2 = acc[mf][nf][2], c3 = acc[mf][nf][3];
            if (w == 0) { c0 *= qscale; c1 *= qscale; c2 *= qscale; c3 *= qscale; }
            __nv_bfloat16 h0 = __float2bfloat16(c0), h1 = __float2bfloat16(c1);
            __nv_bfloat16 h2 = __float2bfloat16(c2), h3 = __float2bfloat16(c3);
            __nv_bfloat16 l0 = __float2bfloat16(c0 - __bfloat162float(h0));
            __nv_bfloat16 l1 = __float2bfloat16(c1 - __bfloat162float(h1));
            __nv_bfloat16 l2 = __float2bfloat16(c2 - __bfloat162float(h2));
            __nv_bfloat16 l3 = __float2bfloat16(c3 - __bfloat162float(h3));
            if (w == 2) {
                // transposed scatter: [d][m]
                g_vth[(size_t)col * MTOT + row0]           = h0;
                g_vth[(size_t)(col + 1) * MTOT + row0]     = h1;
                g_vth[(size_t)col * MTOT + row0 + 8]       = h2;
                g_vth[(size_t)(col + 1) * MTOT + row0 + 8] = h3;
                g_vtl[(size_t)col * MTOT + row0]           = l0;
                g_vtl[(size_t)(col + 1) * MTOT + row0]     = l1;
                g_vtl[(size_t)col * MTOT + row0 + 8]       = l2;
                g_vtl[(size_t)(col + 1) * MTOT + row0 + 8] = l3;
            } else {
                __nv_bfloat16* oh = (w == 0) ? g_qh : g_kh;
                __nv_bfloat16* ol = (w == 0) ? g_ql : g_kl;
                *reinterpret_cast<uint32_t*>(&oh[(size_t)row0 * DD + col])       = packh2(h0, h1);
                *reinterpret_cast<uint32_t*>(&oh[(size_t)(row0 + 8) * DD + col]) = packh2(h2, h3);
                *reinterpret_cast<uint32_t*>(&ol[(size_t)row0 * DD + col])       = packh2(l0, l1);
                *reinterpret_cast<uint32_t*>(&ol[(size_t)(row0 + 8) * DD + col]) = packh2(l2, l3);
            }
        }
}

// ---------------------------------------------------------------------------
// Kernel 2: causal flash attention via mma.sync bf16 split (3 terms each GEMM)
// 128 CTAs x 256 thr (8 warps = 4m x 2n over 64x64 S tile).
// CTA c handles items c and 255-c (65 KV tiles each).
// ---------------------------------------------------------------------------
#define LDK 136
#define LDV 72
#define AQH 0
#define AQL 17408
#define AKH 34816
#define AKL 52224
#define AVH 69632
#define AVL 88064
#define ARED 106496            // redM[2][64], redS[2][64] floats
#define AORED 34816            // overlaps K region (64x132 fp32)
#define ATT_SMEM_BYTES 108544

__global__ __launch_bounds__(256) void attn_kernel(float* __restrict__ outp)
{
    extern __shared__ char smb[];
    __nv_bfloat16* Qh = (__nv_bfloat16*)(smb + AQH);
    __nv_bfloat16* Ql = (__nv_bfloat16*)(smb + AQL);
    __nv_bfloat16* Kh = (__nv_bfloat16*)(smb + AKH);
    __nv_bfloat16* Kl = (__nv_bfloat16*)(smb + AKL);
    __nv_bfloat16* Vh = (__nv_bfloat16*)(smb + AVH);
    __nv_bfloat16* Vl = (__nv_bfloat16*)(smb + AVL);
    float* redM = (float*)(smb + ARED);          // [2][64]
    float* redS = redM + 128;                    // [2][64]
    float* Ored = (float*)(smb + AORED);         // [64][132]

    const uint32_t qh_b = smem_u32(Qh), ql_b = smem_u32(Ql);
    const uint32_t kh_b = smem_u32(Kh), kl_b = smem_u32(Kl);
    const uint32_t vh_b = smem_u32(Vh), vl_b = smem_u32(Vl);

    const int tid  = threadIdx.x;
    const int lane = tid & 31;
    const int wid  = tid >> 5;
    const int wmi  = wid >> 1;         // 0..3
    const int wni  = wid & 1;          // 0..1
    const int wm   = wmi * 16;
    const int wn   = wni * 32;
    const int g    = lane >> 2;
    const int t4   = lane & 3;
    const int lb   = lane >> 3;
    const int lr   = lane & 7;

    #pragma unroll 1
    for (int item_i = 0; item_i < 2; item_i++) {
        const int j  = (item_i == 0) ? blockIdx.x : (255 - (int)blockIdx.x);
        const int qt = 63 - (j >> 2);
        const int b  = j & 3;
        const int m0 = qt * 64;
        const size_t bT = (size_t)b * TT;

        // load Q tile [64][128] hi/lo
        #pragma unroll
        for (int it = 0; it < 4; it++) {
            int idx = tid + it * 256;          // 0..1023 uint4 units
            int r   = idx >> 4;
            int c8  = (idx & 15) * 8;
            *reinterpret_cast<uint4*>(&Qh[r * LDK + c8]) =
                *reinterpret_cast<const uint4*>(&g_qh[(bT + m0 + r) * DD + c8]);
            *reinterpret_cast<uint4*>(&Ql[r * LDK + c8]) =
                *reinterpret_cast<const uint4*>(&g_ql[(bT + m0 + r) * DD + c8]);
        }

        float oacc[16][4];
        #pragma unroll
        for (int i = 0; i < 16; i++)
            #pragma unroll
            for (int c = 0; c < 4; c++) oacc[i][c] = 0.f;
        float m_run0 = -1e30f, m_run1 = -1e30f;
        float l_run0 = 0.f, l_run1 = 0.f;
        __syncthreads();

        #pragma unroll 1
        for (int kt = 0; kt <= qt; kt++) {
            // ---- load K [64][128], V^T [128][64] hi/lo
            #pragma unroll
            for (int it = 0; it < 4; it++) {
                int idx = tid + it * 256;
                int r   = idx >> 4;
                int c8  = (idx & 15) * 8;
                *reinterpret_cast<uint4*>(&Kh[r * LDK + c8]) =
                    *reinterpret_cast<const uint4*>(&g_kh[(bT + kt * 64 + r) * DD + c8]);
                *reinterpret_cast<uint4*>(&Kl[r * LDK + c8]) =
                    *reinterpret_cast<const uint4*>(&g_kl[(bT + kt * 64 + r) * DD + c8]);
            }
            #pragma unroll
            for (int it = 0; it < 4; it++) {
                int idx = tid + it * 256;          // 0..1023
                int r   = idx >> 3;                // 0..127 (d)
                int c8  = (idx & 7) * 8;           // 0..56 (s)
                *reinterpret_cast<uint4*>(&Vh[r * LDV + c8]) =
                    *reinterpret_cast<const uint4*>(&g_vth[(size_t)r * MTOT + bT + kt * 64 + c8]);
                *reinterpret_cast<uint4*>(&Vl[r * LDV + c8]) =
                    *reinterpret_cast<const uint4*>(&g_vtl[(size_t)r * MTOT + bT + kt * 64 + c8]);
            }
            __syncthreads();

            // ---- S = Q K^T (split, 3 terms): warp computes 16x32
            float sacc[4][4];
            #pragma unroll
            for (int i = 0; i < 4; i++)
                #pragma unroll
                for (int c = 0; c < 4; c++) sacc[i][c] = 0.f;

            #pragma unroll
            for (int d8 = 0; d8 < 8; d8++) {
                uint32_t qa[4], qla[4];
                {
                    uint32_t off = (uint32_t)((wm + (lb & 1) * 8 + lr) * LDK
                                              + d8 * 16 + (lb >> 1) * 8) * 2;
                    ldmatrix_x4(qa[0], qa[1], qa[2], qa[3], qh_b + off);
                    ldmatrix_x4(qla[0], qla[1], qla[2], qla[3], ql_b + off);
                }
                #pragma unroll
                for (int np = 0; np < 2; np++) {
                    uint32_t off = (uint32_t)((wn + np * 16 + (lb >> 1) * 8 + lr) * LDK
                                              + d8 * 16 + (lb & 1) * 8) * 2;
                    uint32_t h0, h1, h2, h3, l0, l1, l2, l3;
                    ldmatrix_x4(h0, h1, h2, h3, kh_b + off);
                    ldmatrix_x4(l0, l1, l2, l3, kl_b + off);
                    uint32_t bh0[2] = {h0, h1}, bh1[2] = {h2, h3};
                    uint32_t bl0[2] = {l0, l1}, bl1[2] = {l2, l3};
                    mma16816(sacc[2*np],   qa,  bh0);
                    mma16816(sacc[2*np],   qla, bh0);
                    mma16816(sacc[2*np],   qa,  bl0);
                    mma16816(sacc[2*np+1], qa,  bh1);
                    mma16816(sacc[2*np+1], qla, bh1);
                    mma16816(sacc[2*np+1], qa,  bl1);
                }
            }

            // ---- causal mask on diagonal tile
            if (kt == qt) {
                const int r0 = wm + g, r1 = r0 + 8;
                #pragma unroll
                for (int nf = 0; nf < 4; nf++) {
                    int col = wn + nf * 8 + 2 * t4;
                    if (col     > r0) sacc[nf][0] = -1e30f;
                    if (col + 1 > r0) sacc[nf][1] = -1e30f;
                    if (col     > r1) sacc[nf][2] = -1e30f;
                    if (col + 1 > r1) sacc[nf][3] = -1e30f;
                }
            }

            // ---- warp-local row max (over 32 cols)
            float lm0 = -1e30f, lm1 = -1e30f;
            #pragma unroll
            for (int nf = 0; nf < 4; nf++) {
                lm0 = fmaxf(lm0, fmaxf(sacc[nf][0], sacc[nf][1]));
                lm1 = fmaxf(lm1, fmaxf(sacc[nf][2], sacc[nf][3]));
            }
            lm0 = fmaxf(lm0, __shfl_xor_sync(0xFFFFFFFFu, lm0, 1));
            lm0 = fmaxf(lm0, __shfl_xor_sync(0xFFFFFFFFu, lm0, 2));
            lm1 = fmaxf(lm1, __shfl_xor_sync(0xFFFFFFFFu, lm1, 1));
            lm1 = fmaxf(lm1, __shfl_xor_sync(0xFFFFFFFFu, lm1, 2));

            // p = exp(s - lm), warp-local sums
            float ps0 = 0.f, ps1 = 0.f;
            #pragma unroll
            for (int nf = 0; nf < 4; nf++) {
                sacc[nf][0] = __expf(sacc[nf][0] - lm0);
                sacc[nf][1] = __expf(sacc[nf][1] - lm0);
                sacc[nf][2] = __expf(sacc[nf][2] - lm1);
                sacc[nf][3] = __expf(sacc[nf][3] - lm1);
                ps0 += sacc[nf][0] + sacc[nf][1];
                ps1 += sacc[nf][2] + sacc[nf][3];
            }
            ps0 += __shfl_xor_sync(0xFFFFFFFFu, ps0, 1);
            ps0 += __shfl_xor_sync(0xFFFFFFFFu, ps0, 2);
            ps1 += __shfl_xor_sync(0xFFFFFFFFu, ps1, 1);
            ps1 += __shfl_xor_sync(0xFFFFFFFFu, ps1, 2);

            if (t4 == 0) {
                redM[wni * 64 + wm + g]     = lm0;
                redM[wni * 64 + wm + g + 8] = lm1;
                redS[wni * 64 + wm + g]     = ps0;
                redS[wni * 64 + wm + g + 8] = ps1;
            }
            __syncthreads();

            // ---- combine across the 2 n-warps
            const int r0 = wm + g, r1 = r0 + 8;
            float la0 = redM[r0],      lb0 = redM[64 + r0];
            float la1 = redM[r1],      lb1 = redM[64 + r1];
            float sa0 = redS[r0],      sb0 = redS[64 + r0];
            float sa1 = redS[r1],      sb1 = redS[64 + r1];
            float mn0 = fmaxf(m_run0, fmaxf(la0, lb0));
            float mn1 = fmaxf(m_run1, fmaxf(la1, lb1));
            float rs0 = sa0 * __expf(la0 - mn0) + sb0 * __expf(lb0 - mn0);
            float rs1 = sa1 * __expf(la1 - mn1) + sb1 * __expf(lb1 - mn1);
            float alpha0 = __expf(m_run0 - mn0);
            float alpha1 = __expf(m_run1 - mn1);
            l_run0 = l_run0 * alpha0 + rs0;
            l_run1 = l_run1 * alpha1 + rs1;
            m_run0 = mn0; m_run1 = mn1;
            float scl0 = __expf(lm0 - mn0);
            float scl1 = __expf(lm1 - mn1);

            #pragma unroll
            for (int nf = 0; nf < 16; nf++) {
                oacc[nf][0] *= alpha0; oacc[nf][1] *= alpha0;
                oacc[nf][2] *= alpha1; oacc[nf][3] *= alpha1;
            }
            #pragma unroll
            for (int nf = 0; nf < 4; nf++) {
                sacc[nf][0] *= scl0; sacc[nf][1] *= scl0;
                sacc[nf][2] *= scl1; sacc[nf][3] *= scl1;
            }

            // ---- PV: P (registers) @ V^T tiles, split 3 terms
            #pragma unroll
            for (int ks2 = 0; ks2 < 2; ks2++) {
                uint32_t aPh[4], aPl[4];
                #pragma unroll
                for (int half = 0; half < 2; half++) {
                    const float* pc = sacc[2 * ks2 + half];
                    __nv_bfloat16 h0 = __float2bfloat16(pc[0]);
                    __nv_bfloat16 h1 = __float2bfloat16(pc[1]);
                    __nv_bfloat16 h2 = __float2bfloat16(pc[2]);
                    __nv_bfloat16 h3 = __float2bfloat16(pc[3]);
                    __nv_bfloat16 l0 = __float2bfloat16(pc[0] - __bfloat162float(h0));
                    __nv_bfloat16 l1 = __float2bfloat16(pc[1] - __bfloat162float(h1));
                    __nv_bfloat16 l2 = __float2bfloat16(pc[2] - __bfloat162float(h2));
                    __nv_bfloat16 l3 = __float2bfloat16(pc[3] - __bfloat162float(h3));
                    aPh[0 + 2 * half] = packh2(h0, h1);
                    aPh[1 + 2 * half] = packh2(h2, h3);
                    aPl[0 + 2 * half] = packh2(l0, l1);
                    aPl[1 + 2 * half] = packh2(l2, l3);
                }
                // reorder: a0=(m-lo,k-lo) a1=(m-hi,k-lo) a2=(m-lo,k-hi) a3=(m-hi,k-hi)
                uint32_t Ah_[4] = {aPh[0], aPh[1], aPh[2], aPh[3]};
                uint32_t Al_[4] = {aPl[0], aPl[1], aPl[2], aPl[3]};
                #pragma unroll
                for (int nd = 0; nd < 8; nd++) {
                    uint32_t off = (uint32_t)((nd * 16 + (lb >> 1) * 8 + lr) * LDV
                                              + wn + ks2 * 16 + (lb & 1) * 8) * 2;
                    uint32_t h0, h1, h2, h3, l0, l1, l2, l3;
                    ldmatrix_x4(h0, h1, h2, h3, vh_b + off);
                    ldmatrix_x4(l0, l1, l2, l3, vl_b + off);
                    uint32_t bh0[2] = {h0, h1}, bh1[2] = {h2, h3};
                    uint32_t bl0[2] = {l0, l1}, bl1[2] = {l2, l3};
                    mma16816(oacc[2*nd],   Ah_, bh0);
                    mma16816(oacc[2*nd],   Al_, bh0);
                    mma16816(oacc[2*nd],   Ah_, bl0);
                    mma16816(oacc[2*nd+1], Ah_, bh1);
                    mma16816(oacc[2*nd+1], Al_, bh1);
                    mma16816(oacc[2*nd+1], Ah_, bl1);
                }
            }
            __syncthreads();   // protect K/V/red for next tile
        }

        // ---- cross-warp O reduction (n-warp pair) + store
        const int r0 = wm + g, r1 = r0 + 8;
        if (wni == 1) {
            #pragma unroll
            for (int nf = 0; nf < 16; nf++) {
                int col = nf * 8 + 2 * t4;
                *reinterpret_cast<float2*>(&Ored[r0 * 132 + col]) =
                    make_float2(oacc[nf][0], oacc[nf][1]);
                *reinterpret_cast<float2*>(&Ored[r1 * 132 + col]) =
                    make_float2(oacc[nf][2], oacc[nf][3]);
            }
        }
        __syncthreads();
        if (wni == 0) {
            float inv0 = 1.0f / l_run0;
            float inv1 = 1.0f / l_run1;
            #pragma unroll
            for (int nf = 0; nf < 16; nf++) {
                int col = nf * 8 + 2 * t4;
                float2 p0 = *reinterpret_cast<float2*>(&Ored[r0 * 132 + col]);
                float2 p1 = *reinterpret_cast<float2*>(&Ored[r1 * 132 + col]);
                float2 o0 = make_float2((oacc[nf][0] + p0.x) * inv0,
                                        (oacc[nf][1] + p0.y) * inv0);
                float2 o1 = make_float2((oacc[nf][2] + p1.x) * inv1,
                                        (oacc[nf][3] + p1.y) * inv1);
                *reinterpret_cast<float2*>(&outp[(bT + m0 + r0) * DD + col]) = o0;
                *reinterpret_cast<float2*>(&outp[(bT + m0 + r1) * DD + col]) = o1;
            }
        }
        __syncthreads();
    }
}

// ---------------------------------------------------------------------------
extern "C" void kernel_launch(void* const* d_in, const int* in_sizes, int n_in,
                              void* d_out, int out_size)
{
    const float* x  = (const float*)d_in[0];
    const float* Wq = (const float*)d_in[1];
    const float* Wk = (const float*)d_in[2];
    const float* Wv = (const float*)d_in[3];
    float* out = (float*)d_out;
    (void)in_sizes; (void)n_in; (void)out_size;

    prep_w_kernel<<<dim3(DD, 3), 128>>>(Wq, Wk, Wv);
    proj_mma_kernel<<<dim3(MTOT / 128, 3), 256>>>(x);

    cudaFuncSetAttribute(attn_kernel,
                         cudaFuncAttributeMaxDynamicSharedMemorySize,
                         ATT_SMEM_BYTES);
    attn_kernel<<<128, 256, ATT_SMEM_BYTES>>>(out);
}

// round 7
// speedup vs baseline: 3.9947x; 1.1874x over previous
#include <cuda_runtime.h>
#include <cuda_bf16.h>
#include <cstdint>
#include <math.h>

#define BB 4
#define TT 4096
#define CC 2048
#define DD 128
#define MTOT (BB*TT)   // 16384

// ---------------------------------------------------------------------------
// Global scratch: projections stored as split bf16 (hi/lo)
// q,k: [m][d];  v: transposed [d][m]
// ---------------------------------------------------------------------------
__device__ __nv_bfloat16 g_qh[MTOT*DD];
__device__ __nv_bfloat16 g_ql[MTOT*DD];
__device__ __nv_bfloat16 g_kh[MTOT*DD];
__device__ __nv_bfloat16 g_kl[MTOT*DD];
__device__ __nv_bfloat16 g_vth[DD*MTOT];
__device__ __nv_bfloat16 g_vtl[DD*MTOT];
__device__ __nv_bfloat16 g_wt_hi[3][DD*CC];
__device__ __nv_bfloat16 g_wt_lo[3][DD*CC];

__device__ __forceinline__ uint32_t smem_u32(const void* p) {
    uint32_t a;
    asm("{ .reg .u64 t; cvta.to.shared.u64 t, %1; cvt.u32.u64 %0, t; }"
        : "=r"(a) : "l"(p));
    return a;
}
__device__ __forceinline__ void ldmatrix_x4(uint32_t& r0, uint32_t& r1,
                                            uint32_t& r2, uint32_t& r3,
                                            uint32_t addr) {
    asm volatile("ldmatrix.sync.aligned.m8n8.x4.shared.b16 {%0,%1,%2,%3}, [%4];"
                 : "=r"(r0), "=r"(r1), "=r"(r2), "=r"(r3) : "r"(addr));
}
__device__ __forceinline__ void mma16816(float* c, const uint32_t* a, const uint32_t* b) {
    asm volatile(
        "mma.sync.aligned.m16n8k16.row.col.f32.bf16.bf16.f32 "
        "{%0,%1,%2,%3}, {%4,%5,%6,%7}, {%8,%9}, {%0,%1,%2,%3};"
        : "+f"(c[0]), "+f"(c[1]), "+f"(c[2]), "+f"(c[3])
        : "r"(a[0]), "r"(a[1]), "r"(a[2]), "r"(a[3]), "r"(b[0]), "r"(b[1]));
}
__device__ __forceinline__ uint32_t packh2(__nv_bfloat16 a, __nv_bfloat16 b) {
    return ((uint32_t)__bfloat16_as_ushort(b) << 16) | __bfloat16_as_ushort(a);
}
__device__ __forceinline__ void cp16(uint32_t smem, const void* g) {
    asm volatile("cp.async.cg.shared.global [%0], [%1], 16;" :: "r"(smem), "l"(g));
}
#define CP_COMMIT() asm volatile("cp.async.commit_group;" ::: "memory")
#define CP_WAIT0() asm volatile("cp.async.wait_group 0;" ::: "memory")
#define CP_WAIT1() asm volatile("cp.async.wait_group 1;" ::: "memory")

// ---------------------------------------------------------------------------
// Kernel 0: split W (fp32 [K,128]) into bf16 hi/lo transposed [N,K].
// grid (16, 3), 256 thr. Coalesced load -> smem -> coalesced transposed store.
// ---------------------------------------------------------------------------
#define LDP 132
#define PREP_SMEM (2 * 128 * LDP * 2)   // hi + lo, bf16

__global__ __launch_bounds__(256) void prep_w_kernel(
    const float* __restrict__ Wq,
    const float* __restrict__ Wk,
    const float* __restrict__ Wv)
{
    extern __shared__ __nv_bfloat16 sp[];
    __nv_bfloat16* shh = sp;                 // [128][LDP]
    __nv_bfloat16* shl = sp + 128 * LDP;
    const int w  = blockIdx.y;
    const int k0 = blockIdx.x * 128;
    const float* W = (w == 0) ? Wq : (w == 1) ? Wk : Wv;
    const int tid = threadIdx.x;

    #pragma unroll
    for (int it = 0; it < 16; it++) {
        int idx = tid + it * 256;            // 0..4095 float4 units
        int r   = idx >> 5;                  // k row 0..127
        int c4  = (idx & 31) * 4;            // n col
        float4 v = *reinterpret_cast<const float4*>(&W[(size_t)(k0 + r) * DD + c4]);
        __nv_bfloat16 h0 = __float2bfloat16(v.x), h1 = __float2bfloat16(v.y);
        __nv_bfloat16 h2 = __float2bfloat16(v.z), h3 = __float2bfloat16(v.w);
        __nv_bfloat16 l0 = __float2bfloat16(v.x - __bfloat162float(h0));
        __nv_bfloat16 l1 = __float2bfloat16(v.y - __bfloat162float(h1));
        __nv_bfloat16 l2 = __float2bfloat16(v.z - __bfloat162float(h2));
        __nv_bfloat16 l3 = __float2bfloat16(v.w - __bfloat162float(h3));
        *reinterpret_cast<uint2*>(&shh[r * LDP + c4]) =
            make_uint2(packh2(h0, h1), packh2(h2, h3));
        *reinterpret_cast<uint2*>(&shl[r * LDP + c4]) =
            make_uint2(packh2(l0, l1), packh2(l2, l3));
    }
    __syncthreads();

    const int nb = tid >> 3;           // 0..31
    const int kc = (tid & 7) * 16;     // 0..112
    #pragma unroll
    for (int rep = 0; rep < 4; rep++) {
        int n = rep * 32 + nb;
        ushort hbuf[16], lbuf[16];
        #pragma unroll
        for (int i = 0; i < 16; i++) {
            hbuf[i] = __bfloat16_as_ushort(shh[(kc + i) * LDP + n]);
            lbuf[i] = __bfloat16_as_ushort(shl[(kc + i) * LDP + n]);
        }
        __nv_bfloat16* dh = &g_wt_hi[w][(size_t)n * CC + k0 + kc];
        __nv_bfloat16* dl = &g_wt_lo[w][(size_t)n * CC + k0 + kc];
        *reinterpret_cast<uint4*>(dh)     = *reinterpret_cast<uint4*>(&hbuf[0]);
        *reinterpret_cast<uint4*>(dh + 8) = *reinterpret_cast<uint4*>(&hbuf[8]);
        *reinterpret_cast<uint4*>(dl)     = *reinterpret_cast<uint4*>(&lbuf[0]);
        *reinterpret_cast<uint4*>(dl + 8) = *reinterpret_cast<uint4*>(&lbuf[8]);
    }
}

// ---------------------------------------------------------------------------
// Kernel 1: projection, mma.sync bf16 split, 2-stage pipelined.
// grid (3, 128): w fastest -> 3 CTAs share x tile in L2.
// Dyn smem: A stages 2x20480 at 0, B stages 2x20480 at 40960.
// ---------------------------------------------------------------------------
#define LDA 40
#define PJ_SMEM 81920

__global__ __launch_bounds__(256) void proj_mma_kernel(const float* __restrict__ x)
{
    extern __shared__ char psm[];
    const uint32_t sb = smem_u32(psm);

    const int tid  = threadIdx.x;
    const int lane = tid & 31;
    const int wid  = tid >> 5;
    const int wm   = (wid >> 1) * 32;
    const int wn   = (wid & 1) * 64;
    const int w    = blockIdx.x;
    const int m0   = blockIdx.y * 128;

    const __nv_bfloat16* __restrict__ wt_h = g_wt_hi[w];
    const __nv_bfloat16* __restrict__ wt_l = g_wt_lo[w];

    float acc[2][8][4];
    #pragma unroll
    for (int i = 0; i < 2; i++)
        #pragma unroll
        for (int j = 0; j < 8; j++)
            #pragma unroll
            for (int c = 0; c < 4; c++) acc[i][j][c] = 0.f;

    const int lb = lane >> 3;
    const int lr = lane & 7;
    const int ar = tid >> 3;            // A row this thread loads (0..127 per it? no)
    (void)ar;

    // A prefetch registers (chunk 0)
    float4 xv[4];
    #pragma unroll
    for (int it = 0; it < 4; it++) {
        int idx = tid + it * 256;
        int r   = idx >> 3;
        int c4  = (idx & 7) * 4;
        xv[it] = *reinterpret_cast<const float4*>(&x[(size_t)(m0 + r) * CC + c4]);
    }
    // B prefetch chunk 0 -> stage 0
    {
        uint32_t bh0 = sb + 40960;
        uint32_t bl0 = bh0 + 10240;
        #pragma unroll
        for (int it = 0; it < 2; it++) {
            int idx = tid + it * 256;
            int n   = idx >> 2;
            int k8  = (idx & 3) * 8;
            cp16(bh0 + (n * LDA + k8) * 2, &wt_h[(size_t)n * CC + k8]);
            cp16(bl0 + (n * LDA + k8) * 2, &wt_l[(size_t)n * CC + k8]);
        }
        CP_COMMIT();
    }

    for (int kc = 0; kc < 64; kc++) {
        const int s = kc & 1;
        __nv_bfloat16* Ah = (__nv_bfloat16*)(psm + s * 20480);
        __nv_bfloat16* Al = (__nv_bfloat16*)(psm + s * 20480 + 10240);
        const uint32_t ah_base = sb + s * 20480;
        const uint32_t al_base = ah_base + 10240;
        const uint32_t bh_base = sb + 40960 + s * 20480;
        const uint32_t bl_base = bh_base + 10240;

        // convert & store A (chunk kc) from regs
        #pragma unroll
        for (int it = 0; it < 4; it++) {
            int idx = tid + it * 256;
            int r   = idx >> 3;
            int c4  = (idx & 7) * 4;
            float4 v = xv[it];
            __nv_bfloat16 h0 = __float2bfloat16(v.x), h1 = __float2bfloat16(v.y);
            __nv_bfloat16 h2 = __float2bfloat16(v.z), h3 = __float2bfloat16(v.w);
            __nv_bfloat16 l0 = __float2bfloat16(v.x - __bfloat162float(h0));
            __nv_bfloat16 l1 = __float2bfloat16(v.y - __bfloat162float(h1));
            __nv_bfloat16 l2 = __float2bfloat16(v.z - __bfloat162float(h2));
            __nv_bfloat16 l3 = __float2bfloat16(v.w - __bfloat162float(h3));
            *reinterpret_cast<uint2*>(&Ah[r * LDA + c4]) =
                make_uint2(packh2(h0, h1), packh2(h2, h3));
            *reinterpret_cast<uint2*>(&Al[r * LDA + c4]) =
                make_uint2(packh2(l0, l1), packh2(l2, l3));
        }
        // prefetch A regs + B cp.async for chunk kc+1
        if (kc < 63) {
            const int k0n = (kc + 1) * 32;
            #pragma unroll
            for (int it = 0; it < 4; it++) {
                int idx = tid + it * 256;
                int r   = idx >> 3;
                int c4  = (idx & 7) * 4;
                xv[it] = *reinterpret_cast<const float4*>(
                    &x[(size_t)(m0 + r) * CC + k0n + c4]);
            }
            uint32_t bhn = sb + 40960 + (s ^ 1) * 20480;
            uint32_t bln = bhn + 10240;
            #pragma unroll
            for (int it = 0; it < 2; it++) {
                int idx = tid + it * 256;
                int n   = idx >> 2;
                int k8  = (idx & 3) * 8;
                cp16(bhn + (n * LDA + k8) * 2, &wt_h[(size_t)n * CC + k0n + k8]);
                cp16(bln + (n * LDA + k8) * 2, &wt_l[(size_t)n * CC + k0n + k8]);
            }
            CP_COMMIT();
            CP_WAIT1();
        } else {
            CP_WAIT0();
        }
        __syncthreads();

        #pragma unroll
        for (int ks = 0; ks < 32; ks += 16) {
            uint32_t ah[2][4], al[2][4];
            #pragma unroll
            for (int mf = 0; mf < 2; mf++) {
                uint32_t off = (uint32_t)((wm + mf * 16 + (lb & 1) * 8 + lr) * LDA
                                          + ks + (lb >> 1) * 8) * 2;
                ldmatrix_x4(ah[mf][0], ah[mf][1], ah[mf][2], ah[mf][3], ah_base + off);
                ldmatrix_x4(al[mf][0], al[mf][1], al[mf][2], al[mf][3], al_base + off);
            }
            uint32_t bh[8][2], bl[8][2];
            #pragma unroll
            for (int np = 0; np < 4; np++) {
                uint32_t off = (uint32_t)((wn + np * 16 + (lb >> 1) * 8 + lr) * LDA
                                          + ks + (lb & 1) * 8) * 2;
                uint32_t r0, r1, r2, r3;
                ldmatrix_x4(r0, r1, r2, r3, bh_base + off);
                bh[2*np][0] = r0; bh[2*np][1] = r1; bh[2*np+1][0] = r2; bh[2*np+1][1] = r3;
                ldmatrix_x4(r0, r1, r2, r3, bl_base + off);
                bl[2*np][0] = r0; bl[2*np][1] = r1; bl[2*np+1][0] = r2; bl[2*np+1][1] = r3;
            }
            #pragma unroll
            for (int mf = 0; mf < 2; mf++)
                #pragma unroll
                for (int nf = 0; nf < 8; nf++) {
                    mma16816(acc[mf][nf], ah[mf], bh[nf]);
                    mma16816(acc[mf][nf], al[mf], bh[nf]);
                    mma16816(acc[mf][nf], ah[mf], bl[nf]);
                }
        }
        __syncthreads();
    }

    // ---- epilogue: split outputs to bf16 hi/lo
    const int g  = lane >> 2;
    const int t4 = lane & 3;
    const float qscale = 0.08838834764831845f;
    #pragma unroll
    for (int mf = 0; mf < 2; mf++)
        #pragma unroll
        for (int nf = 0; nf < 8; nf++) {
            int row0 = m0 + wm + mf * 16 + g;
            int col  = wn + nf * 8 + t4 * 2;
            float c0 = acc[mf][nf][0], c1 = acc[mf][nf][1];
            float c2 = acc[mf][nf][2], c3 = acc[mf][nf][3];
            if (w == 0) { c0 *= qscale; c1 *= qscale; c2 *= qscale; c3 *= qscale; }
            __nv_bfloat16 h0 = __float2bfloat16(c0), h1 = __float2bfloat16(c1);
            __nv_bfloat16 h2 = __float2bfloat16(c2), h3 = __float2bfloat16(c3);
            __nv_bfloat16 l0 = __float2bfloat16(c0 - __bfloat162float(h0));
            __nv_bfloat16 l1 = __float2bfloat16(c1 - __bfloat162float(h1));
            __nv_bfloat16 l2 = __float2bfloat16(c2 - __bfloat162float(h2));
            __nv_bfloat16 l3 = __float2bfloat16(c3 - __bfloat162float(h3));
            if (w == 2) {
                g_vth[(size_t)col * MTOT + row0]           = h0;
                g_vth[(size_t)(col + 1) * MTOT + row0]     = h1;
                g_vth[(size_t)col * MTOT + row0 + 8]       = h2;
                g_vth[(size_t)(col + 1) * MTOT + row0 + 8] = h3;
                g_vtl[(size_t)col * MTOT + row0]           = l0;
                g_vtl[(size_t)(col + 1) * MTOT + row0]     = l1;
                g_vtl[(size_t)col * MTOT + row0 + 8]       = l2;
                g_vtl[(size_t)(col + 1) * MTOT + row0 + 8] = l3;
            } else {
                __nv_bfloat16* oh = (w == 0) ? g_qh : g_kh;
                __nv_bfloat16* ol = (w == 0) ? g_ql : g_kl;
                *reinterpret_cast<uint32_t*>(&oh[(size_t)row0 * DD + col])       = packh2(h0, h1);
                *reinterpret_cast<uint32_t*>(&oh[(size_t)(row0 + 8) * DD + col]) = packh2(h2, h3);
                *reinterpret_cast<uint32_t*>(&ol[(size_t)row0 * DD + col])       = packh2(l0, l1);
                *reinterpret_cast<uint32_t*>(&ol[(size_t)(row0 + 8) * DD + col]) = packh2(l2, l3);
            }
        }
}

// ---------------------------------------------------------------------------
// Kernel 2: causal flash attention, mma.sync bf16 split, cp.async 2-stage.
// 128 CTAs x 256 thr; CTA c handles items c and 255-c.
// Smem: Q 34816 | K stages 2x34816 @34816 | V stages 2x36864 @104448 |
//       red @178176 (1KB). Ored overlaps K stage0 (@34816).
// ---------------------------------------------------------------------------
#define LDK 136
#define LDV 72
#define AKST(s) (34816 + (s) * 34816)
#define AVST(s) (104448 + (s) * 36864)
#define ATT_SMEM_BYTES 179200

__global__ __launch_bounds__(256) void attn_kernel(float* __restrict__ outp)
{
    extern __shared__ char smb[];
    const uint32_t sb = smem_u32(smb);
    __nv_bfloat16* Qh = (__nv_bfloat16*)(smb);
    __nv_bfloat16* Ql = (__nv_bfloat16*)(smb + 17408);
    float* Ored = (float*)(smb + 34816);         // [64][132]
    float* redM = (float*)(smb + 178176);        // [2][64]
    float* redS = redM + 128;                    // [2][64]

    const uint32_t q_hb = sb, q_lb = sb + 17408;

    const int tid  = threadIdx.x;
    const int lane = tid & 31;
    const int wid  = tid >> 5;
    const int wni  = wid & 1;
    const int wm   = (wid >> 1) * 16;
    const int wn   = wni * 32;
    const int g    = lane >> 2;
    const int t4   = lane & 3;
    const int lb   = lane >> 3;
    const int lr   = lane & 7;

    #pragma unroll 1
    for (int item_i = 0; item_i < 2; item_i++) {
        const int j  = (item_i == 0) ? blockIdx.x : (255 - (int)blockIdx.x);
        const int qt = 63 - (j >> 2);
        const int b  = j & 3;
        const int m0 = qt * 64;
        const size_t bT = (size_t)b * TT;

        // prologue: prefetch KV tile 0 into stage 0
        {
            const uint32_t khb = sb + AKST(0), klb = khb + 17408;
            const uint32_t vhb = sb + AVST(0), vlb = vhb + 18432;
            #pragma unroll
            for (int it = 0; it < 4; it++) {
                int idx = tid + it * 256;
                int r   = idx >> 4;
                int c8  = (idx & 15) * 8;
                cp16(khb + (r * LDK + c8) * 2, &g_kh[(bT + r) * DD + c8]);
                cp16(klb + (r * LDK + c8) * 2, &g_kl[(bT + r) * DD + c8]);
            }
            #pragma unroll
            for (int it = 0; it < 4; it++) {
                int idx = tid + it * 256;
                int r   = idx >> 3;
                int c8  = (idx & 7) * 8;
                cp16(vhb + (r * LDV + c8) * 2, &g_vth[(size_t)r * MTOT + bT + c8]);
                cp16(vlb + (r * LDV + c8) * 2, &g_vtl[(size_t)r * MTOT + bT + c8]);
            }
            CP_COMMIT();
        }
        // load Q tile (normal loads, overlapped with cp.async above)
        #pragma unroll
        for (int it = 0; it < 4; it++) {
            int idx = tid + it * 256;
            int r   = idx >> 4;
            int c8  = (idx & 15) * 8;
            *reinterpret_cast<uint4*>(&Qh[r * LDK + c8]) =
                *reinterpret_cast<const uint4*>(&g_qh[(bT + m0 + r) * DD + c8]);
            *reinterpret_cast<uint4*>(&Ql[r * LDK + c8]) =
                *reinterpret_cast<const uint4*>(&g_ql[(bT + m0 + r) * DD + c8]);
        }

        float oacc[16][4];
        #pragma unroll
        for (int i = 0; i < 16; i++)
            #pragma unroll
            for (int c = 0; c < 4; c++) oacc[i][c] = 0.f;
        float m_run0 = -1e30f, m_run1 = -1e30f;
        float l_run0 = 0.f, l_run1 = 0.f;

        #pragma unroll 1
        for (int kt = 0; kt <= qt; kt++) {
            const int s = kt & 1;
            // prefetch kt+1 into other stage
            if (kt < qt) {
                const uint32_t khb = sb + AKST(s ^ 1), klb = khb + 17408;
                const uint32_t vhb = sb + AVST(s ^ 1), vlb = vhb + 18432;
                const size_t kvo = bT + (size_t)(kt + 1) * 64;
                #pragma unroll
                for (int it = 0; it < 4; it++) {
                    int idx = tid + it * 256;
                    int r   = idx >> 4;
                    int c8  = (idx & 15) * 8;
                    cp16(khb + (r * LDK + c8) * 2, &g_kh[(kvo + r) * DD + c8]);
                    cp16(klb + (r * LDK + c8) * 2, &g_kl[(kvo + r) * DD + c8]);
                }
                #pragma unroll
                for (int it = 0; it < 4; it++) {
                    int idx = tid + it * 256;
                    int r   = idx >> 3;
                    int c8  = (idx & 7) * 8;
                    cp16(vhb + (r * LDV + c8) * 2, &g_vth[(size_t)r * MTOT + kvo + c8]);
                    cp16(vlb + (r * LDV + c8) * 2, &g_vtl[(size_t)r * MTOT + kvo + c8]);
                }
                CP_COMMIT();
                CP_WAIT1();
            } else {
                CP_WAIT0();
            }
            __syncthreads();

            const uint32_t kh_b = sb + AKST(s), kl_b = kh_b + 17408;
            const uint32_t vh_b = sb + AVST(s), vl_b = vh_b + 18432;

            // ---- S = Q K^T (split, 3 terms): warp computes 16x32
            float sacc[4][4];
            #pragma unroll
            for (int i = 0; i < 4; i++)
                #pragma unroll
                for (int c = 0; c < 4; c++) sacc[i][c] = 0.f;

            #pragma unroll
            for (int d8 = 0; d8 < 8; d8++) {
                uint32_t qa[4], qla[4];
                {
                    uint32_t off = (uint32_t)((wm + (lb & 1) * 8 + lr) * LDK
                                              + d8 * 16 + (lb >> 1) * 8) * 2;
                    ldmatrix_x4(qa[0], qa[1], qa[2], qa[3], q_hb + off);
                    ldmatrix_x4(qla[0], qla[1], qla[2], qla[3], q_lb + off);
                }
                #pragma unroll
                for (int np = 0; np < 2; np++) {
                    uint32_t off = (uint32_t)((wn + np * 16 + (lb >> 1) * 8 + lr) * LDK
                                              + d8 * 16 + (lb & 1) * 8) * 2;
                    uint32_t h0, h1, h2, h3, l0, l1, l2, l3;
                    ldmatrix_x4(h0, h1, h2, h3, kh_b + off);
                    ldmatrix_x4(l0, l1, l2, l3, kl_b + off);
                    uint32_t bh0[2] = {h0, h1}, bh1[2] = {h2, h3};
                    uint32_t bl0[2] = {l0, l1}, bl1[2] = {l2, l3};
                    mma16816(sacc[2*np],   qa,  bh0);
                    mma16816(sacc[2*np],   qla, bh0);
                    mma16816(sacc[2*np],   qa,  bl0);
                    mma16816(sacc[2*np+1], qa,  bh1);
                    mma16816(sacc[2*np+1], qla, bh1);
                    mma16816(sacc[2*np+1], qa,  bl1);
                }
            }

            if (kt == qt) {
                const int r0 = wm + g, r1 = r0 + 8;
                #pragma unroll
                for (int nf = 0; nf < 4; nf++) {
                    int col = wn + nf * 8 + 2 * t4;
                    if (col     > r0) sacc[nf][0] = -1e30f;
                    if (col + 1 > r0) sacc[nf][1] = -1e30f;
                    if (col     > r1) sacc[nf][2] = -1e30f;
                    if (col + 1 > r1) sacc[nf][3] = -1e30f;
                }
            }

            float lm0 = -1e30f, lm1 = -1e30f;
            #pragma unroll
            for (int nf = 0; nf < 4; nf++) {
                lm0 = fmaxf(lm0, fmaxf(sacc[nf][0], sacc[nf][1]));
                lm1 = fmaxf(lm1, fmaxf(sacc[nf][2], sacc[nf][3]));
            }
            lm0 = fmaxf(lm0, __shfl_xor_sync(0xFFFFFFFFu, lm0, 1));
            lm0 = fmaxf(lm0, __shfl_xor_sync(0xFFFFFFFFu, lm0, 2));
            lm1 = fmaxf(lm1, __shfl_xor_sync(0xFFFFFFFFu, lm1, 1));
            lm1 = fmaxf(lm1, __shfl_xor_sync(0xFFFFFFFFu, lm1, 2));

            float ps0 = 0.f, ps1 = 0.f;
            #pragma unroll
            for (int nf = 0; nf < 4; nf++) {
                sacc[nf][0] = __expf(sacc[nf][0] - lm0);
                sacc[nf][1] = __expf(sacc[nf][1] - lm0);
                sacc[nf][2] = __expf(sacc[nf][2] - lm1);
                sacc[nf][3] = __expf(sacc[nf][3] - lm1);
                ps0 += sacc[nf][0] + sacc[nf][1];
                ps1 += sacc[nf][2] + sacc[nf][3];
            }
            ps0 += __shfl_xor_sync(0xFFFFFFFFu, ps0, 1);
            ps0 += __shfl_xor_sync(0xFFFFFFFFu, ps0, 2);
            ps1 += __shfl_xor_sync(0xFFFFFFFFu, ps1, 1);
            ps1 += __shfl_xor_sync(0xFFFFFFFFu, ps1, 2);

            if (t4 == 0) {
                redM[wni * 64 + wm + g]     = lm0;
                redM[wni * 64 + wm + g + 8] = lm1;
                redS[wni * 64 + wm + g]     = ps0;
                redS[wni * 64 + wm + g + 8] = ps1;
            }
            __syncthreads();

            const int r0 = wm + g, r1 = r0 + 8;
            float la0 = redM[r0],      lb0 = redM[64 + r0];
            float la1 = redM[r1],      lb1 = redM[64 + r1];
            float sa0 = redS[r0],      sb0 = redS[64 + r0];
            float sa1 = redS[r1],      sb1 = redS[64 + r1];
            float mn0 = fmaxf(m_run0, fmaxf(la0, lb0));
            float mn1 = fmaxf(m_run1, fmaxf(la1, lb1));
            float rs0 = sa0 * __expf(la0 - mn0) + sb0 * __expf(lb0 - mn0);
            float rs1 = sa1 * __expf(la1 - mn1) + sb1 * __expf(lb1 - mn1);
            float alpha0 = __expf(m_run0 - mn0);
            float alpha1 = __expf(m_run1 - mn1);
            l_run0 = l_run0 * alpha0 + rs0;
            l_run1 = l_run1 * alpha1 + rs1;
            m_run0 = mn0; m_run1 = mn1;
            float scl0 = __expf(lm0 - mn0);
            float scl1 = __expf(lm1 - mn1);

            #pragma unroll
            for (int nf = 0; nf < 16; nf++) {
                oacc[nf][0] *= alpha0; oacc[nf][1] *= alpha0;
                oacc[nf][2] *= alpha1; oacc[nf][3] *= alpha1;
            }
            #pragma unroll
            for (int nf = 0; nf < 4; nf++) {
                sacc[nf][0] *= scl0; sacc[nf][1] *= scl0;
                sacc[nf][2] *= scl1; sacc[nf][3] *= scl1;
            }

            // ---- PV
            #pragma unroll
            for (int ks2 = 0; ks2 < 2; ks2++) {
                uint32_t aPh[4], aPl[4];
                #pragma unroll
                for (int half = 0; half < 2; half++) {
                    const float* pc = sacc[2 * ks2 + half];
                    __nv_bfloat16 h0 = __float2bfloat16(pc[0]);
                    __nv_bfloat16 h1 = __float2bfloat16(pc[1]);
                    __nv_bfloat16 h2 = __float2bfloat16(pc[2]);
                    __nv_bfloat16 h3 = __float2bfloat16(pc[3]);
                    __nv_bfloat16 l0 = __float2bfloat16(pc[0] - __bfloat162float(h0));
                    __nv_bfloat16 l1 = __float2bfloat16(pc[1] - __bfloat162float(h1));
                    __nv_bfloat16 l2 = __float2bfloat16(pc[2] - __bfloat162float(h2));
                    __nv_bfloat16 l3 = __float2bfloat16(pc[3] - __bfloat162float(h3));
                    aPh[0 + 2 * half] = packh2(h0, h1);
                    aPh[1 + 2 * half] = packh2(h2, h3);
                    aPl[0 + 2 * half] = packh2(l0, l1);
                    aPl[1 + 2 * half] = packh2(l2, l3);
                }
                uint32_t Ah_[4] = {aPh[0], aPh[1], aPh[2], aPh[3]};
                uint32_t Al_[4] = {aPl[0], aPl[1], aPl[2], aPl[3]};
                #pragma unroll
                for (int nd = 0; nd < 8; nd++) {
                    uint32_t off = (uint32_t)((nd * 16 + (lb >> 1) * 8 + lr) * LDV
                                              + wn + ks2 * 16 + (lb & 1) * 8) * 2;
                    uint32_t h0, h1, h2, h3, l0, l1, l2, l3;
                    ldmatrix_x4(h0, h1, h2, h3, vh_b + off);
                    ldmatrix_x4(l0, l1, l2, l3, vl_b + off);
                    uint32_t bh0[2] = {h0, h1}, bh1[2] = {h2, h3};
                    uint32_t bl0[2] = {l0, l1}, bl1[2] = {l2, l3};
                    mma16816(oacc[2*nd],   Ah_, bh0);
                    mma16816(oacc[2*nd],   Al_, bh0);
                    mma16816(oacc[2*nd],   Ah_, bl0);
                    mma16816(oacc[2*nd+1], Ah_, bh1);
                    mma16816(oacc[2*nd+1], Al_, bh1);
                    mma16816(oacc[2*nd+1], Ah_, bl1);
                }
            }
            __syncthreads();
        }

        // ---- cross-warp O reduction + store
        const int r0 = wm + g, r1 = r0 + 8;
        if (wni == 1) {
            #pragma unroll
            for (int nf = 0; nf < 16; nf++) {
                int col = nf * 8 + 2 * t4;
                *reinterpret_cast<float2*>(&Ored[r0 * 132 + col]) =
                    make_float2(oacc[nf][0], oacc[nf][1]);
                *reinterpret_cast<float2*>(&Ored[r1 * 132 + col]) =
                    make_float2(oacc[nf][2], oacc[nf][3]);
            }
        }
        __syncthreads();
        if (wni == 0) {
            float inv0 = 1.0f / l_run0;
            float inv1 = 1.0f / l_run1;
            #pragma unroll
            for (int nf = 0; nf < 16; nf++) {
                int col = nf * 8 + 2 * t4;
                float2 p0 = *reinterpret_cast<float2*>(&Ored[r0 * 132 + col]);
                float2 p1 = *reinterpret_cast<float2*>(&Ored[r1 * 132 + col]);
                float2 o0 = make_float2((oacc[nf][0] + p0.x) * inv0,
                                        (oacc[nf][1] + p0.y) * inv0);
                float2 o1 = make_float2((oacc[nf][2] + p1.x) * inv1,
                                        (oacc[nf][3] + p1.y) * inv1);
                *reinterpret_cast<float2*>(&outp[(bT + m0 + r0) * DD + col]) = o0;
                *reinterpret_cast<float2*>(&outp[(bT + m0 + r1) * DD + col]) = o1;
            }
        }
        __syncthreads();
    }
}

// ---------------------------------------------------------------------------
extern "C" void kernel_launch(void* const* d_in, const int* in_sizes, int n_in,
                              void* d_out, int out_size)
{
    const float* x  = (const float*)d_in[0];
    const float* Wq = (const float*)d_in[1];
    const float* Wk = (const float*)d_in[2];
    const float* Wv = (const float*)d_in[3];
    float* out = (float*)d_out;
    (void)in_sizes; (void)n_in; (void)out_size;

    cudaFuncSetAttribute(prep_w_kernel,
                         cudaFuncAttributeMaxDynamicSharedMemorySize, PREP_SMEM);
    prep_w_kernel<<<dim3(16, 3), 256, PREP_SMEM>>>(Wq, Wk, Wv);

    cudaFuncSetAttribute(proj_mma_kernel,
                         cudaFuncAttributeMaxDynamicSharedMemorySize, PJ_SMEM);
    proj_mma_kernel<<<dim3(3, 128), 256, PJ_SMEM>>>(x);

    cudaFuncSetAttribute(attn_kernel,
                         cudaFuncAttributeMaxDynamicSharedMemorySize,
                         ATT_SMEM_BYTES);
    attn_kernel<<<128, 256, ATT_SMEM_BYTES>>>(out);
}

// round 9
// speedup vs baseline: 4.1717x; 1.0443x over previous
#include <cuda_runtime.h>
#include <cuda_bf16.h>
#include <cstdint>
#include <math.h>

#define BB 4
#define TT 4096
#define CC 2048
#define DD 128
#define MTOT (BB*TT)   // 16384

// ---------------------------------------------------------------------------
// Global scratch: projections stored as split bf16 (hi/lo)
// q,k: [m][d];  v: transposed [d][m]
// ---------------------------------------------------------------------------
__device__ __nv_bfloat16 g_qh[MTOT*DD];
__device__ __nv_bfloat16 g_ql[MTOT*DD];
__device__ __nv_bfloat16 g_kh[MTOT*DD];
__device__ __nv_bfloat16 g_kl[MTOT*DD];
__device__ __nv_bfloat16 g_vth[DD*MTOT];
__device__ __nv_bfloat16 g_vtl[DD*MTOT];
__device__ __nv_bfloat16 g_wt_hi[3][DD*CC];
__device__ __nv_bfloat16 g_wt_lo[3][DD*CC];

__device__ __forceinline__ uint32_t smem_u32(const void* p) {
    uint32_t a;
    asm("{ .reg .u64 t; cvta.to.shared.u64 t, %1; cvt.u32.u64 %0, t; }"
        : "=r"(a) : "l"(p));
    return a;
}
__device__ __forceinline__ void ldmatrix_x4(uint32_t& r0, uint32_t& r1,
                                            uint32_t& r2, uint32_t& r3,
                                            uint32_t addr) {
    asm volatile("ldmatrix.sync.aligned.m8n8.x4.shared.b16 {%0,%1,%2,%3}, [%4];"
                 : "=r"(r0), "=r"(r1), "=r"(r2), "=r"(r3) : "r"(addr));
}
__device__ __forceinline__ void mma16816(float* c, const uint32_t* a, const uint32_t* b) {
    asm volatile(
        "mma.sync.aligned.m16n8k16.row.col.f32.bf16.bf16.f32 "
        "{%0,%1,%2,%3}, {%4,%5,%6,%7}, {%8,%9}, {%0,%1,%2,%3};"
        : "+f"(c[0]), "+f"(c[1]), "+f"(c[2]), "+f"(c[3])
        : "r"(a[0]), "r"(a[1]), "r"(a[2]), "r"(a[3]), "r"(b[0]), "r"(b[1]));
}
__device__ __forceinline__ uint32_t packh2(__nv_bfloat16 a, __nv_bfloat16 b) {
    return ((uint32_t)__bfloat16_as_ushort(b) << 16) | __bfloat16_as_ushort(a);
}
__device__ __forceinline__ void cp16(uint32_t smem, const void* g) {
    asm volatile("cp.async.cg.shared.global [%0], [%1], 16;" :: "r"(smem), "l"(g));
}
#define CP_COMMIT() asm volatile("cp.async.commit_group;" ::: "memory")
#define CP_WAIT0() asm volatile("cp.async.wait_group 0;" ::: "memory")
#define CP_WAIT1() asm volatile("cp.async.wait_group 1;" ::: "memory")

// ---------------------------------------------------------------------------
// Kernel 0: split W (fp32 [K,128]) into bf16 hi/lo transposed [N,K].
// ---------------------------------------------------------------------------
#define LDP 132
#define PREP_SMEM (2 * 128 * LDP * 2)

__global__ __launch_bounds__(256) void prep_w_kernel(
    const float* __restrict__ Wq,
    const float* __restrict__ Wk,
    const float* __restrict__ Wv)
{
    extern __shared__ __nv_bfloat16 sp[];
    __nv_bfloat16* shh = sp;
    __nv_bfloat16* shl = sp + 128 * LDP;
    const int w  = blockIdx.y;
    const int k0 = blockIdx.x * 128;
    const float* W = (w == 0) ? Wq : (w == 1) ? Wk : Wv;
    const int tid = threadIdx.x;

    #pragma unroll
    for (int it = 0; it < 16; it++) {
        int idx = tid + it * 256;
        int r   = idx >> 5;
        int c4  = (idx & 31) * 4;
        float4 v = *reinterpret_cast<const float4*>(&W[(size_t)(k0 + r) * DD + c4]);
        __nv_bfloat16 h0 = __float2bfloat16(v.x), h1 = __float2bfloat16(v.y);
        __nv_bfloat16 h2 = __float2bfloat16(v.z), h3 = __float2bfloat16(v.w);
        __nv_bfloat16 l0 = __float2bfloat16(v.x - __bfloat162float(h0));
        __nv_bfloat16 l1 = __float2bfloat16(v.y - __bfloat162float(h1));
        __nv_bfloat16 l2 = __float2bfloat16(v.z - __bfloat162float(h2));
        __nv_bfloat16 l3 = __float2bfloat16(v.w - __bfloat162float(h3));
        *reinterpret_cast<uint2*>(&shh[r * LDP + c4]) =
            make_uint2(packh2(h0, h1), packh2(h2, h3));
        *reinterpret_cast<uint2*>(&shl[r * LDP + c4]) =
            make_uint2(packh2(l0, l1), packh2(l2, l3));
    }
    __syncthreads();

    const int nb = tid >> 3;
    const int kc = (tid & 7) * 16;
    #pragma unroll
    for (int rep = 0; rep < 4; rep++) {
        int n = rep * 32 + nb;
        ushort hbuf[16], lbuf[16];
        #pragma unroll
        for (int i = 0; i < 16; i++) {
            hbuf[i] = __bfloat16_as_ushort(shh[(kc + i) * LDP + n]);
            lbuf[i] = __bfloat16_as_ushort(shl[(kc + i) * LDP + n]);
        }
        __nv_bfloat16* dh = &g_wt_hi[w][(size_t)n * CC + k0 + kc];
        __nv_bfloat16* dl = &g_wt_lo[w][(size_t)n * CC + k0 + kc];
        *reinterpret_cast<uint4*>(dh)     = *reinterpret_cast<uint4*>(&hbuf[0]);
        *reinterpret_cast<uint4*>(dh + 8) = *reinterpret_cast<uint4*>(&hbuf[8]);
        *reinterpret_cast<uint4*>(dl)     = *reinterpret_cast<uint4*>(&lbuf[0]);
        *reinterpret_cast<uint4*>(dl + 8) = *reinterpret_cast<uint4*>(&lbuf[8]);
    }
}

// ---------------------------------------------------------------------------
// Kernel 1: projection, mma.sync bf16 split, 2-stage pipelined. (unchanged)
// ---------------------------------------------------------------------------
#define LDA 40
#define PJ_SMEM 81920

__global__ __launch_bounds__(256) void proj_mma_kernel(const float* __restrict__ x)
{
    extern __shared__ char psm[];
    const uint32_t sb = smem_u32(psm);

    const int tid  = threadIdx.x;
    const int lane = tid & 31;
    const int wid  = tid >> 5;
    const int wm   = (wid >> 1) * 32;
    const int wn   = (wid & 1) * 64;
    const int w    = blockIdx.x;
    const int m0   = blockIdx.y * 128;

    const __nv_bfloat16* __restrict__ wt_h = g_wt_hi[w];
    const __nv_bfloat16* __restrict__ wt_l = g_wt_lo[w];

    float acc[2][8][4];
    #pragma unroll
    for (int i = 0; i < 2; i++)
        #pragma unroll
        for (int j = 0; j < 8; j++)
            #pragma unroll
            for (int c = 0; c < 4; c++) acc[i][j][c] = 0.f;

    const int lb = lane >> 3;
    const int lr = lane & 7;

    float4 xv[4];
    #pragma unroll
    for (int it = 0; it < 4; it++) {
        int idx = tid + it * 256;
        int r   = idx >> 3;
        int c4  = (idx & 7) * 4;
        xv[it] = *reinterpret_cast<const float4*>(&x[(size_t)(m0 + r) * CC + c4]);
    }
    {
        uint32_t bh0 = sb + 40960;
        uint32_t bl0 = bh0 + 10240;
        #pragma unroll
        for (int it = 0; it < 2; it++) {
            int idx = tid + it * 256;
            int n   = idx >> 2;
            int k8  = (idx & 3) * 8;
            cp16(bh0 + (n * LDA + k8) * 2, &wt_h[(size_t)n * CC + k8]);
            cp16(bl0 + (n * LDA + k8) * 2, &wt_l[(size_t)n * CC + k8]);
        }
        CP_COMMIT();
    }

    for (int kc = 0; kc < 64; kc++) {
        const int s = kc & 1;
        __nv_bfloat16* Ah = (__nv_bfloat16*)(psm + s * 20480);
        __nv_bfloat16* Al = (__nv_bfloat16*)(psm + s * 20480 + 10240);
        const uint32_t ah_base = sb + s * 20480;
        const uint32_t al_base = ah_base + 10240;
        const uint32_t bh_base = sb + 40960 + s * 20480;
        const uint32_t bl_base = bh_base + 10240;

        #pragma unroll
        for (int it = 0; it < 4; it++) {
            int idx = tid + it * 256;
            int r   = idx >> 3;
            int c4  = (idx & 7) * 4;
            float4 v = xv[it];
            __nv_bfloat16 h0 = __float2bfloat16(v.x), h1 = __float2bfloat16(v.y);
            __nv_bfloat16 h2 = __float2bfloat16(v.z), h3 = __float2bfloat16(v.w);
            __nv_bfloat16 l0 = __float2bfloat16(v.x - __bfloat162float(h0));
            __nv_bfloat16 l1 = __float2bfloat16(v.y - __bfloat162float(h1));
            __nv_bfloat16 l2 = __float2bfloat16(v.z - __bfloat162float(h2));
            __nv_bfloat16 l3 = __float2bfloat16(v.w - __bfloat162float(h3));
            *reinterpret_cast<uint2*>(&Ah[r * LDA + c4]) =
                make_uint2(packh2(h0, h1), packh2(h2, h3));
            *reinterpret_cast<uint2*>(&Al[r * LDA + c4]) =
                make_uint2(packh2(l0, l1), packh2(l2, l3));
        }
        if (kc < 63) {
            const int k0n = (kc + 1) * 32;
            #pragma unroll
            for (int it = 0; it < 4; it++) {
                int idx = tid + it * 256;
                int r   = idx >> 3;
                int c4  = (idx & 7) * 4;
                xv[it] = *reinterpret_cast<const float4*>(
                    &x[(size_t)(m0 + r) * CC + k0n + c4]);
            }
            uint32_t bhn = sb + 40960 + (s ^ 1) * 20480;
            uint32_t bln = bhn + 10240;
            #pragma unroll
            for (int it = 0; it < 2; it++) {
                int idx = tid + it * 256;
                int n   = idx >> 2;
                int k8  = (idx & 3) * 8;
                cp16(bhn + (n * LDA + k8) * 2, &wt_h[(size_t)n * CC + k0n + k8]);
                cp16(bln + (n * LDA + k8) * 2, &wt_l[(size_t)n * CC + k0n + k8]);
            }
            CP_COMMIT();
            CP_WAIT1();
        } else {
            CP_WAIT0();
        }
        __syncthreads();

        #pragma unroll
        for (int ks = 0; ks < 32; ks += 16) {
            uint32_t ah[2][4], al[2][4];
            #pragma unroll
            for (int mf = 0; mf < 2; mf++) {
                uint32_t off = (uint32_t)((wm + mf * 16 + (lb & 1) * 8 + lr) * LDA
                                          + ks + (lb >> 1) * 8) * 2;
                ldmatrix_x4(ah[mf][0], ah[mf][1], ah[mf][2], ah[mf][3], ah_base + off);
                ldmatrix_x4(al[mf][0], al[mf][1], al[mf][2], al[mf][3], al_base + off);
            }
            uint32_t bh[8][2], bl[8][2];
            #pragma unroll
            for (int np = 0; np < 4; np++) {
                uint32_t off = (uint32_t)((wn + np * 16 + (lb >> 1) * 8 + lr) * LDA
                                          + ks + (lb & 1) * 8) * 2;
                uint32_t r0, r1, r2, r3;
                ldmatrix_x4(r0, r1, r2, r3, bh_base + off);
                bh[2*np][0] = r0; bh[2*np][1] = r1; bh[2*np+1][0] = r2; bh[2*np+1][1] = r3;
                ldmatrix_x4(r0, r1, r2, r3, bl_base + off);
                bl[2*np][0] = r0; bl[2*np][1] = r1; bl[2*np+1][0] = r2; bl[2*np+1][1] = r3;
            }
            #pragma unroll
            for (int mf = 0; mf < 2; mf++)
                #pragma unroll
                for (int nf = 0; nf < 8; nf++) {
                    mma16816(acc[mf][nf], ah[mf], bh[nf]);
                    mma16816(acc[mf][nf], al[mf], bh[nf]);
                    mma16816(acc[mf][nf], ah[mf], bl[nf]);
                }
        }
        __syncthreads();
    }

    const int g  = lane >> 2;
    const int t4 = lane & 3;
    const float qscale = 0.08838834764831845f;
    #pragma unroll
    for (int mf = 0; mf < 2; mf++)
        #pragma unroll
        for (int nf = 0; nf < 8; nf++) {
            int row0 = m0 + wm + mf * 16 + g;
            int col  = wn + nf * 8 + t4 * 2;
            float c0 = acc[mf][nf][0], c1 = acc[mf][nf][1];
            float c2 = acc[mf][nf][2], c3 = acc[mf][nf][3];
            if (w == 0) { c0 *= qscale; c1 *= qscale; c2 *= qscale; c3 *= qscale; }
            __nv_bfloat16 h0 = __float2bfloat16(c0), h1 = __float2bfloat16(c1);
            __nv_bfloat16 h2 = __float2bfloat16(c2), h3 = __float2bfloat16(c3);
            __nv_bfloat16 l0 = __float2bfloat16(c0 - __bfloat162float(h0));
            __nv_bfloat16 l1 = __float2bfloat16(c1 - __bfloat162float(h1));
            __nv_bfloat16 l2 = __float2bfloat16(c2 - __bfloat162float(h2));
            __nv_bfloat16 l3 = __float2bfloat16(c3 - __bfloat162float(h3));
            if (w == 2) {
                g_vth[(size_t)col * MTOT + row0]           = h0;
                g_vth[(size_t)(col + 1) * MTOT + row0]     = h1;
                g_vth[(size_t)col * MTOT + row0 + 8]       = h2;
                g_vth[(size_t)(col + 1) * MTOT + row0 + 8] = h3;
                g_vtl[(size_t)col * MTOT + row0]           = l0;
                g_vtl[(size_t)(col + 1) * MTOT + row0]     = l1;
                g_vtl[(size_t)col * MTOT + row0 + 8]       = l2;
                g_vtl[(size_t)(col + 1) * MTOT + row0 + 8] = l3;
            } else {
                __nv_bfloat16* oh = (w == 0) ? g_qh : g_kh;
                __nv_bfloat16* ol = (w == 0) ? g_ql : g_kl;
                *reinterpret_cast<uint32_t*>(&oh[(size_t)row0 * DD + col])       = packh2(h0, h1);
                *reinterpret_cast<uint32_t*>(&oh[(size_t)(row0 + 8) * DD + col]) = packh2(h2, h3);
                *reinterpret_cast<uint32_t*>(&ol[(size_t)row0 * DD + col])       = packh2(l0, l1);
                *reinterpret_cast<uint32_t*>(&ol[(size_t)(row0 + 8) * DD + col]) = packh2(l2, l3);
            }
        }
}

// ---------------------------------------------------------------------------
// Kernel 2: causal flash attention. Split-KV per n-warp: no per-tile
// cross-warp stat merge; single end-of-item merge. Q fragments in registers.
// ---------------------------------------------------------------------------
#define LDK 136
#define LDV 72
#define AKST(s) (34816 + (s) * 34816)
#define AVST(s) (104448 + (s) * 36864)
#define ATT_SMEM_BYTES 179200

__global__ __launch_bounds__(256) void attn_kernel(float* __restrict__ outp)
{
    extern __shared__ char smb[];
    const uint32_t sb = smem_u32(smb);
    __nv_bfloat16* Qh = (__nv_bfloat16*)(smb);
    __nv_bfloat16* Ql = (__nv_bfloat16*)(smb + 17408);
    float* Ored = (float*)(smb + 34816);         // [64][132] (overlaps K stage0)
    float* redM = (float*)(smb + 178176);        // [64]
    float* redS = redM + 64;                     // [64]

    const uint32_t q_hb = sb, q_lb = sb + 17408;

    const int tid  = threadIdx.x;
    const int lane = tid & 31;
    const int wid  = tid >> 5;
    const int wni  = wid & 1;
    const int wm   = (wid >> 1) * 16;
    const int wn   = wni * 32;
    const int g    = lane >> 2;
    const int t4   = lane & 3;
    const int lb   = lane >> 3;
    const int lr   = lane & 7;

    #pragma unroll 1
    for (int item_i = 0; item_i < 2; item_i++) {
        const int j  = (item_i == 0) ? blockIdx.x : (255 - (int)blockIdx.x);
        const int qt = 63 - (j >> 2);
        const int b  = j & 3;
        const int m0 = qt * 64;
        const size_t bT = (size_t)b * TT;

        // prologue: prefetch KV tile 0 into stage 0
        {
            const uint32_t khb = sb + AKST(0), klb = khb + 17408;
            const uint32_t vhb = sb + AVST(0), vlb = vhb + 18432;
            #pragma unroll
            for (int it = 0; it < 4; it++) {
                int idx = tid + it * 256;
                int r   = idx >> 4;
                int c8  = (idx & 15) * 8;
                cp16(khb + (r * LDK + c8) * 2, &g_kh[(bT + r) * DD + c8]);
                cp16(klb + (r * LDK + c8) * 2, &g_kl[(bT + r) * DD + c8]);
            }
            #pragma unroll
            for (int it = 0; it < 4; it++) {
                int idx = tid + it * 256;
                int r   = idx >> 3;
                int c8  = (idx & 7) * 8;
                cp16(vhb + (r * LDV + c8) * 2, &g_vth[(size_t)r * MTOT + bT + c8]);
                cp16(vlb + (r * LDV + c8) * 2, &g_vtl[(size_t)r * MTOT + bT + c8]);
            }
            CP_COMMIT();
        }
        // load Q tile into smem
        #pragma unroll
        for (int it = 0; it < 4; it++) {
            int idx = tid + it * 256;
            int r   = idx >> 4;
            int c8  = (idx & 15) * 8;
            *reinterpret_cast<uint4*>(&Qh[r * LDK + c8]) =
                *reinterpret_cast<const uint4*>(&g_qh[(bT + m0 + r) * DD + c8]);
            *reinterpret_cast<uint4*>(&Ql[r * LDK + c8]) =
                *reinterpret_cast<const uint4*>(&g_ql[(bT + m0 + r) * DD + c8]);
        }
        __syncthreads();

        // hoist Q fragments to registers (reused across all KV tiles)
        uint32_t qfh[8][4], qfl[8][4];
        #pragma unroll
        for (int d8 = 0; d8 < 8; d8++) {
            uint32_t off = (uint32_t)((wm + (lb & 1) * 8 + lr) * LDK
                                      + d8 * 16 + (lb >> 1) * 8) * 2;
            ldmatrix_x4(qfh[d8][0], qfh[d8][1], qfh[d8][2], qfh[d8][3], q_hb + off);
            ldmatrix_x4(qfl[d8][0], qfl[d8][1], qfl[d8][2], qfl[d8][3], q_lb + off);
        }

        float oacc[16][4];
        #pragma unroll
        for (int i = 0; i < 16; i++)
            #pragma unroll
            for (int c = 0; c < 4; c++) oacc[i][c] = 0.f;
        float m_run0 = -1e30f, m_run1 = -1e30f;
        float l_run0 = 0.f, l_run1 = 0.f;

        #pragma unroll 1
        for (int kt = 0; kt <= qt; kt++) {
            const int s = kt & 1;
            if (kt < qt) {
                const uint32_t khb = sb + AKST(s ^ 1), klb = khb + 17408;
                const uint32_t vhb = sb + AVST(s ^ 1), vlb = vhb + 18432;
                const size_t kvo = bT + (size_t)(kt + 1) * 64;
                #pragma unroll
                for (int it = 0; it < 4; it++) {
                    int idx = tid + it * 256;
                    int r   = idx >> 4;
                    int c8  = (idx & 15) * 8;
                    cp16(khb + (r * LDK + c8) * 2, &g_kh[(kvo + r) * DD + c8]);
                    cp16(klb + (r * LDK + c8) * 2, &g_kl[(kvo + r) * DD + c8]);
                }
                #pragma unroll
                for (int it = 0; it < 4; it++) {
                    int idx = tid + it * 256;
                    int r   = idx >> 3;
                    int c8  = (idx & 7) * 8;
                    cp16(vhb + (r * LDV + c8) * 2, &g_vth[(size_t)r * MTOT + kvo + c8]);
                    cp16(vlb + (r * LDV + c8) * 2, &g_vtl[(size_t)r * MTOT + kvo + c8]);
                }
                CP_COMMIT();
                CP_WAIT1();
            } else {
                CP_WAIT0();
            }
            __syncthreads();

            const uint32_t kh_b = sb + AKST(s), kl_b = kh_b + 17408;
            const uint32_t vh_b = sb + AVST(s), vl_b = vh_b + 18432;

            // ---- S = Q K^T (split, 3 terms): warp computes 16x32
            float sacc[4][4];
            #pragma unroll
            for (int i = 0; i < 4; i++)
                #pragma unroll
                for (int c = 0; c < 4; c++) sacc[i][c] = 0.f;

            #pragma unroll
            for (int d8 = 0; d8 < 8; d8++) {
                #pragma unroll
                for (int np = 0; np < 2; np++) {
                    uint32_t off = (uint32_t)((wn + np * 16 + (lb >> 1) * 8 + lr) * LDK
                                              + d8 * 16 + (lb & 1) * 8) * 2;
                    uint32_t h0, h1, h2, h3, l0, l1, l2, l3;
                    ldmatrix_x4(h0, h1, h2, h3, kh_b + off);
                    ldmatrix_x4(l0, l1, l2, l3, kl_b + off);
                    uint32_t bh0[2] = {h0, h1}, bh1[2] = {h2, h3};
                    uint32_t bl0[2] = {l0, l1}, bl1[2] = {l2, l3};
                    mma16816(sacc[2*np],   qfh[d8], bh0);
                    mma16816(sacc[2*np],   qfl[d8], bh0);
                    mma16816(sacc[2*np],   qfh[d8], bl0);
                    mma16816(sacc[2*np+1], qfh[d8], bh1);
                    mma16816(sacc[2*np+1], qfl[d8], bh1);
                    mma16816(sacc[2*np+1], qfh[d8], bl1);
                }
            }

            if (kt == qt) {
                const int r0 = wm + g, r1 = r0 + 8;
                #pragma unroll
                for (int nf = 0; nf < 4; nf++) {
                    int col = wn + nf * 8 + 2 * t4;
                    if (col     > r0) sacc[nf][0] = -1e30f;
                    if (col + 1 > r0) sacc[nf][1] = -1e30f;
                    if (col     > r1) sacc[nf][2] = -1e30f;
                    if (col + 1 > r1) sacc[nf][3] = -1e30f;
                }
            }

            // ---- per-warp online softmax over this warp's 32 keys
            float lm0 = -1e30f, lm1 = -1e30f;
            #pragma unroll
            for (int nf = 0; nf < 4; nf++) {
                lm0 = fmaxf(lm0, fmaxf(sacc[nf][0], sacc[nf][1]));
                lm1 = fmaxf(lm1, fmaxf(sacc[nf][2], sacc[nf][3]));
            }
            lm0 = fmaxf(lm0, __shfl_xor_sync(0xFFFFFFFFu, lm0, 1));
            lm0 = fmaxf(lm0, __shfl_xor_sync(0xFFFFFFFFu, lm0, 2));
            lm1 = fmaxf(lm1, __shfl_xor_sync(0xFFFFFFFFu, lm1, 1));
            lm1 = fmaxf(lm1, __shfl_xor_sync(0xFFFFFFFFu, lm1, 2));

            float mn0 = fmaxf(m_run0, lm0);
            float mn1 = fmaxf(m_run1, lm1);
            float alpha0 = __expf(m_run0 - mn0);
            float alpha1 = __expf(m_run1 - mn1);

            float ps0 = 0.f, ps1 = 0.f;
            #pragma unroll
            for (int nf = 0; nf < 4; nf++) {
                sacc[nf][0] = __expf(sacc[nf][0] - mn0);
                sacc[nf][1] = __expf(sacc[nf][1] - mn0);
                sacc[nf][2] = __expf(sacc[nf][2] - mn1);
                sacc[nf][3] = __expf(sacc[nf][3] - mn1);
                ps0 += sacc[nf][0] + sacc[nf][1];
                ps1 += sacc[nf][2] + sacc[nf][3];
            }
            ps0 += __shfl_xor_sync(0xFFFFFFFFu, ps0, 1);
            ps0 += __shfl_xor_sync(0xFFFFFFFFu, ps0, 2);
            ps1 += __shfl_xor_sync(0xFFFFFFFFu, ps1, 1);
            ps1 += __shfl_xor_sync(0xFFFFFFFFu, ps1, 2);

            l_run0 = l_run0 * alpha0 + ps0;
            l_run1 = l_run1 * alpha1 + ps1;
            m_run0 = mn0; m_run1 = mn1;

            #pragma unroll
            for (int nf = 0; nf < 16; nf++) {
                oacc[nf][0] *= alpha0; oacc[nf][1] *= alpha0;
                oacc[nf][2] *= alpha1; oacc[nf][3] *= alpha1;
            }

            // ---- PV (split, 3 terms)
            #pragma unroll
            for (int ks2 = 0; ks2 < 2; ks2++) {
                uint32_t aPh[4], aPl[4];
                #pragma unroll
                for (int half = 0; half < 2; half++) {
                    const float* pc = sacc[2 * ks2 + half];
                    __nv_bfloat16 h0 = __float2bfloat16(pc[0]);
                    __nv_bfloat16 h1 = __float2bfloat16(pc[1]);
                    __nv_bfloat16 h2 = __float2bfloat16(pc[2]);
                    __nv_bfloat16 h3 = __float2bfloat16(pc[3]);
                    __nv_bfloat16 l0 = __float2bfloat16(pc[0] - __bfloat162float(h0));
                    __nv_bfloat16 l1 = __float2bfloat16(pc[1] - __bfloat162float(h1));
                    __nv_bfloat16 l2 = __float2bfloat16(pc[2] - __bfloat162float(h2));
                    __nv_bfloat16 l3 = __float2bfloat16(pc[3] - __bfloat162float(h3));
                    aPh[0 + 2 * half] = packh2(h0, h1);
                    aPh[1 + 2 * half] = packh2(h2, h3);
                    aPl[0 + 2 * half] = packh2(l0, l1);
                    aPl[1 + 2 * half] = packh2(l2, l3);
                }
                #pragma unroll
                for (int nd = 0; nd < 8; nd++) {
                    uint32_t off = (uint32_t)((nd * 16 + (lb >> 1) * 8 + lr) * LDV
                                              + wn + ks2 * 16 + (lb & 1) * 8) * 2;
                    uint32_t h0, h1, h2, h3, l0, l1, l2, l3;
                    ldmatrix_x4(h0, h1, h2, h3, vh_b + off);
                    ldmatrix_x4(l0, l1, l2, l3, vl_b + off);
                    uint32_t bh0[2] = {h0, h1}, bh1[2] = {h2, h3};
                    uint32_t bl0[2] = {l0, l1}, bl1[2] = {l2, l3};
                    mma16816(oacc[2*nd],   aPh, bh0);
                    mma16816(oacc[2*nd],   aPl, bh0);
                    mma16816(oacc[2*nd],   aPh, bl0);
                    mma16816(oacc[2*nd+1], aPh, bh1);
                    mma16816(oacc[2*nd+1], aPl, bh1);
                    mma16816(oacc[2*nd+1], aPh, bl1);
                }
            }
            __syncthreads();   // protect stage before overwrite
        }

        // ---- end-of-item merge of the two split-KV halves + store
        const int r0 = wm + g, r1 = r0 + 8;
        if (wni == 1) {
            if (t4 == 0) {
                redM[r0] = m_run0; redM[r1] = m_run1;
                redS[r0] = l_run0; redS[r1] = l_run1;
            }
            #pragma unroll
            for (int nf = 0; nf < 16; nf++) {
                int col = nf * 8 + 2 * t4;
                *reinterpret_cast<float2*>(&Ored[r0 * 132 + col]) =
                    make_float2(oacc[nf][0], oacc[nf][1]);
                *reinterpret_cast<float2*>(&Ored[r1 * 132 + col]) =
                    make_float2(oacc[nf][2], oacc[nf][3]);
            }
        }
        __syncthreads();
        if (wni == 0) {
            float mb0 = redM[r0], mb1 = redM[r1];
            float lb0 = redS[r0], lb1 = redS[r1];
            float mm0 = fmaxf(m_run0, mb0);
            float mm1 = fmaxf(m_run1, mb1);
            float ca0 = __expf(m_run0 - mm0), cb0 = __expf(mb0 - mm0);
            float ca1 = __expf(m_run1 - mm1), cb1 = __expf(mb1 - mm1);
            float inv0 = 1.0f / (l_run0 * ca0 + lb0 * cb0);
            float inv1 = 1.0f / (l_run1 * ca1 + lb1 * cb1);
            #pragma unroll
            for (int nf = 0; nf < 16; nf++) {
                int col = nf * 8 + 2 * t4;
                float2 p0 = *reinterpret_cast<float2*>(&Ored[r0 * 132 + col]);
                float2 p1 = *reinterpret_cast<float2*>(&Ored[r1 * 132 + col]);
                float2 o0 = make_float2((oacc[nf][0] * ca0 + p0.x * cb0) * inv0,
                                        (oacc[nf][1] * ca0 + p0.y * cb0) * inv0);
                float2 o1 = make_float2((oacc[nf][2] * ca1 + p1.x * cb1) * inv1,
                                        (oacc[nf][3] * ca1 + p1.y * cb1) * inv1);
                *reinterpret_cast<float2*>(&outp[(bT + m0 + r0) * DD + col]) = o0;
                *reinterpret_cast<float2*>(&outp[(bT + m0 + r1) * DD + col]) = o1;
            }
        }
        __syncthreads();
    }
}

// ---------------------------------------------------------------------------
extern "C" void kernel_launch(void* const* d_in, const int* in_sizes, int n_in,
                              void* d_out, int out_size)
{
    const float* x  = (const float*)d_in[0];
    const float* Wq = (const float*)d_in[1];
    const float* Wk = (const float*)d_in[2];
    const float* Wv = (const float*)d_in[3];
    float* out = (float*)d_out;
    (void)in_sizes; (void)n_in; (void)out_size;

    cudaFuncSetAttribute(prep_w_kernel,
                         cudaFuncAttributeMaxDynamicSharedMemorySize, PREP_SMEM);
    prep_w_kernel<<<dim3(16, 3), 256, PREP_SMEM>>>(Wq, Wk, Wv);

    cudaFuncSetAttribute(proj_mma_kernel,
                         cudaFuncAttributeMaxDynamicSharedMemorySize, PJ_SMEM);
    proj_mma_kernel<<<dim3(3, 128), 256, PJ_SMEM>>>(x);

    cudaFuncSetAttribute(attn_kernel,
                         cudaFuncAttributeMaxDynamicSharedMemorySize,
                         ATT_SMEM_BYTES);
    attn_kernel<<<128, 256, ATT_SMEM_BYTES>>>(out);
}

// round 14
// speedup vs baseline: 4.2415x; 1.0167x over previous
#include <cuda_runtime.h>
#include <cuda_bf16.h>
#include <cstdint>
#include <math.h>

#define BB 4
#define TT 4096
#define CC 2048
#define DD 128
#define MTOT (BB*TT)   // 16384

// ---------------------------------------------------------------------------
// Global scratch:
//  q, k : fp32 (tf32-pre-rounded; q pre-scaled)  [m][d]
//  v    : split bf16 hi/lo, transposed [d][m]
// ---------------------------------------------------------------------------
__device__ float g_qf[MTOT*DD];
__device__ float g_kf[MTOT*DD];
__device__ __nv_bfloat16 g_vth[DD*MTOT];
__device__ __nv_bfloat16 g_vtl[DD*MTOT];
__device__ __nv_bfloat16 g_wt_hi[3][DD*CC];
__device__ __nv_bfloat16 g_wt_lo[3][DD*CC];

__device__ __forceinline__ uint32_t smem_u32(const void* p) {
    uint32_t a;
    asm("{ .reg .u64 t; cvta.to.shared.u64 t, %1; cvt.u32.u64 %0, t; }"
        : "=r"(a) : "l"(p));
    return a;
}
__device__ __forceinline__ void ldmatrix_x4(uint32_t& r0, uint32_t& r1,
                                            uint32_t& r2, uint32_t& r3,
                                            uint32_t addr) {
    asm volatile("ldmatrix.sync.aligned.m8n8.x4.shared.b16 {%0,%1,%2,%3}, [%4];"
                 : "=r"(r0), "=r"(r1), "=r"(r2), "=r"(r3) : "r"(addr));
}
__device__ __forceinline__ void mma16816(float* c, const uint32_t* a, const uint32_t* b) {
    asm volatile(
        "mma.sync.aligned.m16n8k16.row.col.f32.bf16.bf16.f32 "
        "{%0,%1,%2,%3}, {%4,%5,%6,%7}, {%8,%9}, {%0,%1,%2,%3};"
        : "+f"(c[0]), "+f"(c[1]), "+f"(c[2]), "+f"(c[3])
        : "r"(a[0]), "r"(a[1]), "r"(a[2]), "r"(a[3]), "r"(b[0]), "r"(b[1]));
}
__device__ __forceinline__ void mma_tf32(float* c, const uint32_t* a,
                                         uint32_t b0, uint32_t b1) {
    asm volatile(
        "mma.sync.aligned.m16n8k8.row.col.f32.tf32.tf32.f32 "
        "{%0,%1,%2,%3}, {%4,%5,%6,%7}, {%8,%9}, {%0,%1,%2,%3};"
        : "+f"(c[0]), "+f"(c[1]), "+f"(c[2]), "+f"(c[3])
        : "r"(a[0]), "r"(a[1]), "r"(a[2]), "r"(a[3]), "r"(b0), "r"(b1));
}
__device__ __forceinline__ uint32_t f2tf32(float x) {
    uint32_t r;
    asm("cvt.rna.tf32.f32 %0, %1;" : "=r"(r) : "f"(x));
    return r;
}
__device__ __forceinline__ uint32_t packh2(__nv_bfloat16 a, __nv_bfloat16 b) {
    return ((uint32_t)__bfloat16_as_ushort(b) << 16) | __bfloat16_as_ushort(a);
}
__device__ __forceinline__ void cp16(uint32_t smem, const void* g) {
    asm volatile("cp.async.cg.shared.global [%0], [%1], 16;" :: "r"(smem), "l"(g));
}
#define CP_COMMIT() asm volatile("cp.async.commit_group;" ::: "memory")
#define CP_WAIT0() asm volatile("cp.async.wait_group 0;" ::: "memory")
#define CP_WAIT1() asm volatile("cp.async.wait_group 1;" ::: "memory")

// ---------------------------------------------------------------------------
// Kernel 0: split W (fp32 [K,128]) into bf16 hi/lo transposed [N,K].
// ---------------------------------------------------------------------------
#define LDP 132
#define PREP_SMEM (2 * 128 * LDP * 2)

__global__ __launch_bounds__(256) void prep_w_kernel(
    const float* __restrict__ Wq,
    const float* __restrict__ Wk,
    const float* __restrict__ Wv)
{
    extern __shared__ __nv_bfloat16 sp[];
    __nv_bfloat16* shh = sp;
    __nv_bfloat16* shl = sp + 128 * LDP;
    const int w  = blockIdx.y;
    const int k0 = blockIdx.x * 128;
    const float* W = (w == 0) ? Wq : (w == 1) ? Wk : Wv;
    const int tid = threadIdx.x;

    #pragma unroll
    for (int it = 0; it < 16; it++) {
        int idx = tid + it * 256;
        int r   = idx >> 5;
        int c4  = (idx & 31) * 4;
        float4 v = *reinterpret_cast<const float4*>(&W[(size_t)(k0 + r) * DD + c4]);
        __nv_bfloat16 h0 = __float2bfloat16(v.x), h1 = __float2bfloat16(v.y);
        __nv_bfloat16 h2 = __float2bfloat16(v.z), h3 = __float2bfloat16(v.w);
        __nv_bfloat16 l0 = __float2bfloat16(v.x - __bfloat162float(h0));
        __nv_bfloat16 l1 = __float2bfloat16(v.y - __bfloat162float(h1));
        __nv_bfloat16 l2 = __float2bfloat16(v.z - __bfloat162float(h2));
        __nv_bfloat16 l3 = __float2bfloat16(v.w - __bfloat162float(h3));
        *reinterpret_cast<uint2*>(&shh[r * LDP + c4]) =
            make_uint2(packh2(h0, h1), packh2(h2, h3));
        *reinterpret_cast<uint2*>(&shl[r * LDP + c4]) =
            make_uint2(packh2(l0, l1), packh2(l2, l3));
    }
    __syncthreads();

    const int nb = tid >> 3;
    const int kc = (tid & 7) * 16;
    #pragma unroll
    for (int rep = 0; rep < 4; rep++) {
        int n = rep * 32 + nb;
        ushort hbuf[16], lbuf[16];
        #pragma unroll
        for (int i = 0; i < 16; i++) {
            hbuf[i] = __bfloat16_as_ushort(shh[(kc + i) * LDP + n]);
            lbuf[i] = __bfloat16_as_ushort(shl[(kc + i) * LDP + n]);
        }
        __nv_bfloat16* dh = &g_wt_hi[w][(size_t)n * CC + k0 + kc];
        __nv_bfloat16* dl = &g_wt_lo[w][(size_t)n * CC + k0 + kc];
        *reinterpret_cast<uint4*>(dh)     = *reinterpret_cast<uint4*>(&hbuf[0]);
        *reinterpret_cast<uint4*>(dh + 8) = *reinterpret_cast<uint4*>(&hbuf[8]);
        *reinterpret_cast<uint4*>(dl)     = *reinterpret_cast<uint4*>(&lbuf[0]);
        *reinterpret_cast<uint4*>(dl + 8) = *reinterpret_cast<uint4*>(&lbuf[8]);
    }
}

// ---------------------------------------------------------------------------
// Kernel 1: projection, mma.sync bf16 split, 2-stage pipelined.
// Epilogue: q,k -> tf32-rounded fp32 (q scaled); v -> bf16 hi/lo transposed.
// ---------------------------------------------------------------------------
#define LDA 40
#define PJ_SMEM 81920

__global__ __launch_bounds__(256) void proj_mma_kernel(const float* __restrict__ x)
{
    extern __shared__ char psm[];
    const uint32_t sb = smem_u32(psm);

    const int tid  = threadIdx.x;
    const int lane = tid & 31;
    const int wid  = tid >> 5;
    const int wm   = (wid >> 1) * 32;
    const int wn   = (wid & 1) * 64;
    const int w    = blockIdx.x;
    const int m0   = blockIdx.y * 128;

    const __nv_bfloat16* __restrict__ wt_h = g_wt_hi[w];
    const __nv_bfloat16* __restrict__ wt_l = g_wt_lo[w];

    float acc[2][8][4];
    #pragma unroll
    for (int i = 0; i < 2; i++)
        #pragma unroll
        for (int j = 0; j < 8; j++)
            #pragma unroll
            for (int c = 0; c < 4; c++) acc[i][j][c] = 0.f;

    const int lb = lane >> 3;
    const int lr = lane & 7;

    float4 xv[4];
    #pragma unroll
    for (int it = 0; it < 4; it++) {
        int idx = tid + it * 256;
        int r   = idx >> 3;
        int c4  = (idx & 7) * 4;
        xv[it] = *reinterpret_cast<const float4*>(&x[(size_t)(m0 + r) * CC + c4]);
    }
    {
        uint32_t bh0 = sb + 40960;
        uint32_t bl0 = bh0 + 10240;
        #pragma unroll
        for (int it = 0; it < 2; it++) {
            int idx = tid + it * 256;
            int n   = idx >> 2;
            int k8  = (idx & 3) * 8;
            cp16(bh0 + (n * LDA + k8) * 2, &wt_h[(size_t)n * CC + k8]);
            cp16(bl0 + (n * LDA + k8) * 2, &wt_l[(size_t)n * CC + k8]);
        }
        CP_COMMIT();
    }

    for (int kc = 0; kc < 64; kc++) {
        const int s = kc & 1;
        __nv_bfloat16* Ah = (__nv_bfloat16*)(psm + s * 20480);
        __nv_bfloat16* Al = (__nv_bfloat16*)(psm + s * 20480 + 10240);
        const uint32_t ah_base = sb + s * 20480;
        const uint32_t al_base = ah_base + 10240;
        const uint32_t bh_base = sb + 40960 + s * 20480;
        const uint32_t bl_base = bh_base + 10240;

        #pragma unroll
        for (int it = 0; it < 4; it++) {
            int idx = tid + it * 256;
            int r   = idx >> 3;
            int c4  = (idx & 7) * 4;
            float4 v = xv[it];
            __nv_bfloat16 h0 = __float2bfloat16(v.x), h1 = __float2bfloat16(v.y);
            __nv_bfloat16 h2 = __float2bfloat16(v.z), h3 = __float2bfloat16(v.w);
            __nv_bfloat16 l0 = __float2bfloat16(v.x - __bfloat162float(h0));
            __nv_bfloat16 l1 = __float2bfloat16(v.y - __bfloat162float(h1));
            __nv_bfloat16 l2 = __float2bfloat16(v.z - __bfloat162float(h2));
            __nv_bfloat16 l3 = __float2bfloat16(v.w - __bfloat162float(h3));
            *reinterpret_cast<uint2*>(&Ah[r * LDA + c4]) =
                make_uint2(packh2(h0, h1), packh2(h2, h3));
            *reinterpret_cast<uint2*>(&Al[r * LDA + c4]) =
                make_uint2(packh2(l0, l1), packh2(l2, l3));
        }
        if (kc < 63) {
            const int k0n = (kc + 1) * 32;
            #pragma unroll
            for (int it = 0; it < 4; it++) {
                int idx = tid + it * 256;
                int r   = idx >> 3;
                int c4  = (idx & 7) * 4;
                xv[it] = *reinterpret_cast<const float4*>(
                    &x[(size_t)(m0 + r) * CC + k0n + c4]);
            }
            uint32_t bhn = sb + 40960 + (s ^ 1) * 20480;
            uint32_t bln = bhn + 10240;
            #pragma unroll
            for (int it = 0; it < 2; it++) {
                int idx = tid + it * 256;
                int n   = idx >> 2;
                int k8  = (idx & 3) * 8;
                cp16(bhn + (n * LDA + k8) * 2, &wt_h[(size_t)n * CC + k0n + k8]);
                cp16(bln + (n * LDA + k8) * 2, &wt_l[(size_t)n * CC + k0n + k8]);
            }
            CP_COMMIT();
            CP_WAIT1();
        } else {
            CP_WAIT0();
        }
        __syncthreads();

        #pragma unroll
        for (int ks = 0; ks < 32; ks += 16) {
            uint32_t ah[2][4], al[2][4];
            #pragma unroll
            for (int mf = 0; mf < 2; mf++) {
                uint32_t off = (uint32_t)((wm + mf * 16 + (lb & 1) * 8 + lr) * LDA
                                          + ks + (lb >> 1) * 8) * 2;
                ldmatrix_x4(ah[mf][0], ah[mf][1], ah[mf][2], ah[mf][3], ah_base + off);
                ldmatrix_x4(al[mf][0], al[mf][1], al[mf][2], al[mf][3], al_base + off);
            }
            uint32_t bh[8][2], bl[8][2];
            #pragma unroll
            for (int np = 0; np < 4; np++) {
                uint32_t off = (uint32_t)((wn + np * 16 + (lb >> 1) * 8 + lr) * LDA
                                          + ks + (lb & 1) * 8) * 2;
                uint32_t r0, r1, r2, r3;
                ldmatrix_x4(r0, r1, r2, r3, bh_base + off);
                bh[2*np][0] = r0; bh[2*np][1] = r1; bh[2*np+1][0] = r2; bh[2*np+1][1] = r3;
                ldmatrix_x4(r0, r1, r2, r3, bl_base + off);
                bl[2*np][0] = r0; bl[2*np][1] = r1; bl[2*np+1][0] = r2; bl[2*np+1][1] = r3;
            }
            #pragma unroll
            for (int mf = 0; mf < 2; mf++)
                #pragma unroll
                for (int nf = 0; nf < 8; nf++) {
                    mma16816(acc[mf][nf], ah[mf], bh[nf]);
                    mma16816(acc[mf][nf], al[mf], bh[nf]);
                    mma16816(acc[mf][nf], ah[mf], bl[nf]);
                }
        }
        __syncthreads();
    }

    const int g  = lane >> 2;
    const int t4 = lane & 3;
    const float qscale = 0.08838834764831845f;
    #pragma unroll
    for (int mf = 0; mf < 2; mf++)
        #pragma unroll
        for (int nf = 0; nf < 8; nf++) {
            int row0 = m0 + wm + mf * 16 + g;
            int col  = wn + nf * 8 + t4 * 2;
            float c0 = acc[mf][nf][0], c1 = acc[mf][nf][1];
            float c2 = acc[mf][nf][2], c3 = acc[mf][nf][3];
            if (w == 2) {
                __nv_bfloat16 h0 = __float2bfloat16(c0), h1 = __float2bfloat16(c1);
                __nv_bfloat16 h2 = __float2bfloat16(c2), h3 = __float2bfloat16(c3);
                __nv_bfloat16 l0 = __float2bfloat16(c0 - __bfloat162float(h0));
                __nv_bfloat16 l1 = __float2bfloat16(c1 - __bfloat162float(h1));
                __nv_bfloat16 l2 = __float2bfloat16(c2 - __bfloat162float(h2));
                __nv_bfloat16 l3 = __float2bfloat16(c3 - __bfloat162float(h3));
                g_vth[(size_t)col * MTOT + row0]           = h0;
                g_vth[(size_t)(col + 1) * MTOT + row0]     = h1;
                g_vth[(size_t)col * MTOT + row0 + 8]       = h2;
                g_vth[(size_t)(col + 1) * MTOT + row0 + 8] = h3;
                g_vtl[(size_t)col * MTOT + row0]           = l0;
                g_vtl[(size_t)(col + 1) * MTOT + row0]     = l1;
                g_vtl[(size_t)col * MTOT + row0 + 8]       = l2;
                g_vtl[(size_t)(col + 1) * MTOT + row0 + 8] = l3;
            } else {
                if (w == 0) { c0 *= qscale; c1 *= qscale; c2 *= qscale; c3 *= qscale; }
                float* of = (w == 0) ? g_qf : g_kf;
                float2 o0 = make_float2(__uint_as_float(f2tf32(c0)),
                                        __uint_as_float(f2tf32(c1)));
                float2 o1 = make_float2(__uint_as_float(f2tf32(c2)),
                                        __uint_as_float(f2tf32(c3)));
                *reinterpret_cast<float2*>(&of[(size_t)row0 * DD + col])       = o0;
                *reinterpret_cast<float2*>(&of[(size_t)(row0 + 8) * DD + col]) = o1;
            }
        }
}

// ---------------------------------------------------------------------------
// Kernel 2: causal flash attention.
//   S  = tf32 single-pass (measured err contribution ~2.6e-4)
//   PV = 3-term bf16 split: ph·vh + pl·vh + ph·vl (measured ~2e-5 class)
// Split-KV per n-warp, end-of-item merge; Q tf32 frags in registers.
// Smem: Q fp32 [64][132] @0 | K fp32 stages 2x33792 @33792 |
//       V bf16 stages 2x36864 @101376 | red @175104. Ored overlaps K stage0.
// ---------------------------------------------------------------------------
#define LDKF 132
#define LDV 72
#define AKST(s) (33792 + (s) * 33792)
#define AVST(s) (101376 + (s) * 36864)
#define ARED 175104
#define ATT_SMEM_BYTES 175616

__global__ __launch_bounds__(256) void attn_kernel(float* __restrict__ outp)
{
    extern __shared__ char smb[];
    const uint32_t sb = smem_u32(smb);
    float* Qf = (float*)(smb);                   // [64][132]
    float* Ored = (float*)(smb + 33792);         // [64][132] overlaps K stages
    float* redM = (float*)(smb + ARED);          // [64]
    float* redS = redM + 64;                     // [64]

    const int tid  = threadIdx.x;
    const int lane = tid & 31;
    const int wid  = tid >> 5;
    const int wni  = wid & 1;
    const int wm   = (wid >> 1) * 16;
    const int wn   = wni * 32;
    const int g    = lane >> 2;
    const int t4   = lane & 3;
    const int lb   = lane >> 3;
    const int lr   = lane & 7;

    #pragma unroll 1
    for (int item_i = 0; item_i < 2; item_i++) {
        const int j  = (item_i == 0) ? blockIdx.x : (255 - (int)blockIdx.x);
        const int qt = 63 - (j >> 2);
        const int b  = j & 3;
        const int m0 = qt * 64;
        const size_t bT = (size_t)b * TT;

        // prologue: prefetch KV tile 0 into stage 0
        {
            const uint32_t kb = sb + AKST(0);
            const uint32_t vhb = sb + AVST(0), vlb = vhb + 18432;
            #pragma unroll
            for (int it = 0; it < 8; it++) {
                int idx = tid + it * 256;
                int r   = idx >> 5;
                int c4  = (idx & 31) * 4;
                cp16(kb + (r * LDKF + c4) * 4, &g_kf[(bT + r) * DD + c4]);
            }
            #pragma unroll
            for (int it = 0; it < 4; it++) {
                int idx = tid + it * 256;
                int r   = idx >> 3;
                int c8  = (idx & 7) * 8;
                cp16(vhb + (r * LDV + c8) * 2, &g_vth[(size_t)r * MTOT + bT + c8]);
                cp16(vlb + (r * LDV + c8) * 2, &g_vtl[(size_t)r * MTOT + bT + c8]);
            }
            CP_COMMIT();
        }
        // load Q tile (fp32)
        #pragma unroll
        for (int it = 0; it < 8; it++) {
            int idx = tid + it * 256;
            int r   = idx >> 5;
            int c4  = (idx & 31) * 4;
            *reinterpret_cast<float4*>(&Qf[r * LDKF + c4]) =
                *reinterpret_cast<const float4*>(&g_qf[(bT + m0 + r) * DD + c4]);
        }
        __syncthreads();

        // hoist Q tf32 A-fragments to registers: 16 k-steps x 4 regs
        uint32_t qf[16][4];
        {
            const int row0 = wm + g, row1 = row0 + 8;
            #pragma unroll
            for (int d0 = 0; d0 < 16; d0++) {
                int c0 = d0 * 8 + t4;
                qf[d0][0] = __float_as_uint(Qf[row0 * LDKF + c0]);
                qf[d0][1] = __float_as_uint(Qf[row1 * LDKF + c0]);
                qf[d0][2] = __float_as_uint(Qf[row0 * LDKF + c0 + 4]);
                qf[d0][3] = __float_as_uint(Qf[row1 * LDKF + c0 + 4]);
            }
        }

        float oacc[16][4];
        #pragma unroll
        for (int i = 0; i < 16; i++)
            #pragma unroll
            for (int c = 0; c < 4; c++) oacc[i][c] = 0.f;
        float m_run0 = -1e30f, m_run1 = -1e30f;
        float l_run0 = 0.f, l_run1 = 0.f;

        #pragma unroll 1
        for (int kt = 0; kt <= qt; kt++) {
            const int s = kt & 1;
            if (kt < qt) {
                const uint32_t kb = sb + AKST(s ^ 1);
                const uint32_t vhb = sb + AVST(s ^ 1), vlb = vhb + 18432;
                const size_t kvo = bT + (size_t)(kt + 1) * 64;
                #pragma unroll
                for (int it = 0; it < 8; it++) {
                    int idx = tid + it * 256;
                    int r   = idx >> 5;
                    int c4  = (idx & 31) * 4;
                    cp16(kb + (r * LDKF + c4) * 4, &g_kf[(kvo + r) * DD + c4]);
                }
                #pragma unroll
                for (int it = 0; it < 4; it++) {
                    int idx = tid + it * 256;
                    int r   = idx >> 3;
                    int c8  = (idx & 7) * 8;
                    cp16(vhb + (r * LDV + c8) * 2, &g_vth[(size_t)r * MTOT + kvo + c8]);
                    cp16(vlb + (r * LDV + c8) * 2, &g_vtl[(size_t)r * MTOT + kvo + c8]);
                }
                CP_COMMIT();
                CP_WAIT1();
            } else {
                CP_WAIT0();
            }
            __syncthreads();

            const float* Ks = (const float*)(smb + AKST(s));
            const uint32_t vh_b = sb + AVST(s), vl_b = vh_b + 18432;

            // ---- S = Q K^T, tf32 single-pass. Warp tile 16x32.
            float sacc[4][4];
            #pragma unroll
            for (int i = 0; i < 4; i++)
                #pragma unroll
                for (int c = 0; c < 4; c++) sacc[i][c] = 0.f;

            #pragma unroll
            for (int d0 = 0; d0 < 16; d0++) {
                const int dc = d0 * 8 + t4;
                #pragma unroll
                for (int np = 0; np < 4; np++) {
                    const int key = wn + np * 8 + g;
                    uint32_t b0 = __float_as_uint(Ks[key * LDKF + dc]);
                    uint32_t b1 = __float_as_uint(Ks[key * LDKF + dc + 4]);
                    mma_tf32(sacc[np], qf[d0], b0, b1);
                }
            }

            if (kt == qt) {
                const int r0 = wm + g, r1 = r0 + 8;
                #pragma unroll
                for (int nf = 0; nf < 4; nf++) {
                    int col = wn + nf * 8 + 2 * t4;
                    if (col     > r0) sacc[nf][0] = -1e30f;
                    if (col + 1 > r0) sacc[nf][1] = -1e30f;
                    if (col     > r1) sacc[nf][2] = -1e30f;
                    if (col + 1 > r1) sacc[nf][3] = -1e30f;
                }
            }

            // ---- per-warp online softmax over this warp's 32 keys
            float lm0 = -1e30f, lm1 = -1e30f;
            #pragma unroll
            for (int nf = 0; nf < 4; nf++) {
                lm0 = fmaxf(lm0, fmaxf(sacc[nf][0], sacc[nf][1]));
                lm1 = fmaxf(lm1, fmaxf(sacc[nf][2], sacc[nf][3]));
            }
            lm0 = fmaxf(lm0, __shfl_xor_sync(0xFFFFFFFFu, lm0, 1));
            lm0 = fmaxf(lm0, __shfl_xor_sync(0xFFFFFFFFu, lm0, 2));
            lm1 = fmaxf(lm1, __shfl_xor_sync(0xFFFFFFFFu, lm1, 1));
            lm1 = fmaxf(lm1, __shfl_xor_sync(0xFFFFFFFFu, lm1, 2));

            float mn0 = fmaxf(m_run0, lm0);
            float mn1 = fmaxf(m_run1, lm1);
            float alpha0 = __expf(m_run0 - mn0);
            float alpha1 = __expf(m_run1 - mn1);

            float ps0 = 0.f, ps1 = 0.f;
            #pragma unroll
            for (int nf = 0; nf < 4; nf++) {
                sacc[nf][0] = __expf(sacc[nf][0] - mn0);
                sacc[nf][1] = __expf(sacc[nf][1] - mn0);
                sacc[nf][2] = __expf(sacc[nf][2] - mn1);
                sacc[nf][3] = __expf(sacc[nf][3] - mn1);
                ps0 += sacc[nf][0] + sacc[nf][1];
                ps1 += sacc[nf][2] + sacc[nf][3];
            }
            ps0 += __shfl_xor_sync(0xFFFFFFFFu, ps0, 1);
            ps0 += __shfl_xor_sync(0xFFFFFFFFu, ps0, 2);
            ps1 += __shfl_xor_sync(0xFFFFFFFFu, ps1, 1);
            ps1 += __shfl_xor_sync(0xFFFFFFFFu, ps1, 2);

            l_run0 = l_run0 * alpha0 + ps0;
            l_run1 = l_run1 * alpha1 + ps1;
            m_run0 = mn0; m_run1 = mn1;

            #pragma unroll
            for (int nf = 0; nf < 16; nf++) {
                oacc[nf][0] *= alpha0; oacc[nf][1] *= alpha0;
                oacc[nf][2] *= alpha1; oacc[nf][3] *= alpha1;
            }

            // ---- PV = ph·vh + pl·vh + ph·vl  (full 3-term split)
            #pragma unroll
            for (int ks2 = 0; ks2 < 2; ks2++) {
                uint32_t aPh[4], aPl[4];
                #pragma unroll
                for (int half = 0; half < 2; half++) {
                    const float* pc = sacc[2 * ks2 + half];
                    __nv_bfloat16 h0 = __float2bfloat16(pc[0]);
                    __nv_bfloat16 h1 = __float2bfloat16(pc[1]);
                    __nv_bfloat16 h2 = __float2bfloat16(pc[2]);
                    __nv_bfloat16 h3 = __float2bfloat16(pc[3]);
                    __nv_bfloat16 l0 = __float2bfloat16(pc[0] - __bfloat162float(h0));
                    __nv_bfloat16 l1 = __float2bfloat16(pc[1] - __bfloat162float(h1));
                    __nv_bfloat16 l2 = __float2bfloat16(pc[2] - __bfloat162float(h2));
                    __nv_bfloat16 l3 = __float2bfloat16(pc[3] - __bfloat162float(h3));
                    aPh[0 + 2 * half] = packh2(h0, h1);
                    aPh[1 + 2 * half] = packh2(h2, h3);
                    aPl[0 + 2 * half] = packh2(l0, l1);
                    aPl[1 + 2 * half] = packh2(l2, l3);
                }
                #pragma unroll
                for (int nd = 0; nd < 8; nd++) {
                    uint32_t off = (uint32_t)((nd * 16 + (lb >> 1) * 8 + lr) * LDV
                                              + wn + ks2 * 16 + (lb & 1) * 8) * 2;
                    uint32_t h0, h1, h2, h3, l0, l1, l2, l3;
                    ldmatrix_x4(h0, h1, h2, h3, vh_b + off);
                    ldmatrix_x4(l0, l1, l2, l3, vl_b + off);
                    uint32_t bh0[2] = {h0, h1}, bh1[2] = {h2, h3};
                    uint32_t bl0[2] = {l0, l1}, bl1[2] = {l2, l3};
                    mma16816(oacc[2*nd],   aPh, bh0);
                    mma16816(oacc[2*nd],   aPl, bh0);
                    mma16816(oacc[2*nd],   aPh, bl0);
                    mma16816(oacc[2*nd+1], aPh, bh1);
                    mma16816(oacc[2*nd+1], aPl, bh1);
                    mma16816(oacc[2*nd+1], aPh, bl1);
                }
            }
            __syncthreads();   // protect stage before overwrite
        }

        // ---- end-of-item merge of the two split-KV halves + store
        const int r0 = wm + g, r1 = r0 + 8;
        if (wni == 1) {
            if (t4 == 0) {
                redM[r0] = m_run0; redM[r1] = m_run1;
                redS[r0] = l_run0; redS[r1] = l_run1;
            }
            #pragma unroll
            for (int nf = 0; nf < 16; nf++) {
                int col = nf * 8 + 2 * t4;
                *reinterpret_cast<float2*>(&Ored[r0 * 132 + col]) =
                    make_float2(oacc[nf][0], oacc[nf][1]);
                *reinterpret_cast<float2*>(&Ored[r1 * 132 + col]) =
                    make_float2(oacc[nf][2], oacc[nf][3]);
            }
        }
        __syncthreads();
        if (wni == 0) {
            float mb0 = redM[r0], mb1 = redM[r1];
            float lb0 = redS[r0], lb1 = redS[r1];
            float mm0 = fmaxf(m_run0, mb0);
            float mm1 = fmaxf(m_run1, mb1);
            float ca0 = __expf(m_run0 - mm0), cb0 = __expf(mb0 - mm0);
            float ca1 = __expf(m_run1 - mm1), cb1 = __expf(mb1 - mm1);
            float inv0 = 1.0f / (l_run0 * ca0 + lb0 * cb0);
            float inv1 = 1.0f / (l_run1 * ca1 + lb1 * cb1);
            #pragma unroll
            for (int nf = 0; nf < 16; nf++) {
                int col = nf * 8 + 2 * t4;
                float2 p0 = *reinterpret_cast<float2*>(&Ored[r0 * 132 + col]);
                float2 p1 = *reinterpret_cast<float2*>(&Ored[r1 * 132 + col]);
                float2 o0 = make_float2((oacc[nf][0] * ca0 + p0.x * cb0) * inv0,
                                        (oacc[nf][1] * ca0 + p0.y * cb0) * inv0);
                float2 o1 = make_float2((oacc[nf][2] * ca1 + p1.x * cb1) * inv1,
                                        (oacc[nf][3] * ca1 + p1.y * cb1) * inv1);
                *reinterpret_cast<float2*>(&outp[(bT + m0 + r0) * DD + col]) = o0;
                *reinterpret_cast<float2*>(&outp[(bT + m0 + r1) * DD + col]) = o1;
            }
        }
        __syncthreads();
    }
}

// ---------------------------------------------------------------------------
extern "C" void kernel_launch(void* const* d_in, const int* in_sizes, int n_in,
                              void* d_out, int out_size)
{
    const float* x  = (const float*)d_in[0];
    const float* Wq = (const float*)d_in[1];
    const float* Wk = (const float*)d_in[2];
    const float* Wv = (const float*)d_in[3];
    float* out = (float*)d_out;
    (void)in_sizes; (void)n_in; (void)out_size;

    cudaFuncSetAttribute(prep_w_kernel,
                         cudaFuncAttributeMaxDynamicSharedMemorySize, PREP_SMEM);
    prep_w_kernel<<<dim3(16, 3), 256, PREP_SMEM>>>(Wq, Wk, Wv);

    cudaFuncSetAttribute(proj_mma_kernel,
                         cudaFuncAttributeMaxDynamicSharedMemorySize, PJ_SMEM);
    proj_mma_kernel<<<dim3(3, 128), 256, PJ_SMEM>>>(x);

    cudaFuncSetAttribute(attn_kernel,
                         cudaFuncAttributeMaxDynamicSharedMemorySize,
                         ATT_SMEM_BYTES);
    attn_kernel<<<128, 256, ATT_SMEM_BYTES>>>(out);
}

// round 15
// speedup vs baseline: 5.0642x; 1.1940x over previous
#include <cuda_runtime.h>
#include <cuda_bf16.h>
#include <cuda_fp16.h>
#include <cstdint>
#include <math.h>

#define BB 4
#define TT 4096
#define CC 2048
#define DD 128
#define MTOT (BB*TT)   // 16384

// ---------------------------------------------------------------------------
// Global scratch:
//  q, k : fp16 (q pre-scaled)  [m][d]
//  v    : fp16, transposed [d][m]
//  W^T  : split bf16 hi/lo (proj inputs, full accuracy)
// ---------------------------------------------------------------------------
__device__ __half g_qh[MTOT*DD];
__device__ __half g_kh[MTOT*DD];
__device__ __half g_vt[DD*MTOT];
__device__ __nv_bfloat16 g_wt_hi[3][DD*CC];
__device__ __nv_bfloat16 g_wt_lo[3][DD*CC];

__device__ __forceinline__ uint32_t smem_u32(const void* p) {
    uint32_t a;
    asm("{ .reg .u64 t; cvta.to.shared.u64 t, %1; cvt.u32.u64 %0, t; }"
        : "=r"(a) : "l"(p));
    return a;
}
__device__ __forceinline__ void ldmatrix_x4(uint32_t& r0, uint32_t& r1,
                                            uint32_t& r2, uint32_t& r3,
                                            uint32_t addr) {
    asm volatile("ldmatrix.sync.aligned.m8n8.x4.shared.b16 {%0,%1,%2,%3}, [%4];"
                 : "=r"(r0), "=r"(r1), "=r"(r2), "=r"(r3) : "r"(addr));
}
__device__ __forceinline__ void mma_bf16(float* c, const uint32_t* a, const uint32_t* b) {
    asm volatile(
        "mma.sync.aligned.m16n8k16.row.col.f32.bf16.bf16.f32 "
        "{%0,%1,%2,%3}, {%4,%5,%6,%7}, {%8,%9}, {%0,%1,%2,%3};"
        : "+f"(c[0]), "+f"(c[1]), "+f"(c[2]), "+f"(c[3])
        : "r"(a[0]), "r"(a[1]), "r"(a[2]), "r"(a[3]), "r"(b[0]), "r"(b[1]));
}
__device__ __forceinline__ void mma_f16(float* c, const uint32_t* a,
                                        uint32_t b0, uint32_t b1) {
    asm volatile(
        "mma.sync.aligned.m16n8k16.row.col.f32.f16.f16.f32 "
        "{%0,%1,%2,%3}, {%4,%5,%6,%7}, {%8,%9}, {%0,%1,%2,%3};"
        : "+f"(c[0]), "+f"(c[1]), "+f"(c[2]), "+f"(c[3])
        : "r"(a[0]), "r"(a[1]), "r"(a[2]), "r"(a[3]), "r"(b0), "r"(b1));
}
__device__ __forceinline__ uint32_t packbf2(__nv_bfloat16 a, __nv_bfloat16 b) {
    return ((uint32_t)__bfloat16_as_ushort(b) << 16) | __bfloat16_as_ushort(a);
}
__device__ __forceinline__ uint32_t packh2f(float a, float b) {
    __half2 h = __floats2half2_rn(a, b);
    return *reinterpret_cast<uint32_t*>(&h);
}
__device__ __forceinline__ void cp16(uint32_t smem, const void* g) {
    asm volatile("cp.async.cg.shared.global [%0], [%1], 16;" :: "r"(smem), "l"(g));
}
#define CP_COMMIT() asm volatile("cp.async.commit_group;" ::: "memory")
#define CP_WAIT0() asm volatile("cp.async.wait_group 0;" ::: "memory")
#define CP_WAIT1() asm volatile("cp.async.wait_group 1;" ::: "memory")

// ---------------------------------------------------------------------------
// Kernel 0: split W (fp32 [K,128]) into bf16 hi/lo transposed [N,K].
// ---------------------------------------------------------------------------
#define LDP 132
#define PREP_SMEM (2 * 128 * LDP * 2)

__global__ __launch_bounds__(256) void prep_w_kernel(
    const float* __restrict__ Wq,
    const float* __restrict__ Wk,
    const float* __restrict__ Wv)
{
    extern __shared__ __nv_bfloat16 sp[];
    __nv_bfloat16* shh = sp;
    __nv_bfloat16* shl = sp + 128 * LDP;
    const int w  = blockIdx.y;
    const int k0 = blockIdx.x * 128;
    const float* W = (w == 0) ? Wq : (w == 1) ? Wk : Wv;
    const int tid = threadIdx.x;

    #pragma unroll
    for (int it = 0; it < 16; it++) {
        int idx = tid + it * 256;
        int r   = idx >> 5;
        int c4  = (idx & 31) * 4;
        float4 v = *reinterpret_cast<const float4*>(&W[(size_t)(k0 + r) * DD + c4]);
        __nv_bfloat16 h0 = __float2bfloat16(v.x), h1 = __float2bfloat16(v.y);
        __nv_bfloat16 h2 = __float2bfloat16(v.z), h3 = __float2bfloat16(v.w);
        __nv_bfloat16 l0 = __float2bfloat16(v.x - __bfloat162float(h0));
        __nv_bfloat16 l1 = __float2bfloat16(v.y - __bfloat162float(h1));
        __nv_bfloat16 l2 = __float2bfloat16(v.z - __bfloat162float(h2));
        __nv_bfloat16 l3 = __float2bfloat16(v.w - __bfloat162float(h3));
        *reinterpret_cast<uint2*>(&shh[r * LDP + c4]) =
            make_uint2(packbf2(h0, h1), packbf2(h2, h3));
        *reinterpret_cast<uint2*>(&shl[r * LDP + c4]) =
            make_uint2(packbf2(l0, l1), packbf2(l2, l3));
    }
    __syncthreads();

    const int nb = tid >> 3;
    const int kc = (tid & 7) * 16;
    #pragma unroll
    for (int rep = 0; rep < 4; rep++) {
        int n = rep * 32 + nb;
        ushort hbuf[16], lbuf[16];
        #pragma unroll
        for (int i = 0; i < 16; i++) {
            hbuf[i] = __bfloat16_as_ushort(shh[(kc + i) * LDP + n]);
            lbuf[i] = __bfloat16_as_ushort(shl[(kc + i) * LDP + n]);
        }
        __nv_bfloat16* dh = &g_wt_hi[w][(size_t)n * CC + k0 + kc];
        __nv_bfloat16* dl = &g_wt_lo[w][(size_t)n * CC + k0 + kc];
        *reinterpret_cast<uint4*>(dh)     = *reinterpret_cast<uint4*>(&hbuf[0]);
        *reinterpret_cast<uint4*>(dh + 8) = *reinterpret_cast<uint4*>(&hbuf[8]);
        *reinterpret_cast<uint4*>(dl)     = *reinterpret_cast<uint4*>(&lbuf[0]);
        *reinterpret_cast<uint4*>(dl + 8) = *reinterpret_cast<uint4*>(&lbuf[8]);
    }
}

// ---------------------------------------------------------------------------
// Kernel 1: projection, mma.sync bf16 split (3-term), 2-stage pipelined.
// Epilogue: q (scaled), k -> fp16 [m][d]; v -> fp16 transposed [d][m].
// ---------------------------------------------------------------------------
#define LDA 40
#define PJ_SMEM 81920

__global__ __launch_bounds__(256) void proj_mma_kernel(const float* __restrict__ x)
{
    extern __shared__ char psm[];
    const uint32_t sb = smem_u32(psm);

    const int tid  = threadIdx.x;
    const int lane = tid & 31;
    const int wid  = tid >> 5;
    const int wm   = (wid >> 1) * 32;
    const int wn   = (wid & 1) * 64;
    const int w    = blockIdx.x;
    const int m0   = blockIdx.y * 128;

    const __nv_bfloat16* __restrict__ wt_h = g_wt_hi[w];
    const __nv_bfloat16* __restrict__ wt_l = g_wt_lo[w];

    float acc[2][8][4];
    #pragma unroll
    for (int i = 0; i < 2; i++)
        #pragma unroll
        for (int j = 0; j < 8; j++)
            #pragma unroll
            for (int c = 0; c < 4; c++) acc[i][j][c] = 0.f;

    const int lb = lane >> 3;
    const int lr = lane & 7;

    float4 xv[4];
    #pragma unroll
    for (int it = 0; it < 4; it++) {
        int idx = tid + it * 256;
        int r   = idx >> 3;
        int c4  = (idx & 7) * 4;
        xv[it] = *reinterpret_cast<const float4*>(&x[(size_t)(m0 + r) * CC + c4]);
    }
    {
        uint32_t bh0 = sb + 40960;
        uint32_t bl0 = bh0 + 10240;
        #pragma unroll
        for (int it = 0; it < 2; it++) {
            int idx = tid + it * 256;
            int n   = idx >> 2;
            int k8  = (idx & 3) * 8;
            cp16(bh0 + (n * LDA + k8) * 2, &wt_h[(size_t)n * CC + k8]);
            cp16(bl0 + (n * LDA + k8) * 2, &wt_l[(size_t)n * CC + k8]);
        }
        CP_COMMIT();
    }

    for (int kc = 0; kc < 64; kc++) {
        const int s = kc & 1;
        __nv_bfloat16* Ah = (__nv_bfloat16*)(psm + s * 20480);
        __nv_bfloat16* Al = (__nv_bfloat16*)(psm + s * 20480 + 10240);
        const uint32_t ah_base = sb + s * 20480;
        const uint32_t al_base = ah_base + 10240;
        const uint32_t bh_base = sb + 40960 + s * 20480;
        const uint32_t bl_base = bh_base + 10240;

        #pragma unroll
        for (int it = 0; it < 4; it++) {
            int idx = tid + it * 256;
            int r   = idx >> 3;
            int c4  = (idx & 7) * 4;
            float4 v = xv[it];
            __nv_bfloat16 h0 = __float2bfloat16(v.x), h1 = __float2bfloat16(v.y);
            __nv_bfloat16 h2 = __float2bfloat16(v.z), h3 = __float2bfloat16(v.w);
            __nv_bfloat16 l0 = __float2bfloat16(v.x - __bfloat162float(h0));
            __nv_bfloat16 l1 = __float2bfloat16(v.y - __bfloat162float(h1));
            __nv_bfloat16 l2 = __float2bfloat16(v.z - __bfloat162float(h2));
            __nv_bfloat16 l3 = __float2bfloat16(v.w - __bfloat162float(h3));
            *reinterpret_cast<uint2*>(&Ah[r * LDA + c4]) =
                make_uint2(packbf2(h0, h1), packbf2(h2, h3));
            *reinterpret_cast<uint2*>(&Al[r * LDA + c4]) =
                make_uint2(packbf2(l0, l1), packbf2(l2, l3));
        }
        if (kc < 63) {
            const int k0n = (kc + 1) * 32;
            #pragma unroll
            for (int it = 0; it < 4; it++) {
                int idx = tid + it * 256;
                int r   = idx >> 3;
                int c4  = (idx & 7) * 4;
                xv[it] = *reinterpret_cast<const float4*>(
                    &x[(size_t)(m0 + r) * CC + k0n + c4]);
            }
            uint32_t bhn = sb + 40960 + (s ^ 1) * 20480;
            uint32_t bln = bhn + 10240;
            #pragma unroll
            for (int it = 0; it < 2; it++) {
                int idx = tid + it * 256;
                int n   = idx >> 2;
                int k8  = (idx & 3) * 8;
                cp16(bhn + (n * LDA + k8) * 2, &wt_h[(size_t)n * CC + k0n + k8]);
                cp16(bln + (n * LDA + k8) * 2, &wt_l[(size_t)n * CC + k0n + k8]);
            }
            CP_COMMIT();
            CP_WAIT1();
        } else {
            CP_WAIT0();
        }
        __syncthreads();

        #pragma unroll
        for (int ks = 0; ks < 32; ks += 16) {
            uint32_t ah[2][4], al[2][4];
            #pragma unroll
            for (int mf = 0; mf < 2; mf++) {
                uint32_t off = (uint32_t)((wm + mf * 16 + (lb & 1) * 8 + lr) * LDA
                                          + ks + (lb >> 1) * 8) * 2;
                ldmatrix_x4(ah[mf][0], ah[mf][1], ah[mf][2], ah[mf][3], ah_base + off);
                ldmatrix_x4(al[mf][0], al[mf][1], al[mf][2], al[mf][3], al_base + off);
            }
            uint32_t bh[8][2], bl[8][2];
            #pragma unroll
            for (int np = 0; np < 4; np++) {
                uint32_t off = (uint32_t)((wn + np * 16 + (lb >> 1) * 8 + lr) * LDA
                                          + ks + (lb & 1) * 8) * 2;
                uint32_t r0, r1, r2, r3;
                ldmatrix_x4(r0, r1, r2, r3, bh_base + off);
                bh[2*np][0] = r0; bh[2*np][1] = r1; bh[2*np+1][0] = r2; bh[2*np+1][1] = r3;
                ldmatrix_x4(r0, r1, r2, r3, bl_base + off);
                bl[2*np][0] = r0; bl[2*np][1] = r1; bl[2*np+1][0] = r2; bl[2*np+1][1] = r3;
            }
            #pragma unroll
            for (int mf = 0; mf < 2; mf++)
                #pragma unroll
                for (int nf = 0; nf < 8; nf++) {
                    mma_bf16(acc[mf][nf], ah[mf], bh[nf]);
                    mma_bf16(acc[mf][nf], al[mf], bh[nf]);
                    mma_bf16(acc[mf][nf], ah[mf], bl[nf]);
                }
        }
        __syncthreads();
    }

    const int g  = lane >> 2;
    const int t4 = lane & 3;
    const float qscale = 0.08838834764831845f;
    #pragma unroll
    for (int mf = 0; mf < 2; mf++)
        #pragma unroll
        for (int nf = 0; nf < 8; nf++) {
            int row0 = m0 + wm + mf * 16 + g;
            int col  = wn + nf * 8 + t4 * 2;
            float c0 = acc[mf][nf][0], c1 = acc[mf][nf][1];
            float c2 = acc[mf][nf][2], c3 = acc[mf][nf][3];
            if (w == 2) {
                g_vt[(size_t)col * MTOT + row0]           = __float2half_rn(c0);
                g_vt[(size_t)(col + 1) * MTOT + row0]     = __float2half_rn(c1);
                g_vt[(size_t)col * MTOT + row0 + 8]       = __float2half_rn(c2);
                g_vt[(size_t)(col + 1) * MTOT + row0 + 8] = __float2half_rn(c3);
            } else {
                if (w == 0) { c0 *= qscale; c1 *= qscale; c2 *= qscale; c3 *= qscale; }
                __half* oh = (w == 0) ? g_qh : g_kh;
                *reinterpret_cast<uint32_t*>(&oh[(size_t)row0 * DD + col])       = packh2f(c0, c1);
                *reinterpret_cast<uint32_t*>(&oh[(size_t)(row0 + 8) * DD + col]) = packh2f(c2, c3);
            }
        }
}

// ---------------------------------------------------------------------------
// Kernel 2: causal flash attention, fp16 single-pass S and PV (eps 2^-11).
// Split-KV per n-warp, end-of-item merge; Q fp16 frags in registers.
// Smem: Q fp16 [64][136] @0 (17408) | K fp16 stages 2x17408 @17408 |
//       V fp16 stages 2x18432 @52224 | red @89088. Ored overlaps K stages.
// ---------------------------------------------------------------------------
#define LDK 136
#define LDV 72
#define AKST(s) (17408 + (s) * 17408)
#define AVST(s) (52224 + (s) * 18432)
#define ARED 89088
#define ATT_SMEM_BYTES 89600

__global__ __launch_bounds__(256) void attn_kernel(float* __restrict__ outp)
{
    extern __shared__ char smb[];
    const uint32_t sb = smem_u32(smb);
    __half* Qh = (__half*)(smb);                 // [64][136]
    float* Ored = (float*)(smb + 17408);         // [64][132] overlaps K stages
    float* redM = (float*)(smb + ARED);          // [64]
    float* redS = redM + 64;                     // [64]
    const uint32_t q_hb = sb;

    const int tid  = threadIdx.x;
    const int lane = tid & 31;
    const int wid  = tid >> 5;
    const int wni  = wid & 1;
    const int wm   = (wid >> 1) * 16;
    const int wn   = wni * 32;
    const int g    = lane >> 2;
    const int t4   = lane & 3;
    const int lb   = lane >> 3;
    const int lr   = lane & 7;

    #pragma unroll 1
    for (int item_i = 0; item_i < 2; item_i++) {
        const int j  = (item_i == 0) ? blockIdx.x : (255 - (int)blockIdx.x);
        const int qt = 63 - (j >> 2);
        const int b  = j & 3;
        const int m0 = qt * 64;
        const size_t bT = (size_t)b * TT;

        // prologue: prefetch KV tile 0 into stage 0
        {
            const uint32_t kb = sb + AKST(0);
            const uint32_t vb = sb + AVST(0);
            #pragma unroll
            for (int it = 0; it < 4; it++) {
                int idx = tid + it * 256;
                int r   = idx >> 4;
                int c8  = (idx & 15) * 8;
                cp16(kb + (r * LDK + c8) * 2, &g_kh[(bT + r) * DD + c8]);
            }
            #pragma unroll
            for (int it = 0; it < 4; it++) {
                int idx = tid + it * 256;
                int r   = idx >> 3;
                int c8  = (idx & 7) * 8;
                cp16(vb + (r * LDV + c8) * 2, &g_vt[(size_t)r * MTOT + bT + c8]);
            }
            CP_COMMIT();
        }
        // load Q tile (fp16)
        #pragma unroll
        for (int it = 0; it < 4; it++) {
            int idx = tid + it * 256;
            int r   = idx >> 4;
            int c8  = (idx & 15) * 8;
            *reinterpret_cast<uint4*>(&Qh[r * LDK + c8]) =
                *reinterpret_cast<const uint4*>(&g_qh[(bT + m0 + r) * DD + c8]);
        }
        __syncthreads();

        // hoist Q fp16 fragments to registers (8 d8 x 4 regs = 32 regs)
        uint32_t qf[8][4];
        #pragma unroll
        for (int d8 = 0; d8 < 8; d8++) {
            uint32_t off = (uint32_t)((wm + (lb & 1) * 8 + lr) * LDK
                                      + d8 * 16 + (lb >> 1) * 8) * 2;
            ldmatrix_x4(qf[d8][0], qf[d8][1], qf[d8][2], qf[d8][3], q_hb + off);
        }

        float oacc[16][4];
        #pragma unroll
        for (int i = 0; i < 16; i++)
            #pragma unroll
            for (int c = 0; c < 4; c++) oacc[i][c] = 0.f;
        float m_run0 = -1e30f, m_run1 = -1e30f;
        float l_run0 = 0.f, l_run1 = 0.f;

        #pragma unroll 1
        for (int kt = 0; kt <= qt; kt++) {
            const int s = kt & 1;
            if (kt < qt) {
                const uint32_t kb = sb + AKST(s ^ 1);
                const uint32_t vb = sb + AVST(s ^ 1);
                const size_t kvo = bT + (size_t)(kt + 1) * 64;
                #pragma unroll
                for (int it = 0; it < 4; it++) {
                    int idx = tid + it * 256;
                    int r   = idx >> 4;
                    int c8  = (idx & 15) * 8;
                    cp16(kb + (r * LDK + c8) * 2, &g_kh[(kvo + r) * DD + c8]);
                }
                #pragma unroll
                for (int it = 0; it < 4; it++) {
                    int idx = tid + it * 256;
                    int r   = idx >> 3;
                    int c8  = (idx & 7) * 8;
                    cp16(vb + (r * LDV + c8) * 2, &g_vt[(size_t)r * MTOT + kvo + c8]);
                }
                CP_COMMIT();
                CP_WAIT1();
            } else {
                CP_WAIT0();
            }
            __syncthreads();

            const uint32_t kh_b = sb + AKST(s);
            const uint32_t vh_b = sb + AVST(s);

            // ---- S = Q K^T, fp16 single-pass: 32 MMAs
            float sacc[4][4];
            #pragma unroll
            for (int i = 0; i < 4; i++)
                #pragma unroll
                for (int c = 0; c < 4; c++) sacc[i][c] = 0.f;

            #pragma unroll
            for (int d8 = 0; d8 < 8; d8++) {
                #pragma unroll
                for (int np = 0; np < 2; np++) {
                    uint32_t off = (uint32_t)((wn + np * 16 + (lb >> 1) * 8 + lr) * LDK
                                              + d8 * 16 + (lb & 1) * 8) * 2;
                    uint32_t h0, h1, h2, h3;
                    ldmatrix_x4(h0, h1, h2, h3, kh_b + off);
                    mma_f16(sacc[2*np],   qf[d8], h0, h1);
                    mma_f16(sacc[2*np+1], qf[d8], h2, h3);
                }
            }

            if (kt == qt) {
                const int r0 = wm + g, r1 = r0 + 8;
                #pragma unroll
                for (int nf = 0; nf < 4; nf++) {
                    int col = wn + nf * 8 + 2 * t4;
                    if (col     > r0) sacc[nf][0] = -1e30f;
                    if (col + 1 > r0) sacc[nf][1] = -1e30f;
                    if (col     > r1) sacc[nf][2] = -1e30f;
                    if (col + 1 > r1) sacc[nf][3] = -1e30f;
                }
            }

            // ---- per-warp online softmax over this warp's 32 keys
            float lm0 = -1e30f, lm1 = -1e30f;
            #pragma unroll
            for (int nf = 0; nf < 4; nf++) {
                lm0 = fmaxf(lm0, fmaxf(sacc[nf][0], sacc[nf][1]));
                lm1 = fmaxf(lm1, fmaxf(sacc[nf][2], sacc[nf][3]));
            }
            lm0 = fmaxf(lm0, __shfl_xor_sync(0xFFFFFFFFu, lm0, 1));
            lm0 = fmaxf(lm0, __shfl_xor_sync(0xFFFFFFFFu, lm0, 2));
            lm1 = fmaxf(lm1, __shfl_xor_sync(0xFFFFFFFFu, lm1, 1));
            lm1 = fmaxf(lm1, __shfl_xor_sync(0xFFFFFFFFu, lm1, 2));

            float mn0 = fmaxf(m_run0, lm0);
            float mn1 = fmaxf(m_run1, lm1);
            float alpha0 = __expf(m_run0 - mn0);
            float alpha1 = __expf(m_run1 - mn1);

            float ps0 = 0.f, ps1 = 0.f;
            #pragma unroll
            for (int nf = 0; nf < 4; nf++) {
                sacc[nf][0] = __expf(sacc[nf][0] - mn0);
                sacc[nf][1] = __expf(sacc[nf][1] - mn0);
                sacc[nf][2] = __expf(sacc[nf][2] - mn1);
                sacc[nf][3] = __expf(sacc[nf][3] - mn1);
                ps0 += sacc[nf][0] + sacc[nf][1];
                ps1 += sacc[nf][2] + sacc[nf][3];
            }
            ps0 += __shfl_xor_sync(0xFFFFFFFFu, ps0, 1);
            ps0 += __shfl_xor_sync(0xFFFFFFFFu, ps0, 2);
            ps1 += __shfl_xor_sync(0xFFFFFFFFu, ps1, 1);
            ps1 += __shfl_xor_sync(0xFFFFFFFFu, ps1, 2);

            l_run0 = l_run0 * alpha0 + ps0;
            l_run1 = l_run1 * alpha1 + ps1;
            m_run0 = mn0; m_run1 = mn1;

            #pragma unroll
            for (int nf = 0; nf < 16; nf++) {
                oacc[nf][0] *= alpha0; oacc[nf][1] *= alpha0;
                oacc[nf][2] *= alpha1; oacc[nf][3] *= alpha1;
            }

            // ---- PV fp16 single-pass: 32 MMAs (C->A fragment identity)
            #pragma unroll
            for (int ks2 = 0; ks2 < 2; ks2++) {
                uint32_t aP[4];
                #pragma unroll
                for (int half = 0; half < 2; half++) {
                    const float* pc = sacc[2 * ks2 + half];
                    aP[0 + 2 * half] = packh2f(pc[0], pc[1]);
                    aP[1 + 2 * half] = packh2f(pc[2], pc[3]);
                }
                #pragma unroll
                for (int nd = 0; nd < 8; nd++) {
                    uint32_t off = (uint32_t)((nd * 16 + (lb >> 1) * 8 + lr) * LDV
                                              + wn + ks2 * 16 + (lb & 1) * 8) * 2;
                    uint32_t h0, h1, h2, h3;
                    ldmatrix_x4(h0, h1, h2, h3, vh_b + off);
                    mma_f16(oacc[2*nd],   aP, h0, h1);
                    mma_f16(oacc[2*nd+1], aP, h2, h3);
                }
            }
            __syncthreads();   // protect stage before overwrite
        }

        // ---- end-of-item merge of the two split-KV halves + store
        const int r0 = wm + g, r1 = r0 + 8;
        if (wni == 1) {
            if (t4 == 0) {
                redM[r0] = m_run0; redM[r1] = m_run1;
                redS[r0] = l_run0; redS[r1] = l_run1;
            }
            #pragma unroll
            for (int nf = 0; nf < 16; nf++) {
                int col = nf * 8 + 2 * t4;
                *reinterpret_cast<float2*>(&Ored[r0 * 132 + col]) =
                    make_float2(oacc[nf][0], oacc[nf][1]);
                *reinterpret_cast<float2*>(&Ored[r1 * 132 + col]) =
                    make_float2(oacc[nf][2], oacc[nf][3]);
            }
        }
        __syncthreads();
        if (wni == 0) {
            float mb0 = redM[r0], mb1 = redM[r1];
            float lb0 = redS[r0], lb1 = redS[r1];
            float mm0 = fmaxf(m_run0, mb0);
            float mm1 = fmaxf(m_run1, mb1);
            float ca0 = __expf(m_run0 - mm0), cb0 = __expf(mb0 - mm0);
            float ca1 = __expf(m_run1 - mm1), cb1 = __expf(mb1 - mm1);
            float inv0 = 1.0f / (l_run0 * ca0 + lb0 * cb0);
            float inv1 = 1.0f / (l_run1 * ca1 + lb1 * cb1);
            #pragma unroll
            for (int nf = 0; nf < 16; nf++) {
                int col = nf * 8 + 2 * t4;
                float2 p0 = *reinterpret_cast<float2*>(&Ored[r0 * 132 + col]);
                float2 p1 = *reinterpret_cast<float2*>(&Ored[r1 * 132 + col]);
                float2 o0 = make_float2((oacc[nf][0] * ca0 + p0.x * cb0) * inv0,
                                        (oacc[nf][1] * ca0 + p0.y * cb0) * inv0);
                float2 o1 = make_float2((oacc[nf][2] * ca1 + p1.x * cb1) * inv1,
                                        (oacc[nf][3] * ca1 + p1.y * cb1) * inv1);
                *reinterpret_cast<float2*>(&outp[(bT + m0 + r0) * DD + col]) = o0;
                *reinterpret_cast<float2*>(&outp[(bT + m0 + r1) * DD + col]) = o1;
            }
        }
        __syncthreads();
    }
}

// ---------------------------------------------------------------------------
extern "C" void kernel_launch(void* const* d_in, const int* in_sizes, int n_in,
                              void* d_out, int out_size)
{
    const float* x  = (const float*)d_in[0];
    const float* Wq = (const float*)d_in[1];
    const float* Wk = (const float*)d_in[2];
    const float* Wv = (const float*)d_in[3];
    float* out = (float*)d_out;
    (void)in_sizes; (void)n_in; (void)out_size;

    cudaFuncSetAttribute(prep_w_kernel,
                         cudaFuncAttributeMaxDynamicSharedMemorySize, PREP_SMEM);
    prep_w_kernel<<<dim3(16, 3), 256, PREP_SMEM>>>(Wq, Wk, Wv);

    cudaFuncSetAttribute(proj_mma_kernel,
                         cudaFuncAttributeMaxDynamicSharedMemorySize, PJ_SMEM);
    proj_mma_kernel<<<dim3(3, 128), 256, PJ_SMEM>>>(x);

    cudaFuncSetAttribute(attn_kernel,
                         cudaFuncAttributeMaxDynamicSharedMemorySize,
                         ATT_SMEM_BYTES);
    attn_kernel<<<128, 256, ATT_SMEM_BYTES>>>(out);
}

// round 16
// speedup vs baseline: 8.6443x; 1.7069x over previous
#include <cuda_runtime.h>
#include <cuda_bf16.h>
#include <cuda_fp16.h>
#include <cstdint>
#include <math.h>

#define BB 4
#define TT 4096
#define CC 2048
#define DD 128
#define MTOT (BB*TT)   // 16384

// ---------------------------------------------------------------------------
// Global scratch: q,k fp16 [m][d] (q pre-scaled); v fp16 transposed [d][m];
// W^T fp16 [N][K].
// ---------------------------------------------------------------------------
__device__ __half g_qh[MTOT*DD];
__device__ __half g_kh[MTOT*DD];
__device__ __half g_vt[DD*MTOT];
__device__ __half g_wt16[3][DD*CC];

__device__ __forceinline__ uint32_t smem_u32(const void* p) {
    uint32_t a;
    asm("{ .reg .u64 t; cvta.to.shared.u64 t, %1; cvt.u32.u64 %0, t; }"
        : "=r"(a) : "l"(p));
    return a;
}
__device__ __forceinline__ void ldmatrix_x4(uint32_t& r0, uint32_t& r1,
                                            uint32_t& r2, uint32_t& r3,
                                            uint32_t addr) {
    asm volatile("ldmatrix.sync.aligned.m8n8.x4.shared.b16 {%0,%1,%2,%3}, [%4];"
                 : "=r"(r0), "=r"(r1), "=r"(r2), "=r"(r3) : "r"(addr));
}
__device__ __forceinline__ void mma_f16(float* c, const uint32_t* a,
                                        uint32_t b0, uint32_t b1) {
    asm volatile(
        "mma.sync.aligned.m16n8k16.row.col.f32.f16.f16.f32 "
        "{%0,%1,%2,%3}, {%4,%5,%6,%7}, {%8,%9}, {%0,%1,%2,%3};"
        : "+f"(c[0]), "+f"(c[1]), "+f"(c[2]), "+f"(c[3])
        : "r"(a[0]), "r"(a[1]), "r"(a[2]), "r"(a[3]), "r"(b0), "r"(b1));
}
__device__ __forceinline__ uint32_t packh2f(float a, float b) {
    __half2 h = __floats2half2_rn(a, b);
    return *reinterpret_cast<uint32_t*>(&h);
}
__device__ __forceinline__ void cp16(uint32_t smem, const void* g) {
    asm volatile("cp.async.cg.shared.global [%0], [%1], 16;" :: "r"(smem), "l"(g));
}
#define CP_COMMIT() asm volatile("cp.async.commit_group;" ::: "memory")
#define CP_WAIT0() asm volatile("cp.async.wait_group 0;" ::: "memory")
#define CP_WAIT1() asm volatile("cp.async.wait_group 1;" ::: "memory")

// ---------------------------------------------------------------------------
// Kernel 0: convert W (fp32 [K,128]) to fp16 transposed [N,K].
// ---------------------------------------------------------------------------
#define LDP 132
#define PREP_SMEM (128 * LDP * 2)

__global__ __launch_bounds__(256) void prep_w_kernel(
    const float* __restrict__ Wq,
    const float* __restrict__ Wk,
    const float* __restrict__ Wv)
{
    extern __shared__ __half sp[];
    const int w  = blockIdx.y;
    const int k0 = blockIdx.x * 128;
    const float* W = (w == 0) ? Wq : (w == 1) ? Wk : Wv;
    const int tid = threadIdx.x;

    #pragma unroll
    for (int it = 0; it < 16; it++) {
        int idx = tid + it * 256;
        int r   = idx >> 5;
        int c4  = (idx & 31) * 4;
        float4 v = *reinterpret_cast<const float4*>(&W[(size_t)(k0 + r) * DD + c4]);
        *reinterpret_cast<uint2*>(&sp[r * LDP + c4]) =
            make_uint2(packh2f(v.x, v.y), packh2f(v.z, v.w));
    }
    __syncthreads();

    const int nb = tid >> 3;
    const int kc = (tid & 7) * 16;
    #pragma unroll
    for (int rep = 0; rep < 4; rep++) {
        int n = rep * 32 + nb;
        ushort buf[16];
        #pragma unroll
        for (int i = 0; i < 16; i++)
            buf[i] = *reinterpret_cast<ushort*>(&sp[(kc + i) * LDP + n]);
        __half* d = &g_wt16[w][(size_t)n * CC + k0 + kc];
        *reinterpret_cast<uint4*>(d)     = *reinterpret_cast<uint4*>(&buf[0]);
        *reinterpret_cast<uint4*>(d + 8) = *reinterpret_cast<uint4*>(&buf[8]);
    }
}

// ---------------------------------------------------------------------------
// Kernel 1: projection, fp16 single-pass mma.sync, 2-stage pipelined.
// Grid (3, 128). A stages 2x10240 @0; B stages 2x10240 @20480.
// ---------------------------------------------------------------------------
#define LDA 40
#define PJ_SMEM 40960

__global__ __launch_bounds__(256) void proj_mma_kernel(const float* __restrict__ x)
{
    extern __shared__ char psm[];
    const uint32_t sb = smem_u32(psm);

    const int tid  = threadIdx.x;
    const int lane = tid & 31;
    const int wid  = tid >> 5;
    const int wm   = (wid >> 1) * 32;
    const int wn   = (wid & 1) * 64;
    const int w    = blockIdx.x;
    const int m0   = blockIdx.y * 128;

    const __half* __restrict__ wt = g_wt16[w];

    float acc[2][8][4];
    #pragma unroll
    for (int i = 0; i < 2; i++)
        #pragma unroll
        for (int j = 0; j < 8; j++)
            #pragma unroll
            for (int c = 0; c < 4; c++) acc[i][j][c] = 0.f;

    const int lb = lane >> 3;
    const int lr = lane & 7;

    float4 xv[4];
    #pragma unroll
    for (int it = 0; it < 4; it++) {
        int idx = tid + it * 256;
        int r   = idx >> 3;
        int c4  = (idx & 7) * 4;
        xv[it] = *reinterpret_cast<const float4*>(&x[(size_t)(m0 + r) * CC + c4]);
    }
    {
        uint32_t b0 = sb + 20480;
        #pragma unroll
        for (int it = 0; it < 2; it++) {
            int idx = tid + it * 256;
            int n   = idx >> 2;
            int k8  = (idx & 3) * 8;
            cp16(b0 + (n * LDA + k8) * 2, &wt[(size_t)n * CC + k8]);
        }
        CP_COMMIT();
    }

    for (int kc = 0; kc < 64; kc++) {
        const int s = kc & 1;
        __half* Ah = (__half*)(psm + s * 10240);
        const uint32_t ah_base = sb + s * 10240;
        const uint32_t bh_base = sb + 20480 + s * 10240;

        #pragma unroll
        for (int it = 0; it < 4; it++) {
            int idx = tid + it * 256;
            int r   = idx >> 3;
            int c4  = (idx & 7) * 4;
            float4 v = xv[it];
            *reinterpret_cast<uint2*>(&Ah[r * LDA + c4]) =
                make_uint2(packh2f(v.x, v.y), packh2f(v.z, v.w));
        }
        if (kc < 63) {
            const int k0n = (kc + 1) * 32;
            #pragma unroll
            for (int it = 0; it < 4; it++) {
                int idx = tid + it * 256;
                int r   = idx >> 3;
                int c4  = (idx & 7) * 4;
                xv[it] = *reinterpret_cast<const float4*>(
                    &x[(size_t)(m0 + r) * CC + k0n + c4]);
            }
            uint32_t bn = sb + 20480 + (s ^ 1) * 10240;
            #pragma unroll
            for (int it = 0; it < 2; it++) {
                int idx = tid + it * 256;
                int n   = idx >> 2;
                int k8  = (idx & 3) * 8;
                cp16(bn + (n * LDA + k8) * 2, &wt[(size_t)n * CC + k0n + k8]);
            }
            CP_COMMIT();
            CP_WAIT1();
        } else {
            CP_WAIT0();
        }
        __syncthreads();

        #pragma unroll
        for (int ks = 0; ks < 32; ks += 16) {
            uint32_t ah[2][4];
            #pragma unroll
            for (int mf = 0; mf < 2; mf++) {
                uint32_t off = (uint32_t)((wm + mf * 16 + (lb & 1) * 8 + lr) * LDA
                                          + ks + (lb >> 1) * 8) * 2;
                ldmatrix_x4(ah[mf][0], ah[mf][1], ah[mf][2], ah[mf][3], ah_base + off);
            }
            #pragma unroll
            for (int np = 0; np < 4; np++) {
                uint32_t off = (uint32_t)((wn + np * 16 + (lb >> 1) * 8 + lr) * LDA
                                          + ks + (lb & 1) * 8) * 2;
                uint32_t r0, r1, r2, r3;
                ldmatrix_x4(r0, r1, r2, r3, bh_base + off);
                #pragma unroll
                for (int mf = 0; mf < 2; mf++) {
                    mma_f16(acc[mf][2*np],   ah[mf], r0, r1);
                    mma_f16(acc[mf][2*np+1], ah[mf], r2, r3);
                }
            }
        }
        __syncthreads();
    }

    const int g  = lane >> 2;
    const int t4 = lane & 3;
    const float qscale = 0.08838834764831845f;
    #pragma unroll
    for (int mf = 0; mf < 2; mf++)
        #pragma unroll
        for (int nf = 0; nf < 8; nf++) {
            int row0 = m0 + wm + mf * 16 + g;
            int col  = wn + nf * 8 + t4 * 2;
            float c0 = acc[mf][nf][0], c1 = acc[mf][nf][1];
            float c2 = acc[mf][nf][2], c3 = acc[mf][nf][3];
            if (w == 2) {
                g_vt[(size_t)col * MTOT + row0]           = __float2half_rn(c0);
                g_vt[(size_t)(col + 1) * MTOT + row0]     = __float2half_rn(c1);
                g_vt[(size_t)col * MTOT + row0 + 8]       = __float2half_rn(c2);
                g_vt[(size_t)(col + 1) * MTOT + row0 + 8] = __float2half_rn(c3);
            } else {
                if (w == 0) { c0 *= qscale; c1 *= qscale; c2 *= qscale; c3 *= qscale; }
                __half* oh = (w == 0) ? g_qh : g_kh;
                *reinterpret_cast<uint32_t*>(&oh[(size_t)row0 * DD + col])       = packh2f(c0, c1);
                *reinterpret_cast<uint32_t*>(&oh[(size_t)(row0 + 8) * DD + col]) = packh2f(c2, c3);
            }
        }
}

// ---------------------------------------------------------------------------
// Kernel 2: causal flash attention, fp16 single-pass S and PV.
// S accumulators split even/odd d8 (8 chains x depth 4) for ILP.
// ---------------------------------------------------------------------------
#define LDK 136
#define LDV 72
#define AKST(s) (17408 + (s) * 17408)
#define AVST(s) (52224 + (s) * 18432)
#define ARED 89088
#define ATT_SMEM_BYTES 89600

__global__ __launch_bounds__(256) void attn_kernel(float* __restrict__ outp)
{
    extern __shared__ char smb[];
    const uint32_t sb = smem_u32(smb);
    __half* Qh = (__half*)(smb);                 // [64][136]
    float* Ored = (float*)(smb + 17408);         // [64][132] overlaps K stages
    float* redM = (float*)(smb + ARED);          // [64]
    float* redS = redM + 64;                     // [64]
    const uint32_t q_hb = sb;

    const int tid  = threadIdx.x;
    const int lane = tid & 31;
    const int wid  = tid >> 5;
    const int wni  = wid & 1;
    const int wm   = (wid >> 1) * 16;
    const int wn   = wni * 32;
    const int g    = lane >> 2;
    const int t4   = lane & 3;
    const int lb   = lane >> 3;
    const int lr   = lane & 7;

    #pragma unroll 1
    for (int item_i = 0; item_i < 2; item_i++) {
        const int j  = (item_i == 0) ? blockIdx.x : (255 - (int)blockIdx.x);
        const int qt = 63 - (j >> 2);
        const int b  = j & 3;
        const int m0 = qt * 64;
        const size_t bT = (size_t)b * TT;

        // prologue: prefetch KV tile 0 into stage 0
        {
            const uint32_t kb = sb + AKST(0);
            const uint32_t vb = sb + AVST(0);
            #pragma unroll
            for (int it = 0; it < 4; it++) {
                int idx = tid + it * 256;
                int r   = idx >> 4;
                int c8  = (idx & 15) * 8;
                cp16(kb + (r * LDK + c8) * 2, &g_kh[(bT + r) * DD + c8]);
            }
            #pragma unroll
            for (int it = 0; it < 4; it++) {
                int idx = tid + it * 256;
                int r   = idx >> 3;
                int c8  = (idx & 7) * 8;
                cp16(vb + (r * LDV + c8) * 2, &g_vt[(size_t)r * MTOT + bT + c8]);
            }
            CP_COMMIT();
        }
        // load Q tile (fp16)
        #pragma unroll
        for (int it = 0; it < 4; it++) {
            int idx = tid + it * 256;
            int r   = idx >> 4;
            int c8  = (idx & 15) * 8;
            *reinterpret_cast<uint4*>(&Qh[r * LDK + c8]) =
                *reinterpret_cast<const uint4*>(&g_qh[(bT + m0 + r) * DD + c8]);
        }
        __syncthreads();

        // hoist Q fp16 fragments to registers
        uint32_t qf[8][4];
        #pragma unroll
        for (int d8 = 0; d8 < 8; d8++) {
            uint32_t off = (uint32_t)((wm + (lb & 1) * 8 + lr) * LDK
                                      + d8 * 16 + (lb >> 1) * 8) * 2;
            ldmatrix_x4(qf[d8][0], qf[d8][1], qf[d8][2], qf[d8][3], q_hb + off);
        }

        float oacc[16][4];
        #pragma unroll
        for (int i = 0; i < 16; i++)
            #pragma unroll
            for (int c = 0; c < 4; c++) oacc[i][c] = 0.f;
        float m_run0 = -1e30f, m_run1 = -1e30f;
        float l_run0 = 0.f, l_run1 = 0.f;

        #pragma unroll 1
        for (int kt = 0; kt <= qt; kt++) {
            const int s = kt & 1;
            if (kt < qt) {
                const uint32_t kb = sb + AKST(s ^ 1);
                const uint32_t vb = sb + AVST(s ^ 1);
                const size_t kvo = bT + (size_t)(kt + 1) * 64;
                #pragma unroll
                for (int it = 0; it < 4; it++) {
                    int idx = tid + it * 256;
                    int r   = idx >> 4;
                    int c8  = (idx & 15) * 8;
                    cp16(kb + (r * LDK + c8) * 2, &g_kh[(kvo + r) * DD + c8]);
                }
                #pragma unroll
                for (int it = 0; it < 4; it++) {
                    int idx = tid + it * 256;
                    int r   = idx >> 3;
                    int c8  = (idx & 7) * 8;
                    cp16(vb + (r * LDV + c8) * 2, &g_vt[(size_t)r * MTOT + kvo + c8]);
                }
                CP_COMMIT();
                CP_WAIT1();
            } else {
                CP_WAIT0();
            }
            __syncthreads();

            const uint32_t kh_b = sb + AKST(s);
            const uint32_t vh_b = sb + AVST(s);

            // ---- S = Q K^T fp16: even/odd d8 partial accumulators (8 chains)
            float sA[4][4], sB[4][4];
            #pragma unroll
            for (int i = 0; i < 4; i++)
                #pragma unroll
                for (int c = 0; c < 4; c++) { sA[i][c] = 0.f; sB[i][c] = 0.f; }

            #pragma unroll
            for (int d8 = 0; d8 < 8; d8 += 2) {
                #pragma unroll
                for (int np = 0; np < 2; np++) {
                    uint32_t off0 = (uint32_t)((wn + np * 16 + (lb >> 1) * 8 + lr) * LDK
                                               + d8 * 16 + (lb & 1) * 8) * 2;
                    uint32_t off1 = off0 + 32;   // (d8+1)*16 halfs = +32 bytes
                    uint32_t a0, a1, a2, a3, b0, b1, b2, b3;
                    ldmatrix_x4(a0, a1, a2, a3, kh_b + off0);
                    ldmatrix_x4(b0, b1, b2, b3, kh_b + off1);
                    mma_f16(sA[2*np],   qf[d8],     a0, a1);
                    mma_f16(sA[2*np+1], qf[d8],     a2, a3);
                    mma_f16(sB[2*np],   qf[d8 + 1], b0, b1);
                    mma_f16(sB[2*np+1], qf[d8 + 1], b2, b3);
                }
            }
            float sacc[4][4];
            #pragma unroll
            for (int i = 0; i < 4; i++)
                #pragma unroll
                for (int c = 0; c < 4; c++) sacc[i][c] = sA[i][c] + sB[i][c];

            if (kt == qt) {
                const int r0 = wm + g, r1 = r0 + 8;
                #pragma unroll
                for (int nf = 0; nf < 4; nf++) {
                    int col = wn + nf * 8 + 2 * t4;
                    if (col     > r0) sacc[nf][0] = -1e30f;
                    if (col + 1 > r0) sacc[nf][1] = -1e30f;
                    if (col     > r1) sacc[nf][2] = -1e30f;
                    if (col + 1 > r1) sacc[nf][3] = -1e30f;
                }
            }

            // ---- per-warp online softmax over this warp's 32 keys
            float lm0 = -1e30f, lm1 = -1e30f;
            #pragma unroll
            for (int nf = 0; nf < 4; nf++) {
                lm0 = fmaxf(lm0, fmaxf(sacc[nf][0], sacc[nf][1]));
                lm1 = fmaxf(lm1, fmaxf(sacc[nf][2], sacc[nf][3]));
            }
            lm0 = fmaxf(lm0, __shfl_xor_sync(0xFFFFFFFFu, lm0, 1));
            lm0 = fmaxf(lm0, __shfl_xor_sync(0xFFFFFFFFu, lm0, 2));
            lm1 = fmaxf(lm1, __shfl_xor_sync(0xFFFFFFFFu, lm1, 1));
            lm1 = fmaxf(lm1, __shfl_xor_sync(0xFFFFFFFFu, lm1, 2));

            float mn0 = fmaxf(m_run0, lm0);
            float mn1 = fmaxf(m_run1, lm1);
            float alpha0 = __expf(m_run0 - mn0);
            float alpha1 = __expf(m_run1 - mn1);

            float ps0 = 0.f, ps1 = 0.f;
            #pragma unroll
            for (int nf = 0; nf < 4; nf++) {
                sacc[nf][0] = __expf(sacc[nf][0] - mn0);
                sacc[nf][1] = __expf(sacc[nf][1] - mn0);
                sacc[nf][2] = __expf(sacc[nf][2] - mn1);
                sacc[nf][3] = __expf(sacc[nf][3] - mn1);
                ps0 += sacc[nf][0] + sacc[nf][1];
                ps1 += sacc[nf][2] + sacc[nf][3];
            }
            ps0 += __shfl_xor_sync(0xFFFFFFFFu, ps0, 1);
            ps0 += __shfl_xor_sync(0xFFFFFFFFu, ps0, 2);
            ps1 += __shfl_xor_sync(0xFFFFFFFFu, ps1, 1);
            ps1 += __shfl_xor_sync(0xFFFFFFFFu, ps1, 2);

            l_run0 = l_run0 * alpha0 + ps0;
            l_run1 = l_run1 * alpha1 + ps1;
            m_run0 = mn0; m_run1 = mn1;

            #pragma unroll
            for (int nf = 0; nf < 16; nf++) {
                oacc[nf][0] *= alpha0; oacc[nf][1] *= alpha0;
                oacc[nf][2] *= alpha1; oacc[nf][3] *= alpha1;
            }

            // ---- PV fp16 single-pass
            #pragma unroll
            for (int ks2 = 0; ks2 < 2; ks2++) {
                uint32_t aP[4];
                #pragma unroll
                for (int half = 0; half < 2; half++) {
                    const float* pc = sacc[2 * ks2 + half];
                    aP[0 + 2 * half] = packh2f(pc[0], pc[1]);
                    aP[1 + 2 * half] = packh2f(pc[2], pc[3]);
                }
                #pragma unroll
                for (int nd = 0; nd < 8; nd++) {
                    uint32_t off = (uint32_t)((nd * 16 + (lb >> 1) * 8 + lr) * LDV
                                              + wn + ks2 * 16 + (lb & 1) * 8) * 2;
                    uint32_t h0, h1, h2, h3;
                    ldmatrix_x4(h0, h1, h2, h3, vh_b + off);
                    mma_f16(oacc[2*nd],   aP, h0, h1);
                    mma_f16(oacc[2*nd+1], aP, h2, h3);
                }
            }
            __syncthreads();   // protect stage before overwrite
        }

        // ---- end-of-item merge of the two split-KV halves + store
        const int r0 = wm + g, r1 = r0 + 8;
        if (wni == 1) {
            if (t4 == 0) {
                redM[r0] = m_run0; redM[r1] = m_run1;
                redS[r0] = l_run0; redS[r1] = l_run1;
            }
            #pragma unroll
            for (int nf = 0; nf < 16; nf++) {
                int col = nf * 8 + 2 * t4;
                *reinterpret_cast<float2*>(&Ored[r0 * 132 + col]) =
                    make_float2(oacc[nf][0], oacc[nf][1]);
                *reinterpret_cast<float2*>(&Ored[r1 * 132 + col]) =
                    make_float2(oacc[nf][2], oacc[nf][3]);
            }
        }
        __syncthreads();
        if (wni == 0) {
            float mb0 = redM[r0], mb1 = redM[r1];
            float lb0 = redS[r0], lb1 = redS[r1];
            float mm0 = fmaxf(m_run0, mb0);
            float mm1 = fmaxf(m_run1, mb1);
            float ca0 = __expf(m_run0 - mm0), cb0 = __expf(mb0 - mm0);
            float ca1 = __expf(m_run1 - mm1), cb1 = __expf(mb1 - mm1);
            float inv0 = 1.0f / (l_run0 * ca0 + lb0 * cb0);
            float inv1 = 1.0f / (l_run1 * ca1 + lb1 * cb1);
            #pragma unroll
            for (int nf = 0; nf < 16; nf++) {
                int col = nf * 8 + 2 * t4;
                float2 p0 = *reinterpret_cast<float2*>(&Ored[r0 * 132 + col]);
                float2 p1 = *reinterpret_cast<float2*>(&Ored[r1 * 132 + col]);
                float2 o0 = make_float2((oacc[nf][0] * ca0 + p0.x * cb0) * inv0,
                                        (oacc[nf][1] * ca0 + p0.y * cb0) * inv0);
                float2 o1 = make_float2((oacc[nf][2] * ca1 + p1.x * cb1) * inv1,
                                        (oacc[nf][3] * ca1 + p1.y * cb1) * inv1);
                *reinterpret_cast<float2*>(&outp[(bT + m0 + r0) * DD + col]) = o0;
                *reinterpret_cast<float2*>(&outp[(bT + m0 + r1) * DD + col]) = o1;
            }
        }
        __syncthreads();
    }
}

// ---------------------------------------------------------------------------
extern "C" void kernel_launch(void* const* d_in, const int* in_sizes, int n_in,
                              void* d_out, int out_size)
{
    const float* x  = (const float*)d_in[0];
    const float* Wq = (const float*)d_in[1];
    const float* Wk = (const float*)d_in[2];
    const float* Wv = (const float*)d_in[3];
    float* out = (float*)d_out;
    (void)in_sizes; (void)n_in; (void)out_size;

    cudaFuncSetAttribute(prep_w_kernel,
                         cudaFuncAttributeMaxDynamicSharedMemorySize, PREP_SMEM);
    prep_w_kernel<<<dim3(16, 3), 256, PREP_SMEM>>>(Wq, Wk, Wv);

    cudaFuncSetAttribute(proj_mma_kernel,
                         cudaFuncAttributeMaxDynamicSharedMemorySize, PJ_SMEM);
    proj_mma_kernel<<<dim3(3, 128), 256, PJ_SMEM>>>(x);

    cudaFuncSetAttribute(attn_kernel,
                         cudaFuncAttributeMaxDynamicSharedMemorySize,
                         ATT_SMEM_BYTES);
    attn_kernel<<<128, 256, ATT_SMEM_BYTES>>>(out);
}

// round 17
// speedup vs baseline: 9.2920x; 1.0749x over previous
#include <cuda_runtime.h>
#include <cuda_bf16.h>
#include <cuda_fp16.h>
#include <cstdint>
#include <math.h>

#define BB 4
#define TT 4096
#define CC 2048
#define DD 128
#define MTOT (BB*TT)   // 16384

// ---------------------------------------------------------------------------
// Global scratch: q,k fp16 [m][d] (q pre-scaled); v fp16 transposed [d][m];
// W^T fp16 [N][K].
// ---------------------------------------------------------------------------
__device__ __half g_qh[MTOT*DD];
__device__ __half g_kh[MTOT*DD];
__device__ __half g_vt[DD*MTOT];
__device__ __half g_wt16[3][DD*CC];

__device__ __forceinline__ uint32_t smem_u32(const void* p) {
    uint32_t a;
    asm("{ .reg .u64 t; cvta.to.shared.u64 t, %1; cvt.u32.u64 %0, t; }"
        : "=r"(a) : "l"(p));
    return a;
}
__device__ __forceinline__ void ldmatrix_x4(uint32_t& r0, uint32_t& r1,
                                            uint32_t& r2, uint32_t& r3,
                                            uint32_t addr) {
    asm volatile("ldmatrix.sync.aligned.m8n8.x4.shared.b16 {%0,%1,%2,%3}, [%4];"
                 : "=r"(r0), "=r"(r1), "=r"(r2), "=r"(r3) : "r"(addr));
}
__device__ __forceinline__ void mma_f16(float* c, const uint32_t* a,
                                        uint32_t b0, uint32_t b1) {
    asm volatile(
        "mma.sync.aligned.m16n8k16.row.col.f32.f16.f16.f32 "
        "{%0,%1,%2,%3}, {%4,%5,%6,%7}, {%8,%9}, {%0,%1,%2,%3};"
        : "+f"(c[0]), "+f"(c[1]), "+f"(c[2]), "+f"(c[3])
        : "r"(a[0]), "r"(a[1]), "r"(a[2]), "r"(a[3]), "r"(b0), "r"(b1));
}
__device__ __forceinline__ uint32_t packh2f(float a, float b) {
    __half2 h = __floats2half2_rn(a, b);
    return *reinterpret_cast<uint32_t*>(&h);
}
__device__ __forceinline__ void cp16(uint32_t smem, const void* g) {
    asm volatile("cp.async.cg.shared.global [%0], [%1], 16;" :: "r"(smem), "l"(g));
}
#define CP_COMMIT() asm volatile("cp.async.commit_group;" ::: "memory")
#define CP_WAIT0() asm volatile("cp.async.wait_group 0;" ::: "memory")
#define CP_WAIT1() asm volatile("cp.async.wait_group 1;" ::: "memory")

// ---------------------------------------------------------------------------
// Kernel 0: convert W (fp32 [K,128]) to fp16 transposed [N,K].
// ---------------------------------------------------------------------------
#define LDP 132
#define PREP_SMEM (128 * LDP * 2)

__global__ __launch_bounds__(256) void prep_w_kernel(
    const float* __restrict__ Wq,
    const float* __restrict__ Wk,
    const float* __restrict__ Wv)
{
    extern __shared__ __half sp[];
    const int w  = blockIdx.y;
    const int k0 = blockIdx.x * 128;
    const float* W = (w == 0) ? Wq : (w == 1) ? Wk : Wv;
    const int tid = threadIdx.x;

    #pragma unroll
    for (int it = 0; it < 16; it++) {
        int idx = tid + it * 256;
        int r   = idx >> 5;
        int c4  = (idx & 31) * 4;
        float4 v = *reinterpret_cast<const float4*>(&W[(size_t)(k0 + r) * DD + c4]);
        *reinterpret_cast<uint2*>(&sp[r * LDP + c4]) =
            make_uint2(packh2f(v.x, v.y), packh2f(v.z, v.w));
    }
    __syncthreads();

    const int nb = tid >> 3;
    const int kc = (tid & 7) * 16;
    #pragma unroll
    for (int rep = 0; rep < 4; rep++) {
        int n = rep * 32 + nb;
        ushort buf[16];
        #pragma unroll
        for (int i = 0; i < 16; i++)
            buf[i] = *reinterpret_cast<ushort*>(&sp[(kc + i) * LDP + n]);
        __half* d = &g_wt16[w][(size_t)n * CC + k0 + kc];
        *reinterpret_cast<uint4*>(d)     = *reinterpret_cast<uint4*>(&buf[0]);
        *reinterpret_cast<uint4*>(d + 8) = *reinterpret_cast<uint4*>(&buf[8]);
    }
}

// ---------------------------------------------------------------------------
// Kernel 1: projection, fp16 single-pass mma.sync, 2-stage pipelined.
// ---------------------------------------------------------------------------
#define LDA 40
#define PJ_SMEM 40960

__global__ __launch_bounds__(256) void proj_mma_kernel(const float* __restrict__ x)
{
    extern __shared__ char psm[];
    const uint32_t sb = smem_u32(psm);

    const int tid  = threadIdx.x;
    const int lane = tid & 31;
    const int wid  = tid >> 5;
    const int wm   = (wid >> 1) * 32;
    const int wn   = (wid & 1) * 64;
    const int w    = blockIdx.x;
    const int m0   = blockIdx.y * 128;

    const __half* __restrict__ wt = g_wt16[w];

    float acc[2][8][4];
    #pragma unroll
    for (int i = 0; i < 2; i++)
        #pragma unroll
        for (int j = 0; j < 8; j++)
            #pragma unroll
            for (int c = 0; c < 4; c++) acc[i][j][c] = 0.f;

    const int lb = lane >> 3;
    const int lr = lane & 7;

    float4 xv[4];
    #pragma unroll
    for (int it = 0; it < 4; it++) {
        int idx = tid + it * 256;
        int r   = idx >> 3;
        int c4  = (idx & 7) * 4;
        xv[it] = *reinterpret_cast<const float4*>(&x[(size_t)(m0 + r) * CC + c4]);
    }
    {
        uint32_t b0 = sb + 20480;
        #pragma unroll
        for (int it = 0; it < 2; it++) {
            int idx = tid + it * 256;
            int n   = idx >> 2;
            int k8  = (idx & 3) * 8;
            cp16(b0 + (n * LDA + k8) * 2, &wt[(size_t)n * CC + k8]);
        }
        CP_COMMIT();
    }

    for (int kc = 0; kc < 64; kc++) {
        const int s = kc & 1;
        __half* Ah = (__half*)(psm + s * 10240);
        const uint32_t ah_base = sb + s * 10240;
        const uint32_t bh_base = sb + 20480 + s * 10240;

        #pragma unroll
        for (int it = 0; it < 4; it++) {
            int idx = tid + it * 256;
            int r   = idx >> 3;
            int c4  = (idx & 7) * 4;
            float4 v = xv[it];
            *reinterpret_cast<uint2*>(&Ah[r * LDA + c4]) =
                make_uint2(packh2f(v.x, v.y), packh2f(v.z, v.w));
        }
        if (kc < 63) {
            const int k0n = (kc + 1) * 32;
            #pragma unroll
            for (int it = 0; it < 4; it++) {
                int idx = tid + it * 256;
                int r   = idx >> 3;
                int c4  = (idx & 7) * 4;
                xv[it] = *reinterpret_cast<const float4*>(
                    &x[(size_t)(m0 + r) * CC + k0n + c4]);
            }
            uint32_t bn = sb + 20480 + (s ^ 1) * 10240;
            #pragma unroll
            for (int it = 0; it < 2; it++) {
                int idx = tid + it * 256;
                int n   = idx >> 2;
                int k8  = (idx & 3) * 8;
                cp16(bn + (n * LDA + k8) * 2, &wt[(size_t)n * CC + k0n + k8]);
            }
            CP_COMMIT();
            CP_WAIT1();
        } else {
            CP_WAIT0();
        }
        __syncthreads();

        #pragma unroll
        for (int ks = 0; ks < 32; ks += 16) {
            uint32_t ah[2][4];
            #pragma unroll
            for (int mf = 0; mf < 2; mf++) {
                uint32_t off = (uint32_t)((wm + mf * 16 + (lb & 1) * 8 + lr) * LDA
                                          + ks + (lb >> 1) * 8) * 2;
                ldmatrix_x4(ah[mf][0], ah[mf][1], ah[mf][2], ah[mf][3], ah_base + off);
            }
            #pragma unroll
            for (int np = 0; np < 4; np++) {
                uint32_t off = (uint32_t)((wn + np * 16 + (lb >> 1) * 8 + lr) * LDA
                                          + ks + (lb & 1) * 8) * 2;
                uint32_t r0, r1, r2, r3;
                ldmatrix_x4(r0, r1, r2, r3, bh_base + off);
                #pragma unroll
                for (int mf = 0; mf < 2; mf++) {
                    mma_f16(acc[mf][2*np],   ah[mf], r0, r1);
                    mma_f16(acc[mf][2*np+1], ah[mf], r2, r3);
                }
            }
        }
        __syncthreads();
    }

    const int g  = lane >> 2;
    const int t4 = lane & 3;
    const float qscale = 0.08838834764831845f;
    #pragma unroll
    for (int mf = 0; mf < 2; mf++)
        #pragma unroll
        for (int nf = 0; nf < 8; nf++) {
            int row0 = m0 + wm + mf * 16 + g;
            int col  = wn + nf * 8 + t4 * 2;
            float c0 = acc[mf][nf][0], c1 = acc[mf][nf][1];
            float c2 = acc[mf][nf][2], c3 = acc[mf][nf][3];
            if (w == 2) {
                g_vt[(size_t)col * MTOT + row0]           = __float2half_rn(c0);
                g_vt[(size_t)(col + 1) * MTOT + row0]     = __float2half_rn(c1);
                g_vt[(size_t)col * MTOT + row0 + 8]       = __float2half_rn(c2);
                g_vt[(size_t)(col + 1) * MTOT + row0 + 8] = __float2half_rn(c3);
            } else {
                if (w == 0) { c0 *= qscale; c1 *= qscale; c2 *= qscale; c3 *= qscale; }
                __half* oh = (w == 0) ? g_qh : g_kh;
                *reinterpret_cast<uint32_t*>(&oh[(size_t)row0 * DD + col])       = packh2f(c0, c1);
                *reinterpret_cast<uint32_t*>(&oh[(size_t)(row0 + 8) * DD + col]) = packh2f(c2, c3);
            }
        }
}

// ---------------------------------------------------------------------------
// Kernel 2: causal flash attention, fp16, BKV=128 tiles (halved per-tile
// overhead). Split-KV per n-warp (64 keys each), end-of-item merge.
// Smem: Q [64][136] @0 | K stages 2x[128][136] @17408 |
//       V stages 2x[128][136] @87040 | red @156672. Ored overlaps K stages.
// ---------------------------------------------------------------------------
#define LDK 136
#define LDV 136
#define AKST(s) (17408 + (s) * 34816)
#define AVST(s) (87040 + (s) * 34816)
#define ARED 156672
#define ATT_SMEM_BYTES 157184

__global__ __launch_bounds__(256) void attn_kernel(float* __restrict__ outp)
{
    extern __shared__ char smb[];
    const uint32_t sb = smem_u32(smb);
    __half* Qh = (__half*)(smb);                 // [64][136]
    float* Ored = (float*)(smb + 17408);         // [64][132] overlaps K stages
    float* redM = (float*)(smb + ARED);          // [64]
    float* redS = redM + 64;                     // [64]
    const uint32_t q_hb = sb;

    const int tid  = threadIdx.x;
    const int lane = tid & 31;
    const int wid  = tid >> 5;
    const int wni  = wid & 1;
    const int wm   = (wid >> 1) * 16;
    const int wn2  = wni * 64;                   // 64-key half per n-warp
    const int g    = lane >> 2;
    const int t4   = lane & 3;
    const int lb   = lane >> 3;
    const int lr   = lane & 7;

    #pragma unroll 1
    for (int item_i = 0; item_i < 2; item_i++) {
        const int j  = (item_i == 0) ? blockIdx.x : (255 - (int)blockIdx.x);
        const int qt = 63 - (j >> 2);
        const int b  = j & 3;
        const int m0 = qt * 64;
        const int KT = (qt >> 1) + 1;            // 128-key tiles
        const size_t bT = (size_t)b * TT;

        // prologue: prefetch KV tile 0 into stage 0
        {
            const uint32_t kb = sb + AKST(0);
            const uint32_t vb = sb + AVST(0);
            #pragma unroll
            for (int it = 0; it < 8; it++) {
                int idx = tid + it * 256;        // 0..2047
                int r   = idx >> 4;              // 0..127
                int c8  = (idx & 15) * 8;
                cp16(kb + (r * LDK + c8) * 2, &g_kh[(bT + r) * DD + c8]);
                cp16(vb + (r * LDV + c8) * 2, &g_vt[(size_t)r * MTOT + bT + c8]);
            }
            CP_COMMIT();
        }
        // load Q tile (fp16)
        #pragma unroll
        for (int it = 0; it < 4; it++) {
            int idx = tid + it * 256;
            int r   = idx >> 4;
            int c8  = (idx & 15) * 8;
            *reinterpret_cast<uint4*>(&Qh[r * LDK + c8]) =
                *reinterpret_cast<const uint4*>(&g_qh[(bT + m0 + r) * DD + c8]);
        }
        __syncthreads();

        // hoist Q fp16 fragments to registers
        uint32_t qf[8][4];
        #pragma unroll
        for (int d8 = 0; d8 < 8; d8++) {
            uint32_t off = (uint32_t)((wm + (lb & 1) * 8 + lr) * LDK
                                      + d8 * 16 + (lb >> 1) * 8) * 2;
            ldmatrix_x4(qf[d8][0], qf[d8][1], qf[d8][2], qf[d8][3], q_hb + off);
        }

        float oacc[16][4];
        #pragma unroll
        for (int i = 0; i < 16; i++)
            #pragma unroll
            for (int c = 0; c < 4; c++) oacc[i][c] = 0.f;
        float m_run0 = -1e30f, m_run1 = -1e30f;
        float l_run0 = 0.f, l_run1 = 0.f;

        #pragma unroll 1
        for (int kt = 0; kt < KT; kt++) {
            const int s = kt & 1;
            if (kt < KT - 1) {
                const uint32_t kb = sb + AKST(s ^ 1);
                const uint32_t vb = sb + AVST(s ^ 1);
                const size_t kvo = bT + (size_t)(kt + 1) * 128;
                #pragma unroll
                for (int it = 0; it < 8; it++) {
                    int idx = tid + it * 256;
                    int r   = idx >> 4;
                    int c8  = (idx & 15) * 8;
                    cp16(kb + (r * LDK + c8) * 2, &g_kh[(kvo + r) * DD + c8]);
                    cp16(vb + (r * LDV + c8) * 2, &g_vt[(size_t)r * MTOT + kvo + c8]);
                }
                CP_COMMIT();
                CP_WAIT1();
            } else {
                CP_WAIT0();
            }
            __syncthreads();

            const uint32_t kh_b = sb + AKST(s);
            const uint32_t vh_b = sb + AVST(s);

            // ---- S = Q K^T fp16: warp tile 16 x 64 (keys wn2..wn2+63)
            float sacc[8][4];
            #pragma unroll
            for (int i = 0; i < 8; i++)
                #pragma unroll
                for (int c = 0; c < 4; c++) sacc[i][c] = 0.f;

            #pragma unroll
            for (int d8 = 0; d8 < 8; d8++) {
                #pragma unroll
                for (int np = 0; np < 4; np++) {
                    uint32_t off = (uint32_t)((wn2 + np * 16 + (lb >> 1) * 8 + lr) * LDK
                                              + d8 * 16 + (lb & 1) * 8) * 2;
                    uint32_t h0, h1, h2, h3;
                    ldmatrix_x4(h0, h1, h2, h3, kh_b + off);
                    mma_f16(sacc[2*np],   qf[d8], h0, h1);
                    mma_f16(sacc[2*np+1], qf[d8], h2, h3);
                }
            }

            if (kt == KT - 1) {       // causal mask (global indices)
                const int gr0 = m0 + wm + g, gr1 = gr0 + 8;
                #pragma unroll
                for (int nf = 0; nf < 8; nf++) {
                    int col = kt * 128 + wn2 + nf * 8 + 2 * t4;
                    if (col     > gr0) sacc[nf][0] = -1e30f;
                    if (col + 1 > gr0) sacc[nf][1] = -1e30f;
                    if (col     > gr1) sacc[nf][2] = -1e30f;
                    if (col + 1 > gr1) sacc[nf][3] = -1e30f;
                }
            }

            // ---- per-warp online softmax over this warp's 64 keys
            float lm0 = -1e30f, lm1 = -1e30f;
            #pragma unroll
            for (int nf = 0; nf < 8; nf++) {
                lm0 = fmaxf(lm0, fmaxf(sacc[nf][0], sacc[nf][1]));
                lm1 = fmaxf(lm1, fmaxf(sacc[nf][2], sacc[nf][3]));
            }
            lm0 = fmaxf(lm0, __shfl_xor_sync(0xFFFFFFFFu, lm0, 1));
            lm0 = fmaxf(lm0, __shfl_xor_sync(0xFFFFFFFFu, lm0, 2));
            lm1 = fmaxf(lm1, __shfl_xor_sync(0xFFFFFFFFu, lm1, 1));
            lm1 = fmaxf(lm1, __shfl_xor_sync(0xFFFFFFFFu, lm1, 2));

            float mn0 = fmaxf(m_run0, lm0);
            float mn1 = fmaxf(m_run1, lm1);
            float alpha0 = __expf(m_run0 - mn0);
            float alpha1 = __expf(m_run1 - mn1);

            float ps0 = 0.f, ps1 = 0.f;
            #pragma unroll
            for (int nf = 0; nf < 8; nf++) {
                sacc[nf][0] = __expf(sacc[nf][0] - mn0);
                sacc[nf][1] = __expf(sacc[nf][1] - mn0);
                sacc[nf][2] = __expf(sacc[nf][2] - mn1);
                sacc[nf][3] = __expf(sacc[nf][3] - mn1);
                ps0 += sacc[nf][0] + sacc[nf][1];
                ps1 += sacc[nf][2] + sacc[nf][3];
            }
            ps0 += __shfl_xor_sync(0xFFFFFFFFu, ps0, 1);
            ps0 += __shfl_xor_sync(0xFFFFFFFFu, ps0, 2);
            ps1 += __shfl_xor_sync(0xFFFFFFFFu, ps1, 1);
            ps1 += __shfl_xor_sync(0xFFFFFFFFu, ps1, 2);

            l_run0 = l_run0 * alpha0 + ps0;
            l_run1 = l_run1 * alpha1 + ps1;
            m_run0 = mn0; m_run1 = mn1;

            #pragma unroll
            for (int nf = 0; nf < 16; nf++) {
                oacc[nf][0] *= alpha0; oacc[nf][1] *= alpha0;
                oacc[nf][2] *= alpha1; oacc[nf][3] *= alpha1;
            }

            // ---- PV fp16: 4 k-chunks of 16 keys
            #pragma unroll
            for (int ks2 = 0; ks2 < 4; ks2++) {
                uint32_t aP[4];
                #pragma unroll
                for (int half = 0; half < 2; half++) {
                    const float* pc = sacc[2 * ks2 + half];
                    aP[0 + 2 * half] = packh2f(pc[0], pc[1]);
                    aP[1 + 2 * half] = packh2f(pc[2], pc[3]);
                }
                #pragma unroll
                for (int nd = 0; nd < 8; nd++) {
                    uint32_t off = (uint32_t)((nd * 16 + (lb >> 1) * 8 + lr) * LDV
                                              + wn2 + ks2 * 16 + (lb & 1) * 8) * 2;
                    uint32_t h0, h1, h2, h3;
                    ldmatrix_x4(h0, h1, h2, h3, vh_b + off);
                    mma_f16(oacc[2*nd],   aP, h0, h1);
                    mma_f16(oacc[2*nd+1], aP, h2, h3);
                }
            }
            __syncthreads();   // protect stage before overwrite
        }

        // ---- end-of-item merge of the two split-KV halves + store
        const int r0 = wm + g, r1 = r0 + 8;
        if (wni == 1) {
            if (t4 == 0) {
                redM[r0] = m_run0; redM[r1] = m_run1;
                redS[r0] = l_run0; redS[r1] = l_run1;
            }
            #pragma unroll
            for (int nf = 0; nf < 16; nf++) {
                int col = nf * 8 + 2 * t4;
                *reinterpret_cast<float2*>(&Ored[r0 * 132 + col]) =
                    make_float2(oacc[nf][0], oacc[nf][1]);
                *reinterpret_cast<float2*>(&Ored[r1 * 132 + col]) =
                    make_float2(oacc[nf][2], oacc[nf][3]);
            }
        }
        __syncthreads();
        if (wni == 0) {
            float mb0 = redM[r0], mb1 = redM[r1];
            float lb0 = redS[r0], lb1 = redS[r1];
            float mm0 = fmaxf(m_run0, mb0);
            float mm1 = fmaxf(m_run1, mb1);
            float ca0 = __expf(m_run0 - mm0), cb0 = __expf(mb0 - mm0);
            float ca1 = __expf(m_run1 - mm1), cb1 = __expf(mb1 - mm1);
            float inv0 = 1.0f / (l_run0 * ca0 + lb0 * cb0);
            float inv1 = 1.0f / (l_run1 * ca1 + lb1 * cb1);
            #pragma unroll
            for (int nf = 0; nf < 16; nf++) {
                int col = nf * 8 + 2 * t4;
                float2 p0 = *reinterpret_cast<float2*>(&Ored[r0 * 132 + col]);
                float2 p1 = *reinterpret_cast<float2*>(&Ored[r1 * 132 + col]);
                float2 o0 = make_float2((oacc[nf][0] * ca0 + p0.x * cb0) * inv0,
                                        (oacc[nf][1] * ca0 + p0.y * cb0) * inv0);
                float2 o1 = make_float2((oacc[nf][2] * ca1 + p1.x * cb1) * inv1,
                                        (oacc[nf][3] * ca1 + p1.y * cb1) * inv1);
                *reinterpret_cast<float2*>(&outp[(bT + m0 + r0) * DD + col]) = o0;
                *reinterpret_cast<float2*>(&outp[(bT + m0 + r1) * DD + col]) = o1;
            }
        }
        __syncthreads();
    }
}

// ---------------------------------------------------------------------------
extern "C" void kernel_launch(void* const* d_in, const int* in_sizes, int n_in,
                              void* d_out, int out_size)
{
    const float* x  = (const float*)d_in[0];
    const float* Wq = (const float*)d_in[1];
    const float* Wk = (const float*)d_in[2];
    const float* Wv = (const float*)d_in[3];
    float* out = (float*)d_out;
    (void)in_sizes; (void)n_in; (void)out_size;

    cudaFuncSetAttribute(prep_w_kernel,
                         cudaFuncAttributeMaxDynamicSharedMemorySize, PREP_SMEM);
    prep_w_kernel<<<dim3(16, 3), 256, PREP_SMEM>>>(Wq, Wk, Wv);

    cudaFuncSetAttribute(proj_mma_kernel,
                         cudaFuncAttributeMaxDynamicSharedMemorySize, PJ_SMEM);
    proj_mma_kernel<<<dim3(3, 128), 256, PJ_SMEM>>>(x);

    cudaFuncSetAttribute(attn_kernel,
                         cudaFuncAttributeMaxDynamicSharedMemorySize,
                         ATT_SMEM_BYTES);
    attn_kernel<<<128, 256, ATT_SMEM_BYTES>>>(out);
}